// round 6
// baseline (speedup 1.0000x reference)
#include <cuda_runtime.h>
#include <cuda_bf16.h>
#include <math.h>
#include <stdint.h>

// Problem constants
#define BB   2
#define SS   1024
#define PP   1024
#define TT   (PP + SS)
#define HH   4096
#define NQ   32
#define NKV  8
#define DD   128
#define QKVN ((NQ + 2 * NKV) * DD)   // 6144
#define SCALE 0.08838834764831845f   // 1/sqrt(128)

// ---------------------------------------------------------------------------
// Scratch (device globals: no allocation allowed)
// ---------------------------------------------------------------------------
__device__ float g_qkv[BB * SS * QKVN];
__device__ __nv_bfloat16 g_hid_h[BB * SS * HH];
__device__ __nv_bfloat16 g_hid_l[BB * SS * HH];
__device__ __nv_bfloat16 g_wqkv_h[(size_t)QKVN * HH];   // transposed [N,K]
__device__ __nv_bfloat16 g_wqkv_l[(size_t)QKVN * HH];
__device__ __nv_bfloat16 g_wo_h[(size_t)HH * HH];       // transposed [N,K]
__device__ __nv_bfloat16 g_wo_l[(size_t)HH * HH];
__device__ __nv_bfloat16 g_attn_h[BB * SS * NQ * DD];
__device__ __nv_bfloat16 g_attn_l[BB * SS * NQ * DD];
// Q hi/lo [B][NQ][S][D]
__device__ __nv_bfloat16 g_q_h[(size_t)BB * NQ * SS * DD];
__device__ __nv_bfloat16 g_q_l[(size_t)BB * NQ * SS * DD];
// unified KV hi/lo [B][NKV][T][D]
__device__ __nv_bfloat16 g_k_h[(size_t)BB * NKV * TT * DD];
__device__ __nv_bfloat16 g_k_l[(size_t)BB * NKV * TT * DD];
__device__ __nv_bfloat16 g_v_h[(size_t)BB * NKV * TT * DD];
__device__ __nv_bfloat16 g_v_l[(size_t)BB * NKV * TT * DD];

// ---------------------------------------------------------------------------
// Low-level helpers (plain sm_80+ ISA)
// ---------------------------------------------------------------------------
__device__ __forceinline__ uint32_t smem_u32(const void* p) {
    uint32_t a;
    asm("{ .reg .u64 t; cvta.to.shared.u64 t, %1; cvt.u32.u64 %0, t; }"
        : "=r"(a) : "l"(p));
    return a;
}
__device__ __forceinline__ void cp16(uint32_t dst, const void* src) {
    asm volatile("cp.async.cg.shared.global [%0], [%1], 16;"
                 :: "r"(dst), "l"(src));
}
__device__ __forceinline__ void ldsm4(uint32_t* r, uint32_t a) {
    asm volatile("ldmatrix.sync.aligned.m8n8.x4.shared.b16 {%0,%1,%2,%3}, [%4];"
                 : "=r"(r[0]), "=r"(r[1]), "=r"(r[2]), "=r"(r[3]) : "r"(a));
}
__device__ __forceinline__ void ldsm4t(uint32_t* r, uint32_t a) {
    asm volatile("ldmatrix.sync.aligned.m8n8.x4.trans.shared.b16 {%0,%1,%2,%3}, [%4];"
                 : "=r"(r[0]), "=r"(r[1]), "=r"(r[2]), "=r"(r[3]) : "r"(a));
}
__device__ __forceinline__ void mma16816(float* c, const uint32_t* a,
                                         const uint32_t b0, const uint32_t b1) {
    asm volatile(
        "mma.sync.aligned.m16n8k16.row.col.f32.bf16.bf16.f32 "
        "{%0,%1,%2,%3}, {%4,%5,%6,%7}, {%8,%9}, {%0,%1,%2,%3};"
        : "+f"(c[0]), "+f"(c[1]), "+f"(c[2]), "+f"(c[3])
        : "r"(a[0]), "r"(a[1]), "r"(a[2]), "r"(a[3]), "r"(b0), "r"(b1));
}

// ---------------------------------------------------------------------------
// fp32 -> bf16 hi/lo split (same layout)
// ---------------------------------------------------------------------------
__global__ void split_kernel(const float* __restrict__ x,
                             __nv_bfloat16* __restrict__ xh,
                             __nv_bfloat16* __restrict__ xl, int n)
{
    int i = blockIdx.x * blockDim.x + threadIdx.x;
    if (i >= n) return;
    float v = x[i];
    __nv_bfloat16 hb = __float2bfloat16(v);
    xh[i] = hb;
    xl[i] = __float2bfloat16(v - __bfloat162float(hb));
}

// fp32 [R,C] -> bf16 hi/lo transposed [C,R]
__global__ void split_t_kernel(const float* __restrict__ x,
                               __nv_bfloat16* __restrict__ xh,
                               __nv_bfloat16* __restrict__ xl, int R, int C)
{
    __shared__ float t[32][33];
    int r0 = blockIdx.y * 32, c0 = blockIdx.x * 32;
    int tx = threadIdx.x, ty = threadIdx.y;
#pragma unroll
    for (int j = 0; j < 4; j++)
        t[ty + 8 * j][tx] = x[(size_t)(r0 + ty + 8 * j) * C + c0 + tx];
    __syncthreads();
#pragma unroll
    for (int j = 0; j < 4; j++) {
        float v = t[tx][ty + 8 * j];
        __nv_bfloat16 hb = __float2bfloat16(v);
        size_t o = (size_t)(c0 + ty + 8 * j) * R + r0 + tx;
        xh[o] = hb;
        xl[o] = __float2bfloat16(v - __bfloat162float(hb));
    }
}

// ---------------------------------------------------------------------------
// bf16x3 GEMM via mma.sync: C[M,N] fp32 = (Ah+Al)[M,K] @ (Bh+Bl)[N,K]^T
// 128x128x32 block tile, 8 warps (warp tile 64x32), 3-stage cp.async
// pipeline, 2 CTAs/SM (96KB smem, <=128 regs).
// Smem row packs hi|lo: row r = [Xh r (64B) | Xl r (64B)], 128B xor-swizzle.
// ---------------------------------------------------------------------------
#define STAGE3_B 32768                 // A (16KB) + B (16KB)
#define B_OFF    16384
#define GEMM_SMEM (3 * STAGE3_B)       // 98304

#define LOAD_STAGE(c, s) do {                                                \
    int _k0 = (c) * 32;                                                      \
    uint32_t _stb = smb + (s) * STAGE3_B;                                    \
    _Pragma("unroll")                                                        \
    for (int _i = 0; _i < 4; _i++) {                                         \
        int _id = tid + _i * 256;                                            \
        int _row = _id >> 3, _ch = _id & 7;                                  \
        uint32_t _sw = (_row << 7) + ((_ch ^ (_row & 7)) << 4);              \
        size_t _go = (size_t)_row * K + _k0 + (_ch & 3) * 8;                 \
        cp16(_stb + _sw,         ((_ch < 4) ? srcAh : srcAl) + _go);         \
        cp16(_stb + B_OFF + _sw, ((_ch < 4) ? srcBh : srcBl) + _go);         \
    }                                                                        \
    asm volatile("cp.async.commit_group;");                                  \
} while (0)

__global__ __launch_bounds__(256, 2) void gemm_bf16x3(
    const __nv_bfloat16* __restrict__ Ah, const __nv_bfloat16* __restrict__ Al,
    const __nv_bfloat16* __restrict__ Bh, const __nv_bfloat16* __restrict__ Bl,
    float* __restrict__ C, int M, int N, int K)
{
    extern __shared__ char sm[];
    const uint32_t smb = smem_u32(sm);
    const int tid = threadIdx.x;
    const int wid = tid >> 5, lane = tid & 31;
    const int bm = blockIdx.y * 128, bn = blockIdx.x * 128;
    const int wm = (wid & 1) * 64, wn = (wid >> 1) * 32;

    const __nv_bfloat16* srcAh = Ah + (size_t)bm * K;
    const __nv_bfloat16* srcAl = Al + (size_t)bm * K;
    const __nv_bfloat16* srcBh = Bh + (size_t)bn * K;
    const __nv_bfloat16* srcBl = Bl + (size_t)bn * K;

    float acc[4][4][4];
#pragma unroll
    for (int i = 0; i < 4; i++)
#pragma unroll
        for (int j = 0; j < 4; j++)
#pragma unroll
            for (int e = 0; e < 4; e++) acc[i][j][e] = 0.f;

    const int NC = K / 32;
    LOAD_STAGE(0, 0);
    LOAD_STAGE(1, 1);

    int scur = 0, sload = 2;
    for (int c = 0; c < NC; c++) {
        __syncthreads();   // all warps done reading stage (c+2)%3's buffer
        if (c + 2 < NC) {
            LOAD_STAGE(c + 2, sload);
            asm volatile("cp.async.wait_group 2;");
        } else if (c + 1 < NC) {
            asm volatile("cp.async.wait_group 1;");
        } else {
            asm volatile("cp.async.wait_group 0;");
        }
        __syncthreads();

        const uint32_t base = smb + scur * STAGE3_B;
#pragma unroll
        for (int ks = 0; ks < 2; ks++) {
            const int c0 = ks * 2 + (lane >> 4);   // hi chunks 0..3
            uint32_t ah[4][4], al[4][4];
#pragma unroll
            for (int mi = 0; mi < 4; mi++) {
                int row = wm + mi * 16 + (lane & 15);
                uint32_t rb = (uint32_t)(row << 7);
                ldsm4(ah[mi], base + rb + (((c0    ) ^ (row & 7)) << 4));
                ldsm4(al[mi], base + rb + (((c0 + 4) ^ (row & 7)) << 4));
            }
#pragma unroll
            for (int ni = 0; ni < 2; ni++) {
                int row = wn + ni * 16 + (lane & 15);
                uint32_t rb = (uint32_t)(row << 7);
                uint32_t bh[4], bl[4];
                ldsm4(bh, base + B_OFF + rb + (((c0    ) ^ (row & 7)) << 4));
                ldsm4(bl, base + B_OFF + rb + (((c0 + 4) ^ (row & 7)) << 4));
#pragma unroll
                for (int mi = 0; mi < 4; mi++) {
#pragma unroll
                    for (int sel = 0; sel < 2; sel++) {
                        float* a = acc[mi][ni * 2 + sel];
                        mma16816(a, ah[mi], bh[sel], bh[sel + 2]);
                        mma16816(a, ah[mi], bl[sel], bl[sel + 2]);
                        mma16816(a, al[mi], bh[sel], bh[sel + 2]);
                    }
                }
            }
        }
        scur = (scur == 2) ? 0 : scur + 1;
        sload = (sload == 2) ? 0 : sload + 1;
    }

    const int g = lane >> 2, t = lane & 3;
#pragma unroll
    for (int mi = 0; mi < 4; mi++) {
#pragma unroll
        for (int nj = 0; nj < 4; nj++) {
            const float* a = acc[mi][nj];
            int row = bm + wm + mi * 16 + g;
            int col = bn + wn + nj * 8 + t * 2;
            *(float2*)&C[(size_t)row * N + col] = make_float2(a[0], a[1]);
            *(float2*)&C[(size_t)(row + 8) * N + col] = make_float2(a[2], a[3]);
        }
    }
}

// ---------------------------------------------------------------------------
// Pre-pass 1: RoPE + scale + hi/lo split of Q -> [B][NQ][S][D]
// ---------------------------------------------------------------------------
__global__ void rope_split_q(const float* __restrict__ qkv,
                             const float* __restrict__ cosb,
                             const float* __restrict__ sinb,
                             __nv_bfloat16* __restrict__ qh,
                             __nv_bfloat16* __restrict__ ql)
{
    int idx = blockIdx.x * blockDim.x + threadIdx.x;
    const int total = BB * SS * NQ * 64;
    if (idx >= total) return;
    int d = idx & 63;
    int rest = idx >> 6;
    int h = rest % NQ;
    int s = (rest / NQ) % SS;
    int b = rest / (NQ * SS);
    const float* base = &qkv[((size_t)(b * SS + s)) * QKVN + h * DD];
    float x1 = base[d], x2 = base[d + 64];
    float c0 = cosb[s * DD + d],      s0 = sinb[s * DD + d];
    float c1 = cosb[s * DD + d + 64], s1 = sinb[s * DD + d + 64];
    float y1 = (x1 * c0 - x2 * s0) * SCALE;
    float y2 = (x2 * c1 + x1 * s1) * SCALE;
    size_t o = (((size_t)(b * NQ + h)) * SS + s) * DD + d;
    __nv_bfloat16 h1 = __float2bfloat16(y1);
    __nv_bfloat16 h2 = __float2bfloat16(y2);
    qh[o] = h1;       qh[o + 64] = h2;
    ql[o] = __float2bfloat16(y1 - __bfloat162float(h1));
    ql[o + 64] = __float2bfloat16(y2 - __bfloat162float(h2));
}

// ---------------------------------------------------------------------------
// Pre-pass 2: unified KV hi/lo [B][NKV][T][D]; RoPE on new K rows.
// ---------------------------------------------------------------------------
__global__ void build_kv(const float* __restrict__ qkv,
                         const float* __restrict__ kcache,
                         const float* __restrict__ vcache,
                         const float* __restrict__ cosb,
                         const float* __restrict__ sinb,
                         __nv_bfloat16* __restrict__ khp, __nv_bfloat16* __restrict__ klp,
                         __nv_bfloat16* __restrict__ vhp, __nv_bfloat16* __restrict__ vlp)
{
    int idx = blockIdx.x * blockDim.x + threadIdx.x;
    const int total = BB * NKV * TT * 64;
    if (idx >= total) return;
    int d = idx & 63;
    int rest = idx >> 6;
    int t = rest % TT;
    int kh = (rest / TT) % NKV;
    int b = rest / (TT * NKV);

    float k1, k2, v1, v2;
    if (t < PP) {
        size_t src = (((size_t)(b * PP + t)) * NKV + kh) * DD;
        k1 = kcache[src + d]; k2 = kcache[src + d + 64];
        v1 = vcache[src + d]; v2 = vcache[src + d + 64];
    } else {
        int s = t - PP;
        const float* base = &qkv[((size_t)(b * SS + s)) * QKVN];
        float x1 = base[(NQ + kh) * DD + d], x2 = base[(NQ + kh) * DD + d + 64];
        float c0 = cosb[s * DD + d],      s0 = sinb[s * DD + d];
        float c1 = cosb[s * DD + d + 64], s1 = sinb[s * DD + d + 64];
        k1 = x1 * c0 - x2 * s0;
        k2 = x2 * c1 + x1 * s1;
        v1 = base[(NQ + NKV + kh) * DD + d];
        v2 = base[(NQ + NKV + kh) * DD + d + 64];
    }
    size_t o = (((size_t)(b * NKV + kh)) * TT + t) * DD + d;
    __nv_bfloat16 a;
    a = __float2bfloat16(k1); khp[o] = a;      klp[o] = __float2bfloat16(k1 - __bfloat162float(a));
    a = __float2bfloat16(k2); khp[o + 64] = a; klp[o + 64] = __float2bfloat16(k2 - __bfloat162float(a));
    a = __float2bfloat16(v1); vhp[o] = a;      vlp[o] = __float2bfloat16(v1 - __bfloat162float(a));
    a = __float2bfloat16(v2); vhp[o + 64] = a; vlp[o + 64] = __float2bfloat16(v2 - __bfloat162float(a));
}

// ---------------------------------------------------------------------------
// Flash attention on tensor cores, bf16x3 for QK and PV (unchanged).
// ---------------------------------------------------------------------------
#define FA_SMEM (4 * 64 * 256)   // 65536

__global__ __launch_bounds__(128) void flash_mma(
    const __nv_bfloat16* __restrict__ qh_g, const __nv_bfloat16* __restrict__ ql_g,
    const __nv_bfloat16* __restrict__ kh_g, const __nv_bfloat16* __restrict__ kl_g,
    const __nv_bfloat16* __restrict__ vh_g, const __nv_bfloat16* __restrict__ vl_g,
    __nv_bfloat16* __restrict__ attnh, __nv_bfloat16* __restrict__ attnl)
{
    extern __shared__ char sm[];
    const uint32_t smb = smem_u32(sm);
    const uint32_t KHO = 0, KLO = 16384, VHO = 32768, VLO = 49152;
    const int tid = threadIdx.x, lane = tid & 31, w = tid >> 5;
    const int qi = blockIdx.x, h = blockIdx.y, b = blockIdx.z;
    const int sq0 = qi * 64;
    const int khd = h >> 2;
    const int g = lane >> 2, t4 = lane & 3;
    const int r0 = w * 16 + g, r1 = r0 + 8;

    uint32_t qfh[8][4], qfl[8][4];
    {
        const __nv_bfloat16* qbh = qh_g + (((size_t)(b * NQ + h)) * SS + sq0) * DD;
        const __nv_bfloat16* qbl = ql_g + (((size_t)(b * NQ + h)) * SS + sq0) * DD;
#pragma unroll
        for (int ks = 0; ks < 8; ks++) {
            int c0 = ks * 16 + 2 * t4;
            qfh[ks][0] = *(const uint32_t*)(qbh + r0 * DD + c0);
            qfh[ks][1] = *(const uint32_t*)(qbh + r1 * DD + c0);
            qfh[ks][2] = *(const uint32_t*)(qbh + r0 * DD + c0 + 8);
            qfh[ks][3] = *(const uint32_t*)(qbh + r1 * DD + c0 + 8);
            qfl[ks][0] = *(const uint32_t*)(qbl + r0 * DD + c0);
            qfl[ks][1] = *(const uint32_t*)(qbl + r1 * DD + c0);
            qfl[ks][2] = *(const uint32_t*)(qbl + r0 * DD + c0 + 8);
            qfl[ks][3] = *(const uint32_t*)(qbl + r1 * DD + c0 + 8);
        }
    }

    float oacc[16][4];
#pragma unroll
    for (int i = 0; i < 16; i++)
#pragma unroll
        for (int j = 0; j < 4; j++) oacc[i][j] = 0.f;
    float m0 = -1e30f, m1 = -1e30f, l0 = 0.f, l1 = 0.f;

    const size_t kvb = ((size_t)(b * NKV + khd)) * TT * DD;
    const int nt = qi + 1 + PP / 64;

    for (int kt = 0; kt < nt; kt++) {
        __syncthreads();
        {
            const __nv_bfloat16* srcs[4] = {
                kh_g + kvb + (size_t)kt * 64 * DD,
                kl_g + kvb + (size_t)kt * 64 * DD,
                vh_g + kvb + (size_t)kt * 64 * DD,
                vl_g + kvb + (size_t)kt * 64 * DD };
            const uint32_t offs[4] = { KHO, KLO, VHO, VLO };
#pragma unroll
            for (int a = 0; a < 4; a++) {
#pragma unroll
                for (int i = 0; i < 8; i++) {
                    int id = tid + i * 128;
                    int r = id >> 4, ch = id & 15;
                    cp16(smb + offs[a] + r * 256 + ((ch ^ (r & 7)) << 4),
                         srcs[a] + r * DD + ch * 8);
                }
            }
            asm volatile("cp.async.commit_group;");
            asm volatile("cp.async.wait_group 0;");
            __syncthreads();
        }

        float sacc[8][4];
#pragma unroll
        for (int j = 0; j < 8; j++)
#pragma unroll
            for (int e = 0; e < 4; e++) sacc[j][e] = 0.f;
#pragma unroll
        for (int ks = 0; ks < 8; ks++) {
            const int c0 = ks * 2 + (lane >> 4);
#pragma unroll
            for (int kg = 0; kg < 4; kg++) {
                int r = kg * 16 + (lane & 15);
                uint32_t off = r * 256 + ((c0 ^ (r & 7)) << 4);
                uint32_t kbh[4], kbl[4];
                ldsm4(kbh, smb + KHO + off);
                ldsm4(kbl, smb + KLO + off);
#pragma unroll
                for (int sel = 0; sel < 2; sel++) {
                    float* sj = sacc[kg * 2 + sel];
                    mma16816(sj, qfh[ks], kbh[sel], kbh[sel + 2]);
                    mma16816(sj, qfh[ks], kbl[sel], kbl[sel + 2]);
                    mma16816(sj, qfl[ks], kbh[sel], kbh[sel + 2]);
                }
            }
        }

        if (kt == nt - 1) {
#pragma unroll
            for (int j = 0; j < 8; j++) {
                int cb = j * 8 + 2 * t4;
                if (cb     > r0) sacc[j][0] = -1e30f;
                if (cb + 1 > r0) sacc[j][1] = -1e30f;
                if (cb     > r1) sacc[j][2] = -1e30f;
                if (cb + 1 > r1) sacc[j][3] = -1e30f;
            }
        }

        float mx0 = m0, mx1 = m1;
#pragma unroll
        for (int j = 0; j < 8; j++) {
            mx0 = fmaxf(mx0, fmaxf(sacc[j][0], sacc[j][1]));
            mx1 = fmaxf(mx1, fmaxf(sacc[j][2], sacc[j][3]));
        }
        mx0 = fmaxf(mx0, __shfl_xor_sync(0xffffffff, mx0, 1));
        mx0 = fmaxf(mx0, __shfl_xor_sync(0xffffffff, mx0, 2));
        mx1 = fmaxf(mx1, __shfl_xor_sync(0xffffffff, mx1, 1));
        mx1 = fmaxf(mx1, __shfl_xor_sync(0xffffffff, mx1, 2));
        float rs0 = __expf(m0 - mx0), rs1 = __expf(m1 - mx1);
        m0 = mx0; m1 = mx1;
        l0 *= rs0; l1 *= rs1;

        uint32_t pfh[4][4], pfl[4][4];
#pragma unroll
        for (int j = 0; j < 8; j++) {
            float p0 = __expf(sacc[j][0] - m0);
            float p1 = __expf(sacc[j][1] - m0);
            float p2 = __expf(sacc[j][2] - m1);
            float p3 = __expf(sacc[j][3] - m1);
            l0 += p0 + p1; l1 += p2 + p3;
            int kk = j >> 1, u = (j & 1) * 2;
            __nv_bfloat162 hA = __float22bfloat162_rn(make_float2(p0, p1));
            float2 bA = __bfloat1622float2(hA);
            __nv_bfloat162 lA = __float22bfloat162_rn(make_float2(p0 - bA.x, p1 - bA.y));
            __nv_bfloat162 hB = __float22bfloat162_rn(make_float2(p2, p3));
            float2 bB = __bfloat1622float2(hB);
            __nv_bfloat162 lB = __float22bfloat162_rn(make_float2(p2 - bB.x, p3 - bB.y));
            pfh[kk][u]     = *(uint32_t*)&hA;
            pfh[kk][u + 1] = *(uint32_t*)&hB;
            pfl[kk][u]     = *(uint32_t*)&lA;
            pfl[kk][u + 1] = *(uint32_t*)&lB;
        }

#pragma unroll
        for (int i = 0; i < 16; i++) {
            oacc[i][0] *= rs0; oacc[i][1] *= rs0;
            oacc[i][2] *= rs1; oacc[i][3] *= rs1;
        }

#pragma unroll
        for (int kk = 0; kk < 4; kk++) {
#pragma unroll
            for (int dg = 0; dg < 8; dg++) {
                int r = kk * 16 + (lane & 15);
                int c0 = dg * 2 + (lane >> 4);
                uint32_t off = r * 256 + ((c0 ^ (r & 7)) << 4);
                uint32_t vbh[4], vbl[4];
                ldsm4t(vbh, smb + VHO + off);
                ldsm4t(vbl, smb + VLO + off);
                float* oA = oacc[dg * 2];
                float* oB = oacc[dg * 2 + 1];
                mma16816(oA, pfh[kk], vbh[0], vbh[1]);
                mma16816(oA, pfh[kk], vbl[0], vbl[1]);
                mma16816(oA, pfl[kk], vbh[0], vbh[1]);
                mma16816(oB, pfh[kk], vbh[2], vbh[3]);
                mma16816(oB, pfh[kk], vbl[2], vbl[3]);
                mma16816(oB, pfl[kk], vbh[2], vbh[3]);
            }
        }
    }

    l0 += __shfl_xor_sync(0xffffffff, l0, 1);
    l0 += __shfl_xor_sync(0xffffffff, l0, 2);
    l1 += __shfl_xor_sync(0xffffffff, l1, 1);
    l1 += __shfl_xor_sync(0xffffffff, l1, 2);
    float inv0 = 1.f / l0, inv1 = 1.f / l1;

    size_t rowA = ((size_t)(b * SS + sq0 + r0)) * (NQ * DD) + h * DD;
    size_t rowB = ((size_t)(b * SS + sq0 + r1)) * (NQ * DD) + h * DD;
#pragma unroll
    for (int dt = 0; dt < 16; dt++) {
        int c = dt * 8 + 2 * t4;
        float v0 = oacc[dt][0] * inv0, v1 = oacc[dt][1] * inv0;
        float v2 = oacc[dt][2] * inv1, v3 = oacc[dt][3] * inv1;
        __nv_bfloat162 hA = __float22bfloat162_rn(make_float2(v0, v1));
        float2 bA = __bfloat1622float2(hA);
        __nv_bfloat162 lA = __float22bfloat162_rn(make_float2(v0 - bA.x, v1 - bA.y));
        __nv_bfloat162 hB = __float22bfloat162_rn(make_float2(v2, v3));
        float2 bB = __bfloat1622float2(hB);
        __nv_bfloat162 lB = __float22bfloat162_rn(make_float2(v2 - bB.x, v3 - bB.y));
        *(__nv_bfloat162*)&attnh[rowA + c] = hA;
        *(__nv_bfloat162*)&attnl[rowA + c] = lA;
        *(__nv_bfloat162*)&attnh[rowB + c] = hB;
        *(__nv_bfloat162*)&attnl[rowB + c] = lB;
    }
}

// ---------------------------------------------------------------------------
extern "C" void kernel_launch(void* const* d_in, const int* in_sizes, int n_in,
                              void* d_out, int out_size)
{
    const float* hidden = (const float*)d_in[0];
    const float* w_qkv  = (const float*)d_in[1];
    const float* w_o    = (const float*)d_in[2];
    const float* cosb   = (const float*)d_in[3];
    const float* sinb   = (const float*)d_in[4];
    const float* kc     = (const float*)d_in[5];
    const float* vc     = (const float*)d_in[6];
    float* out = (float*)d_out;

    float *qkv;
    __nv_bfloat16 *hidh, *hidl, *wqh, *wql, *woh, *wol, *ath, *atl;
    __nv_bfloat16 *qh, *ql, *kh, *kl, *vh, *vl;
    cudaGetSymbolAddress((void**)&qkv, g_qkv);
    cudaGetSymbolAddress((void**)&hidh, g_hid_h);
    cudaGetSymbolAddress((void**)&hidl, g_hid_l);
    cudaGetSymbolAddress((void**)&wqh, g_wqkv_h);
    cudaGetSymbolAddress((void**)&wql, g_wqkv_l);
    cudaGetSymbolAddress((void**)&woh, g_wo_h);
    cudaGetSymbolAddress((void**)&wol, g_wo_l);
    cudaGetSymbolAddress((void**)&ath, g_attn_h);
    cudaGetSymbolAddress((void**)&atl, g_attn_l);
    cudaGetSymbolAddress((void**)&qh, g_q_h);
    cudaGetSymbolAddress((void**)&ql, g_q_l);
    cudaGetSymbolAddress((void**)&kh, g_k_h);
    cudaGetSymbolAddress((void**)&kl, g_k_l);
    cudaGetSymbolAddress((void**)&vh, g_v_h);
    cudaGetSymbolAddress((void**)&vl, g_v_l);

    cudaFuncSetAttribute(gemm_bf16x3,
                         cudaFuncAttributeMaxDynamicSharedMemorySize, GEMM_SMEM);
    cudaFuncSetAttribute(flash_mma,
                         cudaFuncAttributeMaxDynamicSharedMemorySize, FA_SMEM);

    const int M = BB * SS;  // 2048

    // 0) hi/lo splits (+ weight transposes to [N,K])
    {
        int n = M * HH;
        split_kernel<<<(n + 255) / 256, 256>>>(hidden, hidh, hidl, n);
        split_t_kernel<<<dim3(QKVN / 32, HH / 32), dim3(32, 8)>>>(
            w_qkv, wqh, wql, HH, QKVN);
        split_t_kernel<<<dim3(HH / 32, HH / 32), dim3(32, 8)>>>(
            w_o, woh, wol, HH, HH);
    }
    // 1) QKV projection
    gemm_bf16x3<<<dim3(QKVN / 128, M / 128), 256, GEMM_SMEM>>>(
        hidh, hidl, wqh, wql, qkv, M, QKVN, HH);
    // 2) pre-passes
    {
        int nq = BB * SS * NQ * 64;
        rope_split_q<<<(nq + 255) / 256, 256>>>(qkv, cosb, sinb, qh, ql);
        int nkv = BB * NKV * TT * 64;
        build_kv<<<(nkv + 255) / 256, 256>>>(qkv, kc, vc, cosb, sinb,
                                             kh, kl, vh, vl);
    }
    // 3) Flash attention
    flash_mma<<<dim3(SS / 64, NQ, BB), 128, FA_SMEM>>>(
        qh, ql, kh, kl, vh, vl, ath, atl);
    // 4) Output projection
    gemm_bf16x3<<<dim3(HH / 128, M / 128), 256, GEMM_SMEM>>>(
        ath, atl, woh, wol, out, M, HH, HH);
}

// round 7
// speedup vs baseline: 1.0587x; 1.0587x over previous
#include <cuda_runtime.h>
#include <cuda_bf16.h>
#include <math.h>
#include <stdint.h>

// Problem constants
#define BB   2
#define SS   1024
#define PP   1024
#define TT   (PP + SS)
#define HH   4096
#define NQ   32
#define NKV  8
#define DD   128
#define QKVN ((NQ + 2 * NKV) * DD)   // 6144
#define SCALE 0.08838834764831845f   // 1/sqrt(128)

// ---------------------------------------------------------------------------
// Scratch (device globals: no allocation allowed)
// ---------------------------------------------------------------------------
__device__ float g_qkv[BB * SS * QKVN];
__device__ __nv_bfloat16 g_hid_h[BB * SS * HH];
__device__ __nv_bfloat16 g_hid_l[BB * SS * HH];
__device__ __nv_bfloat16 g_wqkv_h[(size_t)QKVN * HH];   // transposed [N,K]
__device__ __nv_bfloat16 g_wqkv_l[(size_t)QKVN * HH];
__device__ __nv_bfloat16 g_wo_h[(size_t)HH * HH];       // transposed [N,K]
__device__ __nv_bfloat16 g_wo_l[(size_t)HH * HH];
__device__ __nv_bfloat16 g_attn_h[BB * SS * NQ * DD];
__device__ __nv_bfloat16 g_attn_l[BB * SS * NQ * DD];
// Q hi/lo [B][NQ][S][D]
__device__ __nv_bfloat16 g_q_h[(size_t)BB * NQ * SS * DD];
__device__ __nv_bfloat16 g_q_l[(size_t)BB * NQ * SS * DD];
// unified KV hi/lo [B][NKV][T][D]
__device__ __nv_bfloat16 g_k_h[(size_t)BB * NKV * TT * DD];
__device__ __nv_bfloat16 g_k_l[(size_t)BB * NKV * TT * DD];
__device__ __nv_bfloat16 g_v_h[(size_t)BB * NKV * TT * DD];
__device__ __nv_bfloat16 g_v_l[(size_t)BB * NKV * TT * DD];

// ---------------------------------------------------------------------------
// Low-level helpers (plain sm_80+ ISA)
// ---------------------------------------------------------------------------
__device__ __forceinline__ uint32_t smem_u32(const void* p) {
    uint32_t a;
    asm("{ .reg .u64 t; cvta.to.shared.u64 t, %1; cvt.u32.u64 %0, t; }"
        : "=r"(a) : "l"(p));
    return a;
}
__device__ __forceinline__ void cp16(uint32_t dst, const void* src) {
    asm volatile("cp.async.cg.shared.global [%0], [%1], 16;"
                 :: "r"(dst), "l"(src));
}
__device__ __forceinline__ void ldsm4(uint32_t* r, uint32_t a) {
    asm volatile("ldmatrix.sync.aligned.m8n8.x4.shared.b16 {%0,%1,%2,%3}, [%4];"
                 : "=r"(r[0]), "=r"(r[1]), "=r"(r[2]), "=r"(r[3]) : "r"(a));
}
__device__ __forceinline__ void ldsm4t(uint32_t* r, uint32_t a) {
    asm volatile("ldmatrix.sync.aligned.m8n8.x4.trans.shared.b16 {%0,%1,%2,%3}, [%4];"
                 : "=r"(r[0]), "=r"(r[1]), "=r"(r[2]), "=r"(r[3]) : "r"(a));
}
__device__ __forceinline__ void mma16816(float* c, const uint32_t* a,
                                         const uint32_t b0, const uint32_t b1) {
    asm volatile(
        "mma.sync.aligned.m16n8k16.row.col.f32.bf16.bf16.f32 "
        "{%0,%1,%2,%3}, {%4,%5,%6,%7}, {%8,%9}, {%0,%1,%2,%3};"
        : "+f"(c[0]), "+f"(c[1]), "+f"(c[2]), "+f"(c[3])
        : "r"(a[0]), "r"(a[1]), "r"(a[2]), "r"(a[3]), "r"(b0), "r"(b1));
}

// ---------------------------------------------------------------------------
// fp32 -> bf16 hi/lo split (same layout)
// ---------------------------------------------------------------------------
__global__ void split_kernel(const float* __restrict__ x,
                             __nv_bfloat16* __restrict__ xh,
                             __nv_bfloat16* __restrict__ xl, int n)
{
    int i = blockIdx.x * blockDim.x + threadIdx.x;
    if (i >= n) return;
    float v = x[i];
    __nv_bfloat16 hb = __float2bfloat16(v);
    xh[i] = hb;
    xl[i] = __float2bfloat16(v - __bfloat162float(hb));
}

// fp32 [R,C] -> bf16 hi/lo transposed [C,R]
__global__ void split_t_kernel(const float* __restrict__ x,
                               __nv_bfloat16* __restrict__ xh,
                               __nv_bfloat16* __restrict__ xl, int R, int C)
{
    __shared__ float t[32][33];
    int r0 = blockIdx.y * 32, c0 = blockIdx.x * 32;
    int tx = threadIdx.x, ty = threadIdx.y;
#pragma unroll
    for (int j = 0; j < 4; j++)
        t[ty + 8 * j][tx] = x[(size_t)(r0 + ty + 8 * j) * C + c0 + tx];
    __syncthreads();
#pragma unroll
    for (int j = 0; j < 4; j++) {
        float v = t[tx][ty + 8 * j];
        __nv_bfloat16 hb = __float2bfloat16(v);
        size_t o = (size_t)(c0 + ty + 8 * j) * R + r0 + tx;
        xh[o] = hb;
        xl[o] = __float2bfloat16(v - __bfloat162float(hb));
    }
}

// ---------------------------------------------------------------------------
// bf16x3 GEMM via mma.sync: C[M,N] fp32 = (Ah+Al)[M,K] @ (Bh+Bl)[N,K]^T
// 128x256x64 block tile, 8 warps (warp tile 64x64), cp.async double buffer.
// PASS-MAJOR MMA ordering: per k16 step, all fragments are loaded first,
// then pass hh -> hl -> lh each sweeps all 32 accumulators (reuse distance
// 32 MMAs instead of 1, hiding HMMA RAW latency).
// ---------------------------------------------------------------------------
#define AH_OFF 0
#define AL_OFF 16384
#define BH_OFF 32768
#define BL_OFF 65536
#define STAGE_B  98304
#define GEMM_SMEM (2 * STAGE_B)   // 196608

#define LOAD_STAGE(c, s) do {                                              \
    int _k0 = (c) * 64;                                                    \
    uint32_t _stb = smb + (s) * STAGE_B;                                   \
    _Pragma("unroll")                                                      \
    for (int _i = 0; _i < 4; _i++) {                                       \
        int _id = tid + _i * 256;                                          \
        int _row = _id >> 3, _ch = _id & 7;                                \
        uint32_t _sw = (_row << 7) + ((_ch ^ (_row & 7)) << 4);            \
        const size_t _go = (size_t)_row * K + _k0 + _ch * 8;               \
        cp16(_stb + AH_OFF + _sw, srcAh + _go);                            \
        cp16(_stb + AL_OFF + _sw, srcAl + _go);                            \
    }                                                                      \
    _Pragma("unroll")                                                      \
    for (int _i = 0; _i < 8; _i++) {                                       \
        int _id = tid + _i * 256;                                          \
        int _row = _id >> 3, _ch = _id & 7;                                \
        uint32_t _sw = (_row << 7) + ((_ch ^ (_row & 7)) << 4);            \
        const size_t _go = (size_t)_row * K + _k0 + _ch * 8;               \
        cp16(_stb + BH_OFF + _sw, srcBh + _go);                            \
        cp16(_stb + BL_OFF + _sw, srcBl + _go);                            \
    }                                                                      \
    asm volatile("cp.async.commit_group;");                                \
} while (0)

__global__ __launch_bounds__(256, 1) void gemm_bf16x3(
    const __nv_bfloat16* __restrict__ Ah, const __nv_bfloat16* __restrict__ Al,
    const __nv_bfloat16* __restrict__ Bh, const __nv_bfloat16* __restrict__ Bl,
    float* __restrict__ C, int M, int N, int K)
{
    extern __shared__ char sm[];
    const uint32_t smb = smem_u32(sm);
    const int tid = threadIdx.x;
    const int wid = tid >> 5, lane = tid & 31;
    const int bm = blockIdx.y * 128, bn = blockIdx.x * 256;
    const int wm = (wid & 1) * 64, wn = (wid >> 1) * 64;

    const __nv_bfloat16* srcAh = Ah + (size_t)bm * K;
    const __nv_bfloat16* srcAl = Al + (size_t)bm * K;
    const __nv_bfloat16* srcBh = Bh + (size_t)bn * K;
    const __nv_bfloat16* srcBl = Bl + (size_t)bn * K;

    float acc[4][8][4];
#pragma unroll
    for (int i = 0; i < 4; i++)
#pragma unroll
        for (int j = 0; j < 8; j++)
#pragma unroll
            for (int e = 0; e < 4; e++) acc[i][j][e] = 0.f;

    const int NC = K / 64;
    LOAD_STAGE(0, 0);

    for (int c = 0; c < NC; c++) {
        const int s = c & 1;
        if (c + 1 < NC) {
            LOAD_STAGE(c + 1, s ^ 1);
            asm volatile("cp.async.wait_group 1;");
        } else {
            asm volatile("cp.async.wait_group 0;");
        }
        __syncthreads();

        const uint32_t base = smb + s * STAGE_B;
#pragma unroll
        for (int ks = 0; ks < 4; ks++) {
            const int c0 = ks * 2 + (lane >> 4);
            uint32_t ah[4][4], al[4][4], bh[4][4], bl[4][4];
#pragma unroll
            for (int mi = 0; mi < 4; mi++) {
                int row = wm + mi * 16 + (lane & 15);
                uint32_t off = (row << 7) + ((c0 ^ (row & 7)) << 4);
                ldsm4(ah[mi], base + AH_OFF + off);
                ldsm4(al[mi], base + AL_OFF + off);
            }
#pragma unroll
            for (int ni = 0; ni < 4; ni++) {
                int row = wn + ni * 16 + (lane & 15);
                uint32_t off = (row << 7) + ((c0 ^ (row & 7)) << 4);
                ldsm4(bh[ni], base + BH_OFF + off);
                ldsm4(bl[ni], base + BL_OFF + off);
            }
            // pass 0: Ah * Bh  (32 independent accumulators)
#pragma unroll
            for (int mi = 0; mi < 4; mi++)
#pragma unroll
                for (int ni = 0; ni < 4; ni++)
#pragma unroll
                    for (int sel = 0; sel < 2; sel++)
                        mma16816(acc[mi][ni * 2 + sel], ah[mi],
                                 bh[ni][sel], bh[ni][sel + 2]);
            // pass 1: Ah * Bl
#pragma unroll
            for (int mi = 0; mi < 4; mi++)
#pragma unroll
                for (int ni = 0; ni < 4; ni++)
#pragma unroll
                    for (int sel = 0; sel < 2; sel++)
                        mma16816(acc[mi][ni * 2 + sel], ah[mi],
                                 bl[ni][sel], bl[ni][sel + 2]);
            // pass 2: Al * Bh
#pragma unroll
            for (int mi = 0; mi < 4; mi++)
#pragma unroll
                for (int ni = 0; ni < 4; ni++)
#pragma unroll
                    for (int sel = 0; sel < 2; sel++)
                        mma16816(acc[mi][ni * 2 + sel], al[mi],
                                 bh[ni][sel], bh[ni][sel + 2]);
        }
        __syncthreads();
    }

    const int g = lane >> 2, t = lane & 3;
#pragma unroll
    for (int mi = 0; mi < 4; mi++) {
#pragma unroll
        for (int nj = 0; nj < 8; nj++) {
            const float* a = acc[mi][nj];
            int row = bm + wm + mi * 16 + g;
            int col = bn + wn + nj * 8 + t * 2;
            *(float2*)&C[(size_t)row * N + col] = make_float2(a[0], a[1]);
            *(float2*)&C[(size_t)(row + 8) * N + col] = make_float2(a[2], a[3]);
        }
    }
}

// ---------------------------------------------------------------------------
// Pre-pass 1: RoPE + scale + hi/lo split of Q -> [B][NQ][S][D]
// ---------------------------------------------------------------------------
__global__ void rope_split_q(const float* __restrict__ qkv,
                             const float* __restrict__ cosb,
                             const float* __restrict__ sinb,
                             __nv_bfloat16* __restrict__ qh,
                             __nv_bfloat16* __restrict__ ql)
{
    int idx = blockIdx.x * blockDim.x + threadIdx.x;
    const int total = BB * SS * NQ * 64;
    if (idx >= total) return;
    int d = idx & 63;
    int rest = idx >> 6;
    int h = rest % NQ;
    int s = (rest / NQ) % SS;
    int b = rest / (NQ * SS);
    const float* base = &qkv[((size_t)(b * SS + s)) * QKVN + h * DD];
    float x1 = base[d], x2 = base[d + 64];
    float c0 = cosb[s * DD + d],      s0 = sinb[s * DD + d];
    float c1 = cosb[s * DD + d + 64], s1 = sinb[s * DD + d + 64];
    float y1 = (x1 * c0 - x2 * s0) * SCALE;
    float y2 = (x2 * c1 + x1 * s1) * SCALE;
    size_t o = (((size_t)(b * NQ + h)) * SS + s) * DD + d;
    __nv_bfloat16 h1 = __float2bfloat16(y1);
    __nv_bfloat16 h2 = __float2bfloat16(y2);
    qh[o] = h1;       qh[o + 64] = h2;
    ql[o] = __float2bfloat16(y1 - __bfloat162float(h1));
    ql[o + 64] = __float2bfloat16(y2 - __bfloat162float(h2));
}

// ---------------------------------------------------------------------------
// Pre-pass 2: unified KV hi/lo [B][NKV][T][D]; RoPE on new K rows.
// ---------------------------------------------------------------------------
__global__ void build_kv(const float* __restrict__ qkv,
                         const float* __restrict__ kcache,
                         const float* __restrict__ vcache,
                         const float* __restrict__ cosb,
                         const float* __restrict__ sinb,
                         __nv_bfloat16* __restrict__ khp, __nv_bfloat16* __restrict__ klp,
                         __nv_bfloat16* __restrict__ vhp, __nv_bfloat16* __restrict__ vlp)
{
    int idx = blockIdx.x * blockDim.x + threadIdx.x;
    const int total = BB * NKV * TT * 64;
    if (idx >= total) return;
    int d = idx & 63;
    int rest = idx >> 6;
    int t = rest % TT;
    int kh = (rest / TT) % NKV;
    int b = rest / (TT * NKV);

    float k1, k2, v1, v2;
    if (t < PP) {
        size_t src = (((size_t)(b * PP + t)) * NKV + kh) * DD;
        k1 = kcache[src + d]; k2 = kcache[src + d + 64];
        v1 = vcache[src + d]; v2 = vcache[src + d + 64];
    } else {
        int s = t - PP;
        const float* base = &qkv[((size_t)(b * SS + s)) * QKVN];
        float x1 = base[(NQ + kh) * DD + d], x2 = base[(NQ + kh) * DD + d + 64];
        float c0 = cosb[s * DD + d],      s0 = sinb[s * DD + d];
        float c1 = cosb[s * DD + d + 64], s1 = sinb[s * DD + d + 64];
        k1 = x1 * c0 - x2 * s0;
        k2 = x2 * c1 + x1 * s1;
        v1 = base[(NQ + NKV + kh) * DD + d];
        v2 = base[(NQ + NKV + kh) * DD + d + 64];
    }
    size_t o = (((size_t)(b * NKV + kh)) * TT + t) * DD + d;
    __nv_bfloat16 a;
    a = __float2bfloat16(k1); khp[o] = a;      klp[o] = __float2bfloat16(k1 - __bfloat162float(a));
    a = __float2bfloat16(k2); khp[o + 64] = a; klp[o + 64] = __float2bfloat16(k2 - __bfloat162float(a));
    a = __float2bfloat16(v1); vhp[o] = a;      vlp[o] = __float2bfloat16(v1 - __bfloat162float(a));
    a = __float2bfloat16(v2); vhp[o + 64] = a; vlp[o + 64] = __float2bfloat16(v2 - __bfloat162float(a));
}

// ---------------------------------------------------------------------------
// Flash attention on tensor cores, bf16x3, pass-major MMA ordering.
// ---------------------------------------------------------------------------
#define FA_SMEM (4 * 64 * 256)   // 65536

__global__ __launch_bounds__(128) void flash_mma(
    const __nv_bfloat16* __restrict__ qh_g, const __nv_bfloat16* __restrict__ ql_g,
    const __nv_bfloat16* __restrict__ kh_g, const __nv_bfloat16* __restrict__ kl_g,
    const __nv_bfloat16* __restrict__ vh_g, const __nv_bfloat16* __restrict__ vl_g,
    __nv_bfloat16* __restrict__ attnh, __nv_bfloat16* __restrict__ attnl)
{
    extern __shared__ char sm[];
    const uint32_t smb = smem_u32(sm);
    const uint32_t KHO = 0, KLO = 16384, VHO = 32768, VLO = 49152;
    const int tid = threadIdx.x, lane = tid & 31, w = tid >> 5;
    const int qi = blockIdx.x, h = blockIdx.y, b = blockIdx.z;
    const int sq0 = qi * 64;
    const int khd = h >> 2;
    const int g = lane >> 2, t4 = lane & 3;
    const int r0 = w * 16 + g, r1 = r0 + 8;

    uint32_t qfh[8][4], qfl[8][4];
    {
        const __nv_bfloat16* qbh = qh_g + (((size_t)(b * NQ + h)) * SS + sq0) * DD;
        const __nv_bfloat16* qbl = ql_g + (((size_t)(b * NQ + h)) * SS + sq0) * DD;
#pragma unroll
        for (int ks = 0; ks < 8; ks++) {
            int c0 = ks * 16 + 2 * t4;
            qfh[ks][0] = *(const uint32_t*)(qbh + r0 * DD + c0);
            qfh[ks][1] = *(const uint32_t*)(qbh + r1 * DD + c0);
            qfh[ks][2] = *(const uint32_t*)(qbh + r0 * DD + c0 + 8);
            qfh[ks][3] = *(const uint32_t*)(qbh + r1 * DD + c0 + 8);
            qfl[ks][0] = *(const uint32_t*)(qbl + r0 * DD + c0);
            qfl[ks][1] = *(const uint32_t*)(qbl + r1 * DD + c0);
            qfl[ks][2] = *(const uint32_t*)(qbl + r0 * DD + c0 + 8);
            qfl[ks][3] = *(const uint32_t*)(qbl + r1 * DD + c0 + 8);
        }
    }

    float oacc[16][4];
#pragma unroll
    for (int i = 0; i < 16; i++)
#pragma unroll
        for (int j = 0; j < 4; j++) oacc[i][j] = 0.f;
    float m0 = -1e30f, m1 = -1e30f, l0 = 0.f, l1 = 0.f;

    const size_t kvb = ((size_t)(b * NKV + khd)) * TT * DD;
    const int nt = qi + 1 + PP / 64;

    for (int kt = 0; kt < nt; kt++) {
        __syncthreads();
        {
            const __nv_bfloat16* srcs[4] = {
                kh_g + kvb + (size_t)kt * 64 * DD,
                kl_g + kvb + (size_t)kt * 64 * DD,
                vh_g + kvb + (size_t)kt * 64 * DD,
                vl_g + kvb + (size_t)kt * 64 * DD };
            const uint32_t offs[4] = { KHO, KLO, VHO, VLO };
#pragma unroll
            for (int a = 0; a < 4; a++) {
#pragma unroll
                for (int i = 0; i < 8; i++) {
                    int id = tid + i * 128;
                    int r = id >> 4, ch = id & 15;
                    cp16(smb + offs[a] + r * 256 + ((ch ^ (r & 7)) << 4),
                         srcs[a] + r * DD + ch * 8);
                }
            }
            asm volatile("cp.async.commit_group;");
            asm volatile("cp.async.wait_group 0;");
            __syncthreads();
        }

        float sacc[8][4];
#pragma unroll
        for (int j = 0; j < 8; j++)
#pragma unroll
            for (int e = 0; e < 4; e++) sacc[j][e] = 0.f;
#pragma unroll
        for (int ks = 0; ks < 8; ks++) {
            const int c0 = ks * 2 + (lane >> 4);
            uint32_t kbh[4][4], kbl[4][4];
#pragma unroll
            for (int kg = 0; kg < 4; kg++) {
                int r = kg * 16 + (lane & 15);
                uint32_t off = r * 256 + ((c0 ^ (r & 7)) << 4);
                ldsm4(kbh[kg], smb + KHO + off);
                ldsm4(kbl[kg], smb + KLO + off);
            }
            // pass 0: Qh * Kh
#pragma unroll
            for (int kg = 0; kg < 4; kg++)
#pragma unroll
                for (int sel = 0; sel < 2; sel++)
                    mma16816(sacc[kg * 2 + sel], qfh[ks],
                             kbh[kg][sel], kbh[kg][sel + 2]);
            // pass 1: Qh * Kl
#pragma unroll
            for (int kg = 0; kg < 4; kg++)
#pragma unroll
                for (int sel = 0; sel < 2; sel++)
                    mma16816(sacc[kg * 2 + sel], qfh[ks],
                             kbl[kg][sel], kbl[kg][sel + 2]);
            // pass 2: Ql * Kh
#pragma unroll
            for (int kg = 0; kg < 4; kg++)
#pragma unroll
                for (int sel = 0; sel < 2; sel++)
                    mma16816(sacc[kg * 2 + sel], qfl[ks],
                             kbh[kg][sel], kbh[kg][sel + 2]);
        }

        if (kt == nt - 1) {
#pragma unroll
            for (int j = 0; j < 8; j++) {
                int cb = j * 8 + 2 * t4;
                if (cb     > r0) sacc[j][0] = -1e30f;
                if (cb + 1 > r0) sacc[j][1] = -1e30f;
                if (cb     > r1) sacc[j][2] = -1e30f;
                if (cb + 1 > r1) sacc[j][3] = -1e30f;
            }
        }

        float mx0 = m0, mx1 = m1;
#pragma unroll
        for (int j = 0; j < 8; j++) {
            mx0 = fmaxf(mx0, fmaxf(sacc[j][0], sacc[j][1]));
            mx1 = fmaxf(mx1, fmaxf(sacc[j][2], sacc[j][3]));
        }
        mx0 = fmaxf(mx0, __shfl_xor_sync(0xffffffff, mx0, 1));
        mx0 = fmaxf(mx0, __shfl_xor_sync(0xffffffff, mx0, 2));
        mx1 = fmaxf(mx1, __shfl_xor_sync(0xffffffff, mx1, 1));
        mx1 = fmaxf(mx1, __shfl_xor_sync(0xffffffff, mx1, 2));
        float rs0 = __expf(m0 - mx0), rs1 = __expf(m1 - mx1);
        m0 = mx0; m1 = mx1;
        l0 *= rs0; l1 *= rs1;

        uint32_t pfh[4][4], pfl[4][4];
#pragma unroll
        for (int j = 0; j < 8; j++) {
            float p0 = __expf(sacc[j][0] - m0);
            float p1 = __expf(sacc[j][1] - m0);
            float p2 = __expf(sacc[j][2] - m1);
            float p3 = __expf(sacc[j][3] - m1);
            l0 += p0 + p1; l1 += p2 + p3;
            int kk = j >> 1, u = (j & 1) * 2;
            __nv_bfloat162 hA = __float22bfloat162_rn(make_float2(p0, p1));
            float2 bA = __bfloat1622float2(hA);
            __nv_bfloat162 lA = __float22bfloat162_rn(make_float2(p0 - bA.x, p1 - bA.y));
            __nv_bfloat162 hB = __float22bfloat162_rn(make_float2(p2, p3));
            float2 bB = __bfloat1622float2(hB);
            __nv_bfloat162 lB = __float22bfloat162_rn(make_float2(p2 - bB.x, p3 - bB.y));
            pfh[kk][u]     = *(uint32_t*)&hA;
            pfh[kk][u + 1] = *(uint32_t*)&hB;
            pfl[kk][u]     = *(uint32_t*)&lA;
            pfl[kk][u + 1] = *(uint32_t*)&lB;
        }

#pragma unroll
        for (int i = 0; i < 16; i++) {
            oacc[i][0] *= rs0; oacc[i][1] *= rs0;
            oacc[i][2] *= rs1; oacc[i][3] *= rs1;
        }

        // O += P V, pairwise-dg fragments, pass-major (4 independent accs)
#pragma unroll
        for (int kk = 0; kk < 4; kk++) {
#pragma unroll
            for (int dp = 0; dp < 4; dp++) {
                const int dg0 = dp * 2, dg1 = dp * 2 + 1;
                int r = kk * 16 + (lane & 15);
                int cA = dg0 * 2 + (lane >> 4);
                int cB = dg1 * 2 + (lane >> 4);
                uint32_t offA = r * 256 + ((cA ^ (r & 7)) << 4);
                uint32_t offB = r * 256 + ((cB ^ (r & 7)) << 4);
                uint32_t vh0[4], vl0[4], vh1[4], vl1[4];
                ldsm4t(vh0, smb + VHO + offA);
                ldsm4t(vl0, smb + VLO + offA);
                ldsm4t(vh1, smb + VHO + offB);
                ldsm4t(vl1, smb + VLO + offB);
                float* o0 = oacc[dg0 * 2];
                float* o1 = oacc[dg0 * 2 + 1];
                float* o2 = oacc[dg1 * 2];
                float* o3 = oacc[dg1 * 2 + 1];
                // pass 0: Ph * Vh
                mma16816(o0, pfh[kk], vh0[0], vh0[1]);
                mma16816(o1, pfh[kk], vh0[2], vh0[3]);
                mma16816(o2, pfh[kk], vh1[0], vh1[1]);
                mma16816(o3, pfh[kk], vh1[2], vh1[3]);
                // pass 1: Ph * Vl
                mma16816(o0, pfh[kk], vl0[0], vl0[1]);
                mma16816(o1, pfh[kk], vl0[2], vl0[3]);
                mma16816(o2, pfh[kk], vl1[0], vl1[1]);
                mma16816(o3, pfh[kk], vl1[2], vl1[3]);
                // pass 2: Pl * Vh
                mma16816(o0, pfl[kk], vh0[0], vh0[1]);
                mma16816(o1, pfl[kk], vh0[2], vh0[3]);
                mma16816(o2, pfl[kk], vh1[0], vh1[1]);
                mma16816(o3, pfl[kk], vh1[2], vh1[3]);
            }
        }
    }

    l0 += __shfl_xor_sync(0xffffffff, l0, 1);
    l0 += __shfl_xor_sync(0xffffffff, l0, 2);
    l1 += __shfl_xor_sync(0xffffffff, l1, 1);
    l1 += __shfl_xor_sync(0xffffffff, l1, 2);
    float inv0 = 1.f / l0, inv1 = 1.f / l1;

    size_t rowA = ((size_t)(b * SS + sq0 + r0)) * (NQ * DD) + h * DD;
    size_t rowB = ((size_t)(b * SS + sq0 + r1)) * (NQ * DD) + h * DD;
#pragma unroll
    for (int dt = 0; dt < 16; dt++) {
        int c = dt * 8 + 2 * t4;
        float v0 = oacc[dt][0] * inv0, v1 = oacc[dt][1] * inv0;
        float v2 = oacc[dt][2] * inv1, v3 = oacc[dt][3] * inv1;
        __nv_bfloat162 hA = __float22bfloat162_rn(make_float2(v0, v1));
        float2 bA = __bfloat1622float2(hA);
        __nv_bfloat162 lA = __float22bfloat162_rn(make_float2(v0 - bA.x, v1 - bA.y));
        __nv_bfloat162 hB = __float22bfloat162_rn(make_float2(v2, v3));
        float2 bB = __bfloat1622float2(hB);
        __nv_bfloat162 lB = __float22bfloat162_rn(make_float2(v2 - bB.x, v3 - bB.y));
        *(__nv_bfloat162*)&attnh[rowA + c] = hA;
        *(__nv_bfloat162*)&attnl[rowA + c] = lA;
        *(__nv_bfloat162*)&attnh[rowB + c] = hB;
        *(__nv_bfloat162*)&attnl[rowB + c] = lB;
    }
}

// ---------------------------------------------------------------------------
extern "C" void kernel_launch(void* const* d_in, const int* in_sizes, int n_in,
                              void* d_out, int out_size)
{
    const float* hidden = (const float*)d_in[0];
    const float* w_qkv  = (const float*)d_in[1];
    const float* w_o    = (const float*)d_in[2];
    const float* cosb   = (const float*)d_in[3];
    const float* sinb   = (const float*)d_in[4];
    const float* kc     = (const float*)d_in[5];
    const float* vc     = (const float*)d_in[6];
    float* out = (float*)d_out;

    float *qkv;
    __nv_bfloat16 *hidh, *hidl, *wqh, *wql, *woh, *wol, *ath, *atl;
    __nv_bfloat16 *qh, *ql, *kh, *kl, *vh, *vl;
    cudaGetSymbolAddress((void**)&qkv, g_qkv);
    cudaGetSymbolAddress((void**)&hidh, g_hid_h);
    cudaGetSymbolAddress((void**)&hidl, g_hid_l);
    cudaGetSymbolAddress((void**)&wqh, g_wqkv_h);
    cudaGetSymbolAddress((void**)&wql, g_wqkv_l);
    cudaGetSymbolAddress((void**)&woh, g_wo_h);
    cudaGetSymbolAddress((void**)&wol, g_wo_l);
    cudaGetSymbolAddress((void**)&ath, g_attn_h);
    cudaGetSymbolAddress((void**)&atl, g_attn_l);
    cudaGetSymbolAddress((void**)&qh, g_q_h);
    cudaGetSymbolAddress((void**)&ql, g_q_l);
    cudaGetSymbolAddress((void**)&kh, g_k_h);
    cudaGetSymbolAddress((void**)&kl, g_k_l);
    cudaGetSymbolAddress((void**)&vh, g_v_h);
    cudaGetSymbolAddress((void**)&vl, g_v_l);

    cudaFuncSetAttribute(gemm_bf16x3,
                         cudaFuncAttributeMaxDynamicSharedMemorySize, GEMM_SMEM);
    cudaFuncSetAttribute(flash_mma,
                         cudaFuncAttributeMaxDynamicSharedMemorySize, FA_SMEM);

    const int M = BB * SS;  // 2048

    // 0) hi/lo splits (+ weight transposes to [N,K])
    {
        int n = M * HH;
        split_kernel<<<(n + 255) / 256, 256>>>(hidden, hidh, hidl, n);
        split_t_kernel<<<dim3(QKVN / 32, HH / 32), dim3(32, 8)>>>(
            w_qkv, wqh, wql, HH, QKVN);
        split_t_kernel<<<dim3(HH / 32, HH / 32), dim3(32, 8)>>>(
            w_o, woh, wol, HH, HH);
    }
    // 1) QKV projection
    gemm_bf16x3<<<dim3(QKVN / 256, M / 128), 256, GEMM_SMEM>>>(
        hidh, hidl, wqh, wql, qkv, M, QKVN, HH);
    // 2) pre-passes
    {
        int nq = BB * SS * NQ * 64;
        rope_split_q<<<(nq + 255) / 256, 256>>>(qkv, cosb, sinb, qh, ql);
        int nkv = BB * NKV * TT * 64;
        build_kv<<<(nkv + 255) / 256, 256>>>(qkv, kc, vc, cosb, sinb,
                                             kh, kl, vh, vl);
    }
    // 3) Flash attention
    flash_mma<<<dim3(SS / 64, NQ, BB), 128, FA_SMEM>>>(
        qh, ql, kh, kl, vh, vl, ath, atl);
    // 4) Output projection
    gemm_bf16x3<<<dim3(HH / 256, M / 128), 256, GEMM_SMEM>>>(
        ath, atl, woh, wol, out, M, HH, HH);
}

// round 8
// speedup vs baseline: 1.2142x; 1.1469x over previous
#include <cuda_runtime.h>
#include <cuda_bf16.h>
#include <cuda_fp16.h>
#include <math.h>
#include <stdint.h>

// Problem constants
#define BB   2
#define SS   1024
#define PP   1024
#define TT   (PP + SS)
#define HH   4096
#define NQ   32
#define NKV  8
#define DD   128
#define QKVN ((NQ + 2 * NKV) * DD)   // 6144
#define SCALE 0.08838834764831845f   // 1/sqrt(128)

// ---------------------------------------------------------------------------
// Scratch (device globals: no allocation allowed)
// ---------------------------------------------------------------------------
__device__ float g_qkv[BB * SS * QKVN];
__device__ __nv_bfloat16 g_hid_h[BB * SS * HH];
__device__ __nv_bfloat16 g_hid_l[BB * SS * HH];
__device__ __nv_bfloat16 g_wqkv_h[(size_t)QKVN * HH];   // transposed [N,K]
__device__ __nv_bfloat16 g_wqkv_l[(size_t)QKVN * HH];
__device__ __nv_bfloat16 g_wo_h[(size_t)HH * HH];       // transposed [N,K]
__device__ __nv_bfloat16 g_wo_l[(size_t)HH * HH];
__device__ __nv_bfloat16 g_attn_h[BB * SS * NQ * DD];
__device__ __nv_bfloat16 g_attn_l[BB * SS * NQ * DD];
// fp16 Q [B][NQ][S][D], unified fp16 KV [B][NKV][T][D]
__device__ __half g_q_f[(size_t)BB * NQ * SS * DD];
__device__ __half g_k_f[(size_t)BB * NKV * TT * DD];
__device__ __half g_v_f[(size_t)BB * NKV * TT * DD];

// ---------------------------------------------------------------------------
// Low-level helpers (plain sm_80+ ISA)
// ---------------------------------------------------------------------------
__device__ __forceinline__ uint32_t smem_u32(const void* p) {
    uint32_t a;
    asm("{ .reg .u64 t; cvta.to.shared.u64 t, %1; cvt.u32.u64 %0, t; }"
        : "=r"(a) : "l"(p));
    return a;
}
__device__ __forceinline__ void cp16(uint32_t dst, const void* src) {
    asm volatile("cp.async.cg.shared.global [%0], [%1], 16;"
                 :: "r"(dst), "l"(src));
}
__device__ __forceinline__ void ldsm4(uint32_t* r, uint32_t a) {
    asm volatile("ldmatrix.sync.aligned.m8n8.x4.shared.b16 {%0,%1,%2,%3}, [%4];"
                 : "=r"(r[0]), "=r"(r[1]), "=r"(r[2]), "=r"(r[3]) : "r"(a));
}
__device__ __forceinline__ void ldsm4t(uint32_t* r, uint32_t a) {
    asm volatile("ldmatrix.sync.aligned.m8n8.x4.trans.shared.b16 {%0,%1,%2,%3}, [%4];"
                 : "=r"(r[0]), "=r"(r[1]), "=r"(r[2]), "=r"(r[3]) : "r"(a));
}
// bf16 mma
__device__ __forceinline__ void mma16816(float* c, const uint32_t* a,
                                         const uint32_t b0, const uint32_t b1) {
    asm volatile(
        "mma.sync.aligned.m16n8k16.row.col.f32.bf16.bf16.f32 "
        "{%0,%1,%2,%3}, {%4,%5,%6,%7}, {%8,%9}, {%0,%1,%2,%3};"
        : "+f"(c[0]), "+f"(c[1]), "+f"(c[2]), "+f"(c[3])
        : "r"(a[0]), "r"(a[1]), "r"(a[2]), "r"(a[3]), "r"(b0), "r"(b1));
}
// fp16 mma
__device__ __forceinline__ void mma16816h(float* c, const uint32_t* a,
                                          const uint32_t b0, const uint32_t b1) {
    asm volatile(
        "mma.sync.aligned.m16n8k16.row.col.f32.f16.f16.f32 "
        "{%0,%1,%2,%3}, {%4,%5,%6,%7}, {%8,%9}, {%0,%1,%2,%3};"
        : "+f"(c[0]), "+f"(c[1]), "+f"(c[2]), "+f"(c[3])
        : "r"(a[0]), "r"(a[1]), "r"(a[2]), "r"(a[3]), "r"(b0), "r"(b1));
}

// ---------------------------------------------------------------------------
// fp32 -> bf16 hi/lo split (same layout)
// ---------------------------------------------------------------------------
__global__ void split_kernel(const float* __restrict__ x,
                             __nv_bfloat16* __restrict__ xh,
                             __nv_bfloat16* __restrict__ xl, int n)
{
    int i = blockIdx.x * blockDim.x + threadIdx.x;
    if (i >= n) return;
    float v = x[i];
    __nv_bfloat16 hb = __float2bfloat16(v);
    xh[i] = hb;
    xl[i] = __float2bfloat16(v - __bfloat162float(hb));
}

// fp32 [R,C] -> bf16 hi/lo transposed [C,R]
__global__ void split_t_kernel(const float* __restrict__ x,
                               __nv_bfloat16* __restrict__ xh,
                               __nv_bfloat16* __restrict__ xl, int R, int C)
{
    __shared__ float t[32][33];
    int r0 = blockIdx.y * 32, c0 = blockIdx.x * 32;
    int tx = threadIdx.x, ty = threadIdx.y;
#pragma unroll
    for (int j = 0; j < 4; j++)
        t[ty + 8 * j][tx] = x[(size_t)(r0 + ty + 8 * j) * C + c0 + tx];
    __syncthreads();
#pragma unroll
    for (int j = 0; j < 4; j++) {
        float v = t[tx][ty + 8 * j];
        __nv_bfloat16 hb = __float2bfloat16(v);
        size_t o = (size_t)(c0 + ty + 8 * j) * R + r0 + tx;
        xh[o] = hb;
        xl[o] = __float2bfloat16(v - __bfloat162float(hb));
    }
}

// ---------------------------------------------------------------------------
// bf16x3 GEMM via mma.sync (identical to round 7; 58% tensor)
// ---------------------------------------------------------------------------
#define AH_OFF 0
#define AL_OFF 16384
#define BH_OFF 32768
#define BL_OFF 65536
#define STAGE_B  98304
#define GEMM_SMEM (2 * STAGE_B)   // 196608

#define LOAD_STAGE(c, s) do {                                              \
    int _k0 = (c) * 64;                                                    \
    uint32_t _stb = smb + (s) * STAGE_B;                                   \
    _Pragma("unroll")                                                      \
    for (int _i = 0; _i < 4; _i++) {                                       \
        int _id = tid + _i * 256;                                          \
        int _row = _id >> 3, _ch = _id & 7;                                \
        uint32_t _sw = (_row << 7) + ((_ch ^ (_row & 7)) << 4);            \
        const size_t _go = (size_t)_row * K + _k0 + _ch * 8;               \
        cp16(_stb + AH_OFF + _sw, srcAh + _go);                            \
        cp16(_stb + AL_OFF + _sw, srcAl + _go);                            \
    }                                                                      \
    _Pragma("unroll")                                                      \
    for (int _i = 0; _i < 8; _i++) {                                       \
        int _id = tid + _i * 256;                                          \
        int _row = _id >> 3, _ch = _id & 7;                                \
        uint32_t _sw = (_row << 7) + ((_ch ^ (_row & 7)) << 4);            \
        const size_t _go = (size_t)_row * K + _k0 + _ch * 8;               \
        cp16(_stb + BH_OFF + _sw, srcBh + _go);                            \
        cp16(_stb + BL_OFF + _sw, srcBl + _go);                            \
    }                                                                      \
    asm volatile("cp.async.commit_group;");                                \
} while (0)

__global__ __launch_bounds__(256, 1) void gemm_bf16x3(
    const __nv_bfloat16* __restrict__ Ah, const __nv_bfloat16* __restrict__ Al,
    const __nv_bfloat16* __restrict__ Bh, const __nv_bfloat16* __restrict__ Bl,
    float* __restrict__ C, int M, int N, int K)
{
    extern __shared__ char sm[];
    const uint32_t smb = smem_u32(sm);
    const int tid = threadIdx.x;
    const int wid = tid >> 5, lane = tid & 31;
    const int bm = blockIdx.y * 128, bn = blockIdx.x * 256;
    const int wm = (wid & 1) * 64, wn = (wid >> 1) * 64;

    const __nv_bfloat16* srcAh = Ah + (size_t)bm * K;
    const __nv_bfloat16* srcAl = Al + (size_t)bm * K;
    const __nv_bfloat16* srcBh = Bh + (size_t)bn * K;
    const __nv_bfloat16* srcBl = Bl + (size_t)bn * K;

    float acc[4][8][4];
#pragma unroll
    for (int i = 0; i < 4; i++)
#pragma unroll
        for (int j = 0; j < 8; j++)
#pragma unroll
            for (int e = 0; e < 4; e++) acc[i][j][e] = 0.f;

    const int NC = K / 64;
    LOAD_STAGE(0, 0);

    for (int c = 0; c < NC; c++) {
        const int s = c & 1;
        if (c + 1 < NC) {
            LOAD_STAGE(c + 1, s ^ 1);
            asm volatile("cp.async.wait_group 1;");
        } else {
            asm volatile("cp.async.wait_group 0;");
        }
        __syncthreads();

        const uint32_t base = smb + s * STAGE_B;
#pragma unroll
        for (int ks = 0; ks < 4; ks++) {
            const int c0 = ks * 2 + (lane >> 4);
            uint32_t ah[4][4], al[4][4], bh[4][4], bl[4][4];
#pragma unroll
            for (int mi = 0; mi < 4; mi++) {
                int row = wm + mi * 16 + (lane & 15);
                uint32_t off = (row << 7) + ((c0 ^ (row & 7)) << 4);
                ldsm4(ah[mi], base + AH_OFF + off);
                ldsm4(al[mi], base + AL_OFF + off);
            }
#pragma unroll
            for (int ni = 0; ni < 4; ni++) {
                int row = wn + ni * 16 + (lane & 15);
                uint32_t off = (row << 7) + ((c0 ^ (row & 7)) << 4);
                ldsm4(bh[ni], base + BH_OFF + off);
                ldsm4(bl[ni], base + BL_OFF + off);
            }
#pragma unroll
            for (int mi = 0; mi < 4; mi++)
#pragma unroll
                for (int ni = 0; ni < 4; ni++)
#pragma unroll
                    for (int sel = 0; sel < 2; sel++)
                        mma16816(acc[mi][ni * 2 + sel], ah[mi],
                                 bh[ni][sel], bh[ni][sel + 2]);
#pragma unroll
            for (int mi = 0; mi < 4; mi++)
#pragma unroll
                for (int ni = 0; ni < 4; ni++)
#pragma unroll
                    for (int sel = 0; sel < 2; sel++)
                        mma16816(acc[mi][ni * 2 + sel], ah[mi],
                                 bl[ni][sel], bl[ni][sel + 2]);
#pragma unroll
            for (int mi = 0; mi < 4; mi++)
#pragma unroll
                for (int ni = 0; ni < 4; ni++)
#pragma unroll
                    for (int sel = 0; sel < 2; sel++)
                        mma16816(acc[mi][ni * 2 + sel], al[mi],
                                 bh[ni][sel], bh[ni][sel + 2]);
        }
        __syncthreads();
    }

    const int g = lane >> 2, t = lane & 3;
#pragma unroll
    for (int mi = 0; mi < 4; mi++) {
#pragma unroll
        for (int nj = 0; nj < 8; nj++) {
            const float* a = acc[mi][nj];
            int row = bm + wm + mi * 16 + g;
            int col = bn + wn + nj * 8 + t * 2;
            *(float2*)&C[(size_t)row * N + col] = make_float2(a[0], a[1]);
            *(float2*)&C[(size_t)(row + 8) * N + col] = make_float2(a[2], a[3]);
        }
    }
}

// ---------------------------------------------------------------------------
// Pre-pass 1: RoPE + scale, fp16 Q -> [B][NQ][S][D]
// ---------------------------------------------------------------------------
__global__ void rope_q_f16(const float* __restrict__ qkv,
                           const float* __restrict__ cosb,
                           const float* __restrict__ sinb,
                           __half* __restrict__ qf)
{
    int idx = blockIdx.x * blockDim.x + threadIdx.x;
    const int total = BB * SS * NQ * 64;
    if (idx >= total) return;
    int d = idx & 63;
    int rest = idx >> 6;
    int h = rest % NQ;
    int s = (rest / NQ) % SS;
    int b = rest / (NQ * SS);
    const float* base = &qkv[((size_t)(b * SS + s)) * QKVN + h * DD];
    float x1 = base[d], x2 = base[d + 64];
    float c0 = cosb[s * DD + d],      s0 = sinb[s * DD + d];
    float c1 = cosb[s * DD + d + 64], s1 = sinb[s * DD + d + 64];
    size_t o = (((size_t)(b * NQ + h)) * SS + s) * DD + d;
    qf[o]      = __float2half((x1 * c0 - x2 * s0) * SCALE);
    qf[o + 64] = __float2half((x2 * c1 + x1 * s1) * SCALE);
}

// ---------------------------------------------------------------------------
// Pre-pass 2: unified fp16 KV [B][NKV][T][D]; RoPE on new K rows.
// ---------------------------------------------------------------------------
__global__ void build_kv_f16(const float* __restrict__ qkv,
                             const float* __restrict__ kcache,
                             const float* __restrict__ vcache,
                             const float* __restrict__ cosb,
                             const float* __restrict__ sinb,
                             __half* __restrict__ kf, __half* __restrict__ vf)
{
    int idx = blockIdx.x * blockDim.x + threadIdx.x;
    const int total = BB * NKV * TT * 64;
    if (idx >= total) return;
    int d = idx & 63;
    int rest = idx >> 6;
    int t = rest % TT;
    int kh = (rest / TT) % NKV;
    int b = rest / (TT * NKV);

    float k1, k2, v1, v2;
    if (t < PP) {
        size_t src = (((size_t)(b * PP + t)) * NKV + kh) * DD;
        k1 = kcache[src + d]; k2 = kcache[src + d + 64];
        v1 = vcache[src + d]; v2 = vcache[src + d + 64];
    } else {
        int s = t - PP;
        const float* base = &qkv[((size_t)(b * SS + s)) * QKVN];
        float x1 = base[(NQ + kh) * DD + d], x2 = base[(NQ + kh) * DD + d + 64];
        float c0 = cosb[s * DD + d],      s0 = sinb[s * DD + d];
        float c1 = cosb[s * DD + d + 64], s1 = sinb[s * DD + d + 64];
        k1 = x1 * c0 - x2 * s0;
        k2 = x2 * c1 + x1 * s1;
        v1 = base[(NQ + NKV + kh) * DD + d];
        v2 = base[(NQ + NKV + kh) * DD + d + 64];
    }
    size_t o = (((size_t)(b * NKV + kh)) * TT + t) * DD + d;
    kf[o]      = __float2half(k1);
    kf[o + 64] = __float2half(k2);
    vf[o]      = __float2half(v1);
    vf[o + 64] = __float2half(v2);
}

// ---------------------------------------------------------------------------
// Flash attention on tensor cores, fp16 single-pass QK and PV.
// Block: 64 queries x (1 q-head) x (1 batch), 4 warps.
// Epilogue still emits bf16 hi/lo for the bf16x3 output GEMM.
// ---------------------------------------------------------------------------
#define FA_SMEM (2 * 64 * 256)   // 32768: K tile + V tile (fp16)

__global__ __launch_bounds__(128) void flash_mma(
    const __half* __restrict__ qf_g,
    const __half* __restrict__ kf_g,
    const __half* __restrict__ vf_g,
    __nv_bfloat16* __restrict__ attnh, __nv_bfloat16* __restrict__ attnl)
{
    extern __shared__ char sm[];
    const uint32_t smb = smem_u32(sm);
    const uint32_t KO = 0, VO = 16384;
    const int tid = threadIdx.x, lane = tid & 31, w = tid >> 5;
    const int qi = blockIdx.x, h = blockIdx.y, b = blockIdx.z;
    const int sq0 = qi * 64;
    const int khd = h >> 2;
    const int g = lane >> 2, t4 = lane & 3;
    const int r0 = w * 16 + g, r1 = r0 + 8;

    // Q fragments straight from gmem (reused across all key tiles)
    uint32_t qf[8][4];
    {
        const __half* qb = qf_g + (((size_t)(b * NQ + h)) * SS + sq0) * DD;
#pragma unroll
        for (int ks = 0; ks < 8; ks++) {
            int c0 = ks * 16 + 2 * t4;
            qf[ks][0] = *(const uint32_t*)(qb + r0 * DD + c0);
            qf[ks][1] = *(const uint32_t*)(qb + r1 * DD + c0);
            qf[ks][2] = *(const uint32_t*)(qb + r0 * DD + c0 + 8);
            qf[ks][3] = *(const uint32_t*)(qb + r1 * DD + c0 + 8);
        }
    }

    float oacc[16][4];
#pragma unroll
    for (int i = 0; i < 16; i++)
#pragma unroll
        for (int j = 0; j < 4; j++) oacc[i][j] = 0.f;
    float m0 = -1e30f, m1 = -1e30f, l0 = 0.f, l1 = 0.f;

    const size_t kvb = ((size_t)(b * NKV + khd)) * TT * DD;
    const int nt = qi + 1 + PP / 64;

    for (int kt = 0; kt < nt; kt++) {
        __syncthreads();
        {
            const __half* srcK = kf_g + kvb + (size_t)kt * 64 * DD;
            const __half* srcV = vf_g + kvb + (size_t)kt * 64 * DD;
#pragma unroll
            for (int i = 0; i < 8; i++) {
                int id = tid + i * 128;
                int r = id >> 4, ch = id & 15;
                uint32_t sw = r * 256 + ((ch ^ (r & 7)) << 4);
                cp16(smb + KO + sw, srcK + r * DD + ch * 8);
                cp16(smb + VO + sw, srcV + r * DD + ch * 8);
            }
            asm volatile("cp.async.commit_group;");
            asm volatile("cp.async.wait_group 0;");
            __syncthreads();
        }

        // S = Q K^T (fp16 single pass)
        float sacc[8][4];
#pragma unroll
        for (int j = 0; j < 8; j++)
#pragma unroll
            for (int e = 0; e < 4; e++) sacc[j][e] = 0.f;
#pragma unroll
        for (int ks = 0; ks < 8; ks++) {
            const int c0 = ks * 2 + (lane >> 4);
            uint32_t kb[4][4];
#pragma unroll
            for (int kg = 0; kg < 4; kg++) {
                int r = kg * 16 + (lane & 15);
                ldsm4(kb[kg], smb + KO + r * 256 + ((c0 ^ (r & 7)) << 4));
            }
#pragma unroll
            for (int kg = 0; kg < 4; kg++)
#pragma unroll
                for (int sel = 0; sel < 2; sel++)
                    mma16816h(sacc[kg * 2 + sel], qf[ks],
                              kb[kg][sel], kb[kg][sel + 2]);
        }

        if (kt == nt - 1) {
#pragma unroll
            for (int j = 0; j < 8; j++) {
                int cb = j * 8 + 2 * t4;
                if (cb     > r0) sacc[j][0] = -1e30f;
                if (cb + 1 > r0) sacc[j][1] = -1e30f;
                if (cb     > r1) sacc[j][2] = -1e30f;
                if (cb + 1 > r1) sacc[j][3] = -1e30f;
            }
        }

        // online softmax
        float mx0 = m0, mx1 = m1;
#pragma unroll
        for (int j = 0; j < 8; j++) {
            mx0 = fmaxf(mx0, fmaxf(sacc[j][0], sacc[j][1]));
            mx1 = fmaxf(mx1, fmaxf(sacc[j][2], sacc[j][3]));
        }
        mx0 = fmaxf(mx0, __shfl_xor_sync(0xffffffff, mx0, 1));
        mx0 = fmaxf(mx0, __shfl_xor_sync(0xffffffff, mx0, 2));
        mx1 = fmaxf(mx1, __shfl_xor_sync(0xffffffff, mx1, 1));
        mx1 = fmaxf(mx1, __shfl_xor_sync(0xffffffff, mx1, 2));
        float rs0 = __expf(m0 - mx0), rs1 = __expf(m1 - mx1);
        m0 = mx0; m1 = mx1;
        l0 *= rs0; l1 *= rs1;

        uint32_t pf[4][4];
#pragma unroll
        for (int j = 0; j < 8; j++) {
            float p0 = __expf(sacc[j][0] - m0);
            float p1 = __expf(sacc[j][1] - m0);
            float p2 = __expf(sacc[j][2] - m1);
            float p3 = __expf(sacc[j][3] - m1);
            l0 += p0 + p1; l1 += p2 + p3;
            int kk = j >> 1, u = (j & 1) * 2;
            __half2 hA = __float22half2_rn(make_float2(p0, p1));
            __half2 hB = __float22half2_rn(make_float2(p2, p3));
            pf[kk][u]     = *(uint32_t*)&hA;
            pf[kk][u + 1] = *(uint32_t*)&hB;
        }

#pragma unroll
        for (int i = 0; i < 16; i++) {
            oacc[i][0] *= rs0; oacc[i][1] *= rs0;
            oacc[i][2] *= rs1; oacc[i][3] *= rs1;
        }

        // O += P V (fp16 single pass)
#pragma unroll
        for (int kk = 0; kk < 4; kk++) {
#pragma unroll
            for (int dp = 0; dp < 4; dp++) {
                const int dg0 = dp * 2, dg1 = dp * 2 + 1;
                int r = kk * 16 + (lane & 15);
                int cA = dg0 * 2 + (lane >> 4);
                int cB = dg1 * 2 + (lane >> 4);
                uint32_t v0[4], v1[4];
                ldsm4t(v0, smb + VO + r * 256 + ((cA ^ (r & 7)) << 4));
                ldsm4t(v1, smb + VO + r * 256 + ((cB ^ (r & 7)) << 4));
                mma16816h(oacc[dg0 * 2],     pf[kk], v0[0], v0[1]);
                mma16816h(oacc[dg0 * 2 + 1], pf[kk], v0[2], v0[3]);
                mma16816h(oacc[dg1 * 2],     pf[kk], v1[0], v1[1]);
                mma16816h(oacc[dg1 * 2 + 1], pf[kk], v1[2], v1[3]);
            }
        }
    }

    l0 += __shfl_xor_sync(0xffffffff, l0, 1);
    l0 += __shfl_xor_sync(0xffffffff, l0, 2);
    l1 += __shfl_xor_sync(0xffffffff, l1, 1);
    l1 += __shfl_xor_sync(0xffffffff, l1, 2);
    float inv0 = 1.f / l0, inv1 = 1.f / l1;

    size_t rowA = ((size_t)(b * SS + sq0 + r0)) * (NQ * DD) + h * DD;
    size_t rowB = ((size_t)(b * SS + sq0 + r1)) * (NQ * DD) + h * DD;
#pragma unroll
    for (int dt = 0; dt < 16; dt++) {
        int c = dt * 8 + 2 * t4;
        float v0 = oacc[dt][0] * inv0, v1 = oacc[dt][1] * inv0;
        float v2 = oacc[dt][2] * inv1, v3 = oacc[dt][3] * inv1;
        __nv_bfloat162 hA = __float22bfloat162_rn(make_float2(v0, v1));
        float2 bA = __bfloat1622float2(hA);
        __nv_bfloat162 lA = __float22bfloat162_rn(make_float2(v0 - bA.x, v1 - bA.y));
        __nv_bfloat162 hB = __float22bfloat162_rn(make_float2(v2, v3));
        float2 bB = __bfloat1622float2(hB);
        __nv_bfloat162 lB = __float22bfloat162_rn(make_float2(v2 - bB.x, v3 - bB.y));
        *(__nv_bfloat162*)&attnh[rowA + c] = hA;
        *(__nv_bfloat162*)&attnl[rowA + c] = lA;
        *(__nv_bfloat162*)&attnh[rowB + c] = hB;
        *(__nv_bfloat162*)&attnl[rowB + c] = lB;
    }
}

// ---------------------------------------------------------------------------
extern "C" void kernel_launch(void* const* d_in, const int* in_sizes, int n_in,
                              void* d_out, int out_size)
{
    const float* hidden = (const float*)d_in[0];
    const float* w_qkv  = (const float*)d_in[1];
    const float* w_o    = (const float*)d_in[2];
    const float* cosb   = (const float*)d_in[3];
    const float* sinb   = (const float*)d_in[4];
    const float* kc     = (const float*)d_in[5];
    const float* vc     = (const float*)d_in[6];
    float* out = (float*)d_out;

    float *qkv;
    __nv_bfloat16 *hidh, *hidl, *wqh, *wql, *woh, *wol, *ath, *atl;
    __half *qf, *kf, *vf;
    cudaGetSymbolAddress((void**)&qkv, g_qkv);
    cudaGetSymbolAddress((void**)&hidh, g_hid_h);
    cudaGetSymbolAddress((void**)&hidl, g_hid_l);
    cudaGetSymbolAddress((void**)&wqh, g_wqkv_h);
    cudaGetSymbolAddress((void**)&wql, g_wqkv_l);
    cudaGetSymbolAddress((void**)&woh, g_wo_h);
    cudaGetSymbolAddress((void**)&wol, g_wo_l);
    cudaGetSymbolAddress((void**)&ath, g_attn_h);
    cudaGetSymbolAddress((void**)&atl, g_attn_l);
    cudaGetSymbolAddress((void**)&qf, g_q_f);
    cudaGetSymbolAddress((void**)&kf, g_k_f);
    cudaGetSymbolAddress((void**)&vf, g_v_f);

    cudaFuncSetAttribute(gemm_bf16x3,
                         cudaFuncAttributeMaxDynamicSharedMemorySize, GEMM_SMEM);
    cudaFuncSetAttribute(flash_mma,
                         cudaFuncAttributeMaxDynamicSharedMemorySize, FA_SMEM);

    const int M = BB * SS;  // 2048

    // 0) hi/lo splits (+ weight transposes to [N,K])
    {
        int n = M * HH;
        split_kernel<<<(n + 255) / 256, 256>>>(hidden, hidh, hidl, n);
        split_t_kernel<<<dim3(QKVN / 32, HH / 32), dim3(32, 8)>>>(
            w_qkv, wqh, wql, HH, QKVN);
        split_t_kernel<<<dim3(HH / 32, HH / 32), dim3(32, 8)>>>(
            w_o, woh, wol, HH, HH);
    }
    // 1) QKV projection (bf16x3)
    gemm_bf16x3<<<dim3(QKVN / 256, M / 128), 256, GEMM_SMEM>>>(
        hidh, hidl, wqh, wql, qkv, M, QKVN, HH);
    // 2) pre-passes (fp16 q/k/v)
    {
        int nq = BB * SS * NQ * 64;
        rope_q_f16<<<(nq + 255) / 256, 256>>>(qkv, cosb, sinb, qf);
        int nkv = BB * NKV * TT * 64;
        build_kv_f16<<<(nkv + 255) / 256, 256>>>(qkv, kc, vc, cosb, sinb, kf, vf);
    }
    // 3) Flash attention (fp16 single pass)
    flash_mma<<<dim3(SS / 64, NQ, BB), 128, FA_SMEM>>>(qf, kf, vf, ath, atl);
    // 4) Output projection (bf16x3)
    gemm_bf16x3<<<dim3(HH / 256, M / 128), 256, GEMM_SMEM>>>(
        ath, atl, woh, wol, out, M, HH, HH);
}

// round 9
// speedup vs baseline: 1.6773x; 1.3814x over previous
#include <cuda_runtime.h>
#include <cuda_bf16.h>
#include <cuda_fp16.h>
#include <math.h>
#include <stdint.h>

// Problem constants
#define BB   2
#define SS   1024
#define PP   1024
#define TT   (PP + SS)
#define HH   4096
#define NQ   32
#define NKV  8
#define DD   128
#define QKVN ((NQ + 2 * NKV) * DD)   // 6144
#define SCALE 0.08838834764831845f   // 1/sqrt(128)

// ---------------------------------------------------------------------------
// Scratch (device globals: no allocation allowed)
// ---------------------------------------------------------------------------
__device__ float g_qkv[BB * SS * QKVN];
__device__ __half g_hid_h[BB * SS * HH];             // activation hi
__device__ __half g_hid_l[BB * SS * HH];             // activation lo
__device__ __half g_wqkv[(size_t)QKVN * HH];         // weights fp16, transposed [N,K]
__device__ __half g_wo[(size_t)HH * HH];             // weights fp16, transposed [N,K]
__device__ __half g_attn_h[BB * SS * NQ * DD];       // attn out hi
__device__ __half g_attn_l[BB * SS * NQ * DD];       // attn out lo
// fp16 Q [B][NQ][S][D], unified fp16 KV [B][NKV][T][D]
__device__ __half g_q_f[(size_t)BB * NQ * SS * DD];
__device__ __half g_k_f[(size_t)BB * NKV * TT * DD];
__device__ __half g_v_f[(size_t)BB * NKV * TT * DD];

// ---------------------------------------------------------------------------
// Low-level helpers (plain sm_80+ ISA)
// ---------------------------------------------------------------------------
__device__ __forceinline__ uint32_t smem_u32(const void* p) {
    uint32_t a;
    asm("{ .reg .u64 t; cvta.to.shared.u64 t, %1; cvt.u32.u64 %0, t; }"
        : "=r"(a) : "l"(p));
    return a;
}
__device__ __forceinline__ void cp16(uint32_t dst, const void* src) {
    asm volatile("cp.async.cg.shared.global [%0], [%1], 16;"
                 :: "r"(dst), "l"(src));
}
__device__ __forceinline__ void ldsm4(uint32_t* r, uint32_t a) {
    asm volatile("ldmatrix.sync.aligned.m8n8.x4.shared.b16 {%0,%1,%2,%3}, [%4];"
                 : "=r"(r[0]), "=r"(r[1]), "=r"(r[2]), "=r"(r[3]) : "r"(a));
}
__device__ __forceinline__ void ldsm4t(uint32_t* r, uint32_t a) {
    asm volatile("ldmatrix.sync.aligned.m8n8.x4.trans.shared.b16 {%0,%1,%2,%3}, [%4];"
                 : "=r"(r[0]), "=r"(r[1]), "=r"(r[2]), "=r"(r[3]) : "r"(a));
}
// fp16 mma
__device__ __forceinline__ void mma16816h(float* c, const uint32_t* a,
                                          const uint32_t b0, const uint32_t b1) {
    asm volatile(
        "mma.sync.aligned.m16n8k16.row.col.f32.f16.f16.f32 "
        "{%0,%1,%2,%3}, {%4,%5,%6,%7}, {%8,%9}, {%0,%1,%2,%3};"
        : "+f"(c[0]), "+f"(c[1]), "+f"(c[2]), "+f"(c[3])
        : "r"(a[0]), "r"(a[1]), "r"(a[2]), "r"(a[3]), "r"(b0), "r"(b1));
}

// ---------------------------------------------------------------------------
// fp32 -> fp16 hi/lo split (same layout) — activations
// ---------------------------------------------------------------------------
__global__ void split_f16(const float* __restrict__ x,
                          __half* __restrict__ xh,
                          __half* __restrict__ xl, int n)
{
    int i = blockIdx.x * blockDim.x + threadIdx.x;
    if (i >= n) return;
    float v = x[i];
    __half hb = __float2half(v);
    xh[i] = hb;
    xl[i] = __float2half(v - __half2float(hb));
}

// fp32 [R,C] -> single fp16 transposed [C,R] — weights
__global__ void trans_f16(const float* __restrict__ x,
                          __half* __restrict__ xo, int R, int C)
{
    __shared__ float t[32][33];
    int r0 = blockIdx.y * 32, c0 = blockIdx.x * 32;
    int tx = threadIdx.x, ty = threadIdx.y;
#pragma unroll
    for (int j = 0; j < 4; j++)
        t[ty + 8 * j][tx] = x[(size_t)(r0 + ty + 8 * j) * C + c0 + tx];
    __syncthreads();
#pragma unroll
    for (int j = 0; j < 4; j++)
        xo[(size_t)(c0 + ty + 8 * j) * R + r0 + tx] = __float2half(t[tx][ty + 8 * j]);
}

// ---------------------------------------------------------------------------
// fp16x2 GEMM via mma.sync: C[M,N] fp32 = (Ah+Al)[M,K] @ B[N,K]^T
// 128x256x64 block tile, 8 warps (warp tile 64x64), cp.async double buffer,
// 2 MMA passes per k-step (hh, lh). Weight rounding error ~2^-12 relative.
// ---------------------------------------------------------------------------
#define AH_OFF 0
#define AL_OFF 16384
#define BH_OFF 32768
#define STAGE_B  65536
#define GEMM_SMEM (2 * STAGE_B)   // 131072

#define LOAD_STAGE(c, s) do {                                              \
    int _k0 = (c) * 64;                                                    \
    uint32_t _stb = smb + (s) * STAGE_B;                                   \
    _Pragma("unroll")                                                      \
    for (int _i = 0; _i < 4; _i++) {                                       \
        int _id = tid + _i * 256;                                          \
        int _row = _id >> 3, _ch = _id & 7;                                \
        uint32_t _sw = (_row << 7) + ((_ch ^ (_row & 7)) << 4);            \
        const size_t _go = (size_t)_row * K + _k0 + _ch * 8;               \
        cp16(_stb + AH_OFF + _sw, srcAh + _go);                            \
        cp16(_stb + AL_OFF + _sw, srcAl + _go);                            \
    }                                                                      \
    _Pragma("unroll")                                                      \
    for (int _i = 0; _i < 8; _i++) {                                       \
        int _id = tid + _i * 256;                                          \
        int _row = _id >> 3, _ch = _id & 7;                                \
        uint32_t _sw = (_row << 7) + ((_ch ^ (_row & 7)) << 4);            \
        cp16(_stb + BH_OFF + _sw, srcB + (size_t)_row * K + _k0 + _ch * 8); \
    }                                                                      \
    asm volatile("cp.async.commit_group;");                                \
} while (0)

__global__ __launch_bounds__(256, 1) void gemm_f16x2(
    const __half* __restrict__ Ah, const __half* __restrict__ Al,
    const __half* __restrict__ B,
    float* __restrict__ C, int M, int N, int K)
{
    extern __shared__ char sm[];
    const uint32_t smb = smem_u32(sm);
    const int tid = threadIdx.x;
    const int wid = tid >> 5, lane = tid & 31;
    const int bm = blockIdx.y * 128, bn = blockIdx.x * 256;
    const int wm = (wid & 1) * 64, wn = (wid >> 1) * 64;

    const __half* srcAh = Ah + (size_t)bm * K;
    const __half* srcAl = Al + (size_t)bm * K;
    const __half* srcB  = B  + (size_t)bn * K;

    float acc[4][8][4];
#pragma unroll
    for (int i = 0; i < 4; i++)
#pragma unroll
        for (int j = 0; j < 8; j++)
#pragma unroll
            for (int e = 0; e < 4; e++) acc[i][j][e] = 0.f;

    const int NC = K / 64;
    LOAD_STAGE(0, 0);

    for (int c = 0; c < NC; c++) {
        const int s = c & 1;
        if (c + 1 < NC) {
            LOAD_STAGE(c + 1, s ^ 1);
            asm volatile("cp.async.wait_group 1;");
        } else {
            asm volatile("cp.async.wait_group 0;");
        }
        __syncthreads();

        const uint32_t base = smb + s * STAGE_B;
#pragma unroll
        for (int ks = 0; ks < 4; ks++) {
            const int c0 = ks * 2 + (lane >> 4);
            uint32_t ah[4][4], al[4][4], bh[4][4];
#pragma unroll
            for (int mi = 0; mi < 4; mi++) {
                int row = wm + mi * 16 + (lane & 15);
                uint32_t off = (row << 7) + ((c0 ^ (row & 7)) << 4);
                ldsm4(ah[mi], base + AH_OFF + off);
                ldsm4(al[mi], base + AL_OFF + off);
            }
#pragma unroll
            for (int ni = 0; ni < 4; ni++) {
                int row = wn + ni * 16 + (lane & 15);
                uint32_t off = (row << 7) + ((c0 ^ (row & 7)) << 4);
                ldsm4(bh[ni], base + BH_OFF + off);
            }
            // pass 0: Ah * B  (32 independent accumulators)
#pragma unroll
            for (int mi = 0; mi < 4; mi++)
#pragma unroll
                for (int ni = 0; ni < 4; ni++)
#pragma unroll
                    for (int sel = 0; sel < 2; sel++)
                        mma16816h(acc[mi][ni * 2 + sel], ah[mi],
                                  bh[ni][sel], bh[ni][sel + 2]);
            // pass 1: Al * B
#pragma unroll
            for (int mi = 0; mi < 4; mi++)
#pragma unroll
                for (int ni = 0; ni < 4; ni++)
#pragma unroll
                    for (int sel = 0; sel < 2; sel++)
                        mma16816h(acc[mi][ni * 2 + sel], al[mi],
                                  bh[ni][sel], bh[ni][sel + 2]);
        }
        __syncthreads();
    }

    const int g = lane >> 2, t = lane & 3;
#pragma unroll
    for (int mi = 0; mi < 4; mi++) {
#pragma unroll
        for (int nj = 0; nj < 8; nj++) {
            const float* a = acc[mi][nj];
            int row = bm + wm + mi * 16 + g;
            int col = bn + wn + nj * 8 + t * 2;
            *(float2*)&C[(size_t)row * N + col] = make_float2(a[0], a[1]);
            *(float2*)&C[(size_t)(row + 8) * N + col] = make_float2(a[2], a[3]);
        }
    }
}

// ---------------------------------------------------------------------------
// Pre-pass 1: RoPE + scale, fp16 Q -> [B][NQ][S][D]
// ---------------------------------------------------------------------------
__global__ void rope_q_f16(const float* __restrict__ qkv,
                           const float* __restrict__ cosb,
                           const float* __restrict__ sinb,
                           __half* __restrict__ qf)
{
    int idx = blockIdx.x * blockDim.x + threadIdx.x;
    const int total = BB * SS * NQ * 64;
    if (idx >= total) return;
    int d = idx & 63;
    int rest = idx >> 6;
    int h = rest % NQ;
    int s = (rest / NQ) % SS;
    int b = rest / (NQ * SS);
    const float* base = &qkv[((size_t)(b * SS + s)) * QKVN + h * DD];
    float x1 = base[d], x2 = base[d + 64];
    float c0 = cosb[s * DD + d],      s0 = sinb[s * DD + d];
    float c1 = cosb[s * DD + d + 64], s1 = sinb[s * DD + d + 64];
    size_t o = (((size_t)(b * NQ + h)) * SS + s) * DD + d;
    qf[o]      = __float2half((x1 * c0 - x2 * s0) * SCALE);
    qf[o + 64] = __float2half((x2 * c1 + x1 * s1) * SCALE);
}

// ---------------------------------------------------------------------------
// Pre-pass 2: unified fp16 KV [B][NKV][T][D]; RoPE on new K rows.
// ---------------------------------------------------------------------------
__global__ void build_kv_f16(const float* __restrict__ qkv,
                             const float* __restrict__ kcache,
                             const float* __restrict__ vcache,
                             const float* __restrict__ cosb,
                             const float* __restrict__ sinb,
                             __half* __restrict__ kf, __half* __restrict__ vf)
{
    int idx = blockIdx.x * blockDim.x + threadIdx.x;
    const int total = BB * NKV * TT * 64;
    if (idx >= total) return;
    int d = idx & 63;
    int rest = idx >> 6;
    int t = rest % TT;
    int kh = (rest / TT) % NKV;
    int b = rest / (TT * NKV);

    float k1, k2, v1, v2;
    if (t < PP) {
        size_t src = (((size_t)(b * PP + t)) * NKV + kh) * DD;
        k1 = kcache[src + d]; k2 = kcache[src + d + 64];
        v1 = vcache[src + d]; v2 = vcache[src + d + 64];
    } else {
        int s = t - PP;
        const float* base = &qkv[((size_t)(b * SS + s)) * QKVN];
        float x1 = base[(NQ + kh) * DD + d], x2 = base[(NQ + kh) * DD + d + 64];
        float c0 = cosb[s * DD + d],      s0 = sinb[s * DD + d];
        float c1 = cosb[s * DD + d + 64], s1 = sinb[s * DD + d + 64];
        k1 = x1 * c0 - x2 * s0;
        k2 = x2 * c1 + x1 * s1;
        v1 = base[(NQ + NKV + kh) * DD + d];
        v2 = base[(NQ + NKV + kh) * DD + d + 64];
    }
    size_t o = (((size_t)(b * NKV + kh)) * TT + t) * DD + d;
    kf[o]      = __float2half(k1);
    kf[o + 64] = __float2half(k2);
    vf[o]      = __float2half(v1);
    vf[o + 64] = __float2half(v2);
}

// ---------------------------------------------------------------------------
// Flash attention on tensor cores, fp16 single-pass QK and PV.
// Epilogue emits fp16 hi/lo for the fp16x2 output GEMM.
// ---------------------------------------------------------------------------
#define FA_SMEM (2 * 64 * 256)   // 32768: K tile + V tile (fp16)

__global__ __launch_bounds__(128) void flash_mma(
    const __half* __restrict__ qf_g,
    const __half* __restrict__ kf_g,
    const __half* __restrict__ vf_g,
    __half* __restrict__ attnh, __half* __restrict__ attnl)
{
    extern __shared__ char sm[];
    const uint32_t smb = smem_u32(sm);
    const uint32_t KO = 0, VO = 16384;
    const int tid = threadIdx.x, lane = tid & 31, w = tid >> 5;
    const int qi = blockIdx.x, h = blockIdx.y, b = blockIdx.z;
    const int sq0 = qi * 64;
    const int khd = h >> 2;
    const int g = lane >> 2, t4 = lane & 3;
    const int r0 = w * 16 + g, r1 = r0 + 8;

    uint32_t qf[8][4];
    {
        const __half* qb = qf_g + (((size_t)(b * NQ + h)) * SS + sq0) * DD;
#pragma unroll
        for (int ks = 0; ks < 8; ks++) {
            int c0 = ks * 16 + 2 * t4;
            qf[ks][0] = *(const uint32_t*)(qb + r0 * DD + c0);
            qf[ks][1] = *(const uint32_t*)(qb + r1 * DD + c0);
            qf[ks][2] = *(const uint32_t*)(qb + r0 * DD + c0 + 8);
            qf[ks][3] = *(const uint32_t*)(qb + r1 * DD + c0 + 8);
        }
    }

    float oacc[16][4];
#pragma unroll
    for (int i = 0; i < 16; i++)
#pragma unroll
        for (int j = 0; j < 4; j++) oacc[i][j] = 0.f;
    float m0 = -1e30f, m1 = -1e30f, l0 = 0.f, l1 = 0.f;

    const size_t kvb = ((size_t)(b * NKV + khd)) * TT * DD;
    const int nt = qi + 1 + PP / 64;

    for (int kt = 0; kt < nt; kt++) {
        __syncthreads();
        {
            const __half* srcK = kf_g + kvb + (size_t)kt * 64 * DD;
            const __half* srcV = vf_g + kvb + (size_t)kt * 64 * DD;
#pragma unroll
            for (int i = 0; i < 8; i++) {
                int id = tid + i * 128;
                int r = id >> 4, ch = id & 15;
                uint32_t sw = r * 256 + ((ch ^ (r & 7)) << 4);
                cp16(smb + KO + sw, srcK + r * DD + ch * 8);
                cp16(smb + VO + sw, srcV + r * DD + ch * 8);
            }
            asm volatile("cp.async.commit_group;");
            asm volatile("cp.async.wait_group 0;");
            __syncthreads();
        }

        float sacc[8][4];
#pragma unroll
        for (int j = 0; j < 8; j++)
#pragma unroll
            for (int e = 0; e < 4; e++) sacc[j][e] = 0.f;
#pragma unroll
        for (int ks = 0; ks < 8; ks++) {
            const int c0 = ks * 2 + (lane >> 4);
            uint32_t kb[4][4];
#pragma unroll
            for (int kg = 0; kg < 4; kg++) {
                int r = kg * 16 + (lane & 15);
                ldsm4(kb[kg], smb + KO + r * 256 + ((c0 ^ (r & 7)) << 4));
            }
#pragma unroll
            for (int kg = 0; kg < 4; kg++)
#pragma unroll
                for (int sel = 0; sel < 2; sel++)
                    mma16816h(sacc[kg * 2 + sel], qf[ks],
                              kb[kg][sel], kb[kg][sel + 2]);
        }

        if (kt == nt - 1) {
#pragma unroll
            for (int j = 0; j < 8; j++) {
                int cb = j * 8 + 2 * t4;
                if (cb     > r0) sacc[j][0] = -1e30f;
                if (cb + 1 > r0) sacc[j][1] = -1e30f;
                if (cb     > r1) sacc[j][2] = -1e30f;
                if (cb + 1 > r1) sacc[j][3] = -1e30f;
            }
        }

        float mx0 = m0, mx1 = m1;
#pragma unroll
        for (int j = 0; j < 8; j++) {
            mx0 = fmaxf(mx0, fmaxf(sacc[j][0], sacc[j][1]));
            mx1 = fmaxf(mx1, fmaxf(sacc[j][2], sacc[j][3]));
        }
        mx0 = fmaxf(mx0, __shfl_xor_sync(0xffffffff, mx0, 1));
        mx0 = fmaxf(mx0, __shfl_xor_sync(0xffffffff, mx0, 2));
        mx1 = fmaxf(mx1, __shfl_xor_sync(0xffffffff, mx1, 1));
        mx1 = fmaxf(mx1, __shfl_xor_sync(0xffffffff, mx1, 2));
        float rs0 = __expf(m0 - mx0), rs1 = __expf(m1 - mx1);
        m0 = mx0; m1 = mx1;
        l0 *= rs0; l1 *= rs1;

        uint32_t pf[4][4];
#pragma unroll
        for (int j = 0; j < 8; j++) {
            float p0 = __expf(sacc[j][0] - m0);
            float p1 = __expf(sacc[j][1] - m0);
            float p2 = __expf(sacc[j][2] - m1);
            float p3 = __expf(sacc[j][3] - m1);
            l0 += p0 + p1; l1 += p2 + p3;
            int kk = j >> 1, u = (j & 1) * 2;
            __half2 hA = __float22half2_rn(make_float2(p0, p1));
            __half2 hB = __float22half2_rn(make_float2(p2, p3));
            pf[kk][u]     = *(uint32_t*)&hA;
            pf[kk][u + 1] = *(uint32_t*)&hB;
        }

#pragma unroll
        for (int i = 0; i < 16; i++) {
            oacc[i][0] *= rs0; oacc[i][1] *= rs0;
            oacc[i][2] *= rs1; oacc[i][3] *= rs1;
        }

#pragma unroll
        for (int kk = 0; kk < 4; kk++) {
#pragma unroll
            for (int dp = 0; dp < 4; dp++) {
                const int dg0 = dp * 2, dg1 = dp * 2 + 1;
                int r = kk * 16 + (lane & 15);
                int cA = dg0 * 2 + (lane >> 4);
                int cB = dg1 * 2 + (lane >> 4);
                uint32_t v0[4], v1[4];
                ldsm4t(v0, smb + VO + r * 256 + ((cA ^ (r & 7)) << 4));
                ldsm4t(v1, smb + VO + r * 256 + ((cB ^ (r & 7)) << 4));
                mma16816h(oacc[dg0 * 2],     pf[kk], v0[0], v0[1]);
                mma16816h(oacc[dg0 * 2 + 1], pf[kk], v0[2], v0[3]);
                mma16816h(oacc[dg1 * 2],     pf[kk], v1[0], v1[1]);
                mma16816h(oacc[dg1 * 2 + 1], pf[kk], v1[2], v1[3]);
            }
        }
    }

    l0 += __shfl_xor_sync(0xffffffff, l0, 1);
    l0 += __shfl_xor_sync(0xffffffff, l0, 2);
    l1 += __shfl_xor_sync(0xffffffff, l1, 1);
    l1 += __shfl_xor_sync(0xffffffff, l1, 2);
    float inv0 = 1.f / l0, inv1 = 1.f / l1;

    size_t rowA = ((size_t)(b * SS + sq0 + r0)) * (NQ * DD) + h * DD;
    size_t rowB = ((size_t)(b * SS + sq0 + r1)) * (NQ * DD) + h * DD;
#pragma unroll
    for (int dt = 0; dt < 16; dt++) {
        int c = dt * 8 + 2 * t4;
        float v0 = oacc[dt][0] * inv0, v1 = oacc[dt][1] * inv0;
        float v2 = oacc[dt][2] * inv1, v3 = oacc[dt][3] * inv1;
        __half2 hA = __float22half2_rn(make_float2(v0, v1));
        float2 fA = __half22float2(hA);
        __half2 lA = __float22half2_rn(make_float2(v0 - fA.x, v1 - fA.y));
        __half2 hB = __float22half2_rn(make_float2(v2, v3));
        float2 fB = __half22float2(hB);
        __half2 lB = __float22half2_rn(make_float2(v2 - fB.x, v3 - fB.y));
        *(__half2*)&attnh[rowA + c] = hA;
        *(__half2*)&attnl[rowA + c] = lA;
        *(__half2*)&attnh[rowB + c] = hB;
        *(__half2*)&attnl[rowB + c] = lB;
    }
}

// ---------------------------------------------------------------------------
extern "C" void kernel_launch(void* const* d_in, const int* in_sizes, int n_in,
                              void* d_out, int out_size)
{
    const float* hidden = (const float*)d_in[0];
    const float* w_qkv  = (const float*)d_in[1];
    const float* w_o    = (const float*)d_in[2];
    const float* cosb   = (const float*)d_in[3];
    const float* sinb   = (const float*)d_in[4];
    const float* kc     = (const float*)d_in[5];
    const float* vc     = (const float*)d_in[6];
    float* out = (float*)d_out;

    float *qkv;
    __half *hidh, *hidl, *wq, *wo, *ath, *atl, *qf, *kf, *vf;
    cudaGetSymbolAddress((void**)&qkv, g_qkv);
    cudaGetSymbolAddress((void**)&hidh, g_hid_h);
    cudaGetSymbolAddress((void**)&hidl, g_hid_l);
    cudaGetSymbolAddress((void**)&wq, g_wqkv);
    cudaGetSymbolAddress((void**)&wo, g_wo);
    cudaGetSymbolAddress((void**)&ath, g_attn_h);
    cudaGetSymbolAddress((void**)&atl, g_attn_l);
    cudaGetSymbolAddress((void**)&qf, g_q_f);
    cudaGetSymbolAddress((void**)&kf, g_k_f);
    cudaGetSymbolAddress((void**)&vf, g_v_f);

    cudaFuncSetAttribute(gemm_f16x2,
                         cudaFuncAttributeMaxDynamicSharedMemorySize, GEMM_SMEM);
    cudaFuncSetAttribute(flash_mma,
                         cudaFuncAttributeMaxDynamicSharedMemorySize, FA_SMEM);

    const int M = BB * SS;  // 2048

    // 0) activation split + weight transposes (single fp16)
    {
        int n = M * HH;
        split_f16<<<(n + 255) / 256, 256>>>(hidden, hidh, hidl, n);
        trans_f16<<<dim3(QKVN / 32, HH / 32), dim3(32, 8)>>>(w_qkv, wq, HH, QKVN);
        trans_f16<<<dim3(HH / 32, HH / 32), dim3(32, 8)>>>(w_o, wo, HH, HH);
    }
    // 1) QKV projection (fp16x2, 2-pass)
    gemm_f16x2<<<dim3(QKVN / 256, M / 128), 256, GEMM_SMEM>>>(
        hidh, hidl, wq, qkv, M, QKVN, HH);
    // 2) pre-passes (fp16 q/k/v)
    {
        int nq = BB * SS * NQ * 64;
        rope_q_f16<<<(nq + 255) / 256, 256>>>(qkv, cosb, sinb, qf);
        int nkv = BB * NKV * TT * 64;
        build_kv_f16<<<(nkv + 255) / 256, 256>>>(qkv, kc, vc, cosb, sinb, kf, vf);
    }
    // 3) Flash attention (fp16 single pass)
    flash_mma<<<dim3(SS / 64, NQ, BB), 128, FA_SMEM>>>(qf, kf, vf, ath, atl);
    // 4) Output projection (fp16x2, 2-pass)
    gemm_f16x2<<<dim3(HH / 256, M / 128), 256, GEMM_SMEM>>>(
        ath, atl, wo, out, M, HH, HH);
}

// round 10
// speedup vs baseline: 2.1400x; 1.2759x over previous
#include <cuda_runtime.h>
#include <cuda_bf16.h>
#include <cuda_fp16.h>
#include <math.h>
#include <stdint.h>

// Problem constants
#define BB   2
#define SS   1024
#define PP   1024
#define TT   (PP + SS)
#define HH   4096
#define NQ   32
#define NKV  8
#define DD   128
#define QKVN ((NQ + 2 * NKV) * DD)   // 6144
#define SCALE 0.08838834764831845f   // 1/sqrt(128)

// ---------------------------------------------------------------------------
// Scratch (device globals: no allocation allowed)
// ---------------------------------------------------------------------------
__device__ float g_qkv[BB * SS * QKVN];
__device__ __half g_hid[BB * SS * HH];               // activations fp16 (GEMM1)
__device__ __half g_wqkv[(size_t)QKVN * HH];         // weights fp16, transposed [N,K]
__device__ __half g_wo[(size_t)HH * HH];             // weights fp16, transposed [N,K]
__device__ __half g_attn_h[BB * SS * NQ * DD];       // attn out hi
__device__ __half g_attn_l[BB * SS * NQ * DD];       // attn out lo
// fp16 Q [B][NQ][S][D], unified fp16 KV [B][NKV][T][D]
__device__ __half g_q_f[(size_t)BB * NQ * SS * DD];
__device__ __half g_k_f[(size_t)BB * NKV * TT * DD];
__device__ __half g_v_f[(size_t)BB * NKV * TT * DD];

// ---------------------------------------------------------------------------
// Low-level helpers (plain sm_80+ ISA)
// ---------------------------------------------------------------------------
__device__ __forceinline__ uint32_t smem_u32(const void* p) {
    uint32_t a;
    asm("{ .reg .u64 t; cvta.to.shared.u64 t, %1; cvt.u32.u64 %0, t; }"
        : "=r"(a) : "l"(p));
    return a;
}
__device__ __forceinline__ void cp16(uint32_t dst, const void* src) {
    asm volatile("cp.async.cg.shared.global [%0], [%1], 16;"
                 :: "r"(dst), "l"(src));
}
__device__ __forceinline__ void ldsm4(uint32_t* r, uint32_t a) {
    asm volatile("ldmatrix.sync.aligned.m8n8.x4.shared.b16 {%0,%1,%2,%3}, [%4];"
                 : "=r"(r[0]), "=r"(r[1]), "=r"(r[2]), "=r"(r[3]) : "r"(a));
}
__device__ __forceinline__ void ldsm4t(uint32_t* r, uint32_t a) {
    asm volatile("ldmatrix.sync.aligned.m8n8.x4.trans.shared.b16 {%0,%1,%2,%3}, [%4];"
                 : "=r"(r[0]), "=r"(r[1]), "=r"(r[2]), "=r"(r[3]) : "r"(a));
}
// fp16 mma
__device__ __forceinline__ void mma16816h(float* c, const uint32_t* a,
                                          const uint32_t b0, const uint32_t b1) {
    asm volatile(
        "mma.sync.aligned.m16n8k16.row.col.f32.f16.f16.f32 "
        "{%0,%1,%2,%3}, {%4,%5,%6,%7}, {%8,%9}, {%0,%1,%2,%3};"
        : "+f"(c[0]), "+f"(c[1]), "+f"(c[2]), "+f"(c[3])
        : "r"(a[0]), "r"(a[1]), "r"(a[2]), "r"(a[3]), "r"(b0), "r"(b1));
}

// ---------------------------------------------------------------------------
// fp32 -> fp16 convert (same layout) — GEMM1 activations
// ---------------------------------------------------------------------------
__global__ void conv_f16(const float* __restrict__ x,
                         __half* __restrict__ xo, int n)
{
    int i = blockIdx.x * blockDim.x + threadIdx.x;
    if (i >= n) return;
    xo[i] = __float2half(x[i]);
}

// fp32 [R,C] -> single fp16 transposed [C,R] — weights
__global__ void trans_f16(const float* __restrict__ x,
                          __half* __restrict__ xo, int R, int C)
{
    __shared__ float t[32][33];
    int r0 = blockIdx.y * 32, c0 = blockIdx.x * 32;
    int tx = threadIdx.x, ty = threadIdx.y;
#pragma unroll
    for (int j = 0; j < 4; j++)
        t[ty + 8 * j][tx] = x[(size_t)(r0 + ty + 8 * j) * C + c0 + tx];
    __syncthreads();
#pragma unroll
    for (int j = 0; j < 4; j++)
        xo[(size_t)(c0 + ty + 8 * j) * R + r0 + tx] = __float2half(t[tx][ty + 8 * j]);
}

// ---------------------------------------------------------------------------
// fp16 single-pass GEMM: C[M,N] fp32 = A[M,K] @ B[N,K]^T    (QKV projection)
// 128x256x64 block tile, 8 warps (warp tile 64x64), cp.async double buffer.
// ---------------------------------------------------------------------------
#define X1_A_OFF 0
#define X1_B_OFF 16384
#define X1_STAGE 49152
#define GEMM1_SMEM (2 * X1_STAGE)   // 98304

#define LOAD_STAGE1(c, s) do {                                             \
    int _k0 = (c) * 64;                                                    \
    uint32_t _stb = smb + (s) * X1_STAGE;                                  \
    _Pragma("unroll")                                                      \
    for (int _i = 0; _i < 4; _i++) {                                       \
        int _id = tid + _i * 256;                                          \
        int _row = _id >> 3, _ch = _id & 7;                                \
        uint32_t _sw = (_row << 7) + ((_ch ^ (_row & 7)) << 4);            \
        cp16(_stb + X1_A_OFF + _sw, srcA + (size_t)_row * K + _k0 + _ch * 8); \
    }                                                                      \
    _Pragma("unroll")                                                      \
    for (int _i = 0; _i < 8; _i++) {                                       \
        int _id = tid + _i * 256;                                          \
        int _row = _id >> 3, _ch = _id & 7;                                \
        uint32_t _sw = (_row << 7) + ((_ch ^ (_row & 7)) << 4);            \
        cp16(_stb + X1_B_OFF + _sw, srcB + (size_t)_row * K + _k0 + _ch * 8); \
    }                                                                      \
    asm volatile("cp.async.commit_group;");                                \
} while (0)

__global__ __launch_bounds__(256, 1) void gemm_f16x1(
    const __half* __restrict__ A, const __half* __restrict__ B,
    float* __restrict__ C, int M, int N, int K)
{
    extern __shared__ char sm[];
    const uint32_t smb = smem_u32(sm);
    const int tid = threadIdx.x;
    const int wid = tid >> 5, lane = tid & 31;
    const int bm = blockIdx.y * 128, bn = blockIdx.x * 256;
    const int wm = (wid & 1) * 64, wn = (wid >> 1) * 64;

    const __half* srcA = A + (size_t)bm * K;
    const __half* srcB = B + (size_t)bn * K;

    float acc[4][8][4];
#pragma unroll
    for (int i = 0; i < 4; i++)
#pragma unroll
        for (int j = 0; j < 8; j++)
#pragma unroll
            for (int e = 0; e < 4; e++) acc[i][j][e] = 0.f;

    const int NC = K / 64;
    LOAD_STAGE1(0, 0);

    for (int c = 0; c < NC; c++) {
        const int s = c & 1;
        if (c + 1 < NC) {
            LOAD_STAGE1(c + 1, s ^ 1);
            asm volatile("cp.async.wait_group 1;");
        } else {
            asm volatile("cp.async.wait_group 0;");
        }
        __syncthreads();

        const uint32_t base = smb + s * X1_STAGE;
#pragma unroll
        for (int ks = 0; ks < 4; ks++) {
            const int c0 = ks * 2 + (lane >> 4);
            uint32_t ah[4][4], bh[4][4];
#pragma unroll
            for (int mi = 0; mi < 4; mi++) {
                int row = wm + mi * 16 + (lane & 15);
                uint32_t off = (row << 7) + ((c0 ^ (row & 7)) << 4);
                ldsm4(ah[mi], base + X1_A_OFF + off);
            }
#pragma unroll
            for (int ni = 0; ni < 4; ni++) {
                int row = wn + ni * 16 + (lane & 15);
                uint32_t off = (row << 7) + ((c0 ^ (row & 7)) << 4);
                ldsm4(bh[ni], base + X1_B_OFF + off);
            }
#pragma unroll
            for (int mi = 0; mi < 4; mi++)
#pragma unroll
                for (int ni = 0; ni < 4; ni++)
#pragma unroll
                    for (int sel = 0; sel < 2; sel++)
                        mma16816h(acc[mi][ni * 2 + sel], ah[mi],
                                  bh[ni][sel], bh[ni][sel + 2]);
        }
        __syncthreads();
    }

    const int g = lane >> 2, t = lane & 3;
#pragma unroll
    for (int mi = 0; mi < 4; mi++) {
#pragma unroll
        for (int nj = 0; nj < 8; nj++) {
            const float* a = acc[mi][nj];
            int row = bm + wm + mi * 16 + g;
            int col = bn + wn + nj * 8 + t * 2;
            *(float2*)&C[(size_t)row * N + col] = make_float2(a[0], a[1]);
            *(float2*)&C[(size_t)(row + 8) * N + col] = make_float2(a[2], a[3]);
        }
    }
}

// ---------------------------------------------------------------------------
// fp16x2 GEMM (output projection; unchanged from round 9)
// ---------------------------------------------------------------------------
#define AH_OFF 0
#define AL_OFF 16384
#define BH_OFF 32768
#define STAGE_B  65536
#define GEMM_SMEM (2 * STAGE_B)   // 131072

#define LOAD_STAGE(c, s) do {                                              \
    int _k0 = (c) * 64;                                                    \
    uint32_t _stb = smb + (s) * STAGE_B;                                   \
    _Pragma("unroll")                                                      \
    for (int _i = 0; _i < 4; _i++) {                                       \
        int _id = tid + _i * 256;                                          \
        int _row = _id >> 3, _ch = _id & 7;                                \
        uint32_t _sw = (_row << 7) + ((_ch ^ (_row & 7)) << 4);            \
        const size_t _go = (size_t)_row * K + _k0 + _ch * 8;               \
        cp16(_stb + AH_OFF + _sw, srcAh + _go);                            \
        cp16(_stb + AL_OFF + _sw, srcAl + _go);                            \
    }                                                                      \
    _Pragma("unroll")                                                      \
    for (int _i = 0; _i < 8; _i++) {                                       \
        int _id = tid + _i * 256;                                          \
        int _row = _id >> 3, _ch = _id & 7;                                \
        uint32_t _sw = (_row << 7) + ((_ch ^ (_row & 7)) << 4);            \
        cp16(_stb + BH_OFF + _sw, srcB + (size_t)_row * K + _k0 + _ch * 8); \
    }                                                                      \
    asm volatile("cp.async.commit_group;");                                \
} while (0)

__global__ __launch_bounds__(256, 1) void gemm_f16x2(
    const __half* __restrict__ Ah, const __half* __restrict__ Al,
    const __half* __restrict__ B,
    float* __restrict__ C, int M, int N, int K)
{
    extern __shared__ char sm[];
    const uint32_t smb = smem_u32(sm);
    const int tid = threadIdx.x;
    const int wid = tid >> 5, lane = tid & 31;
    const int bm = blockIdx.y * 128, bn = blockIdx.x * 256;
    const int wm = (wid & 1) * 64, wn = (wid >> 1) * 64;

    const __half* srcAh = Ah + (size_t)bm * K;
    const __half* srcAl = Al + (size_t)bm * K;
    const __half* srcB  = B  + (size_t)bn * K;

    float acc[4][8][4];
#pragma unroll
    for (int i = 0; i < 4; i++)
#pragma unroll
        for (int j = 0; j < 8; j++)
#pragma unroll
            for (int e = 0; e < 4; e++) acc[i][j][e] = 0.f;

    const int NC = K / 64;
    LOAD_STAGE(0, 0);

    for (int c = 0; c < NC; c++) {
        const int s = c & 1;
        if (c + 1 < NC) {
            LOAD_STAGE(c + 1, s ^ 1);
            asm volatile("cp.async.wait_group 1;");
        } else {
            asm volatile("cp.async.wait_group 0;");
        }
        __syncthreads();

        const uint32_t base = smb + s * STAGE_B;
#pragma unroll
        for (int ks = 0; ks < 4; ks++) {
            const int c0 = ks * 2 + (lane >> 4);
            uint32_t ah[4][4], al[4][4], bh[4][4];
#pragma unroll
            for (int mi = 0; mi < 4; mi++) {
                int row = wm + mi * 16 + (lane & 15);
                uint32_t off = (row << 7) + ((c0 ^ (row & 7)) << 4);
                ldsm4(ah[mi], base + AH_OFF + off);
                ldsm4(al[mi], base + AL_OFF + off);
            }
#pragma unroll
            for (int ni = 0; ni < 4; ni++) {
                int row = wn + ni * 16 + (lane & 15);
                uint32_t off = (row << 7) + ((c0 ^ (row & 7)) << 4);
                ldsm4(bh[ni], base + BH_OFF + off);
            }
#pragma unroll
            for (int mi = 0; mi < 4; mi++)
#pragma unroll
                for (int ni = 0; ni < 4; ni++)
#pragma unroll
                    for (int sel = 0; sel < 2; sel++)
                        mma16816h(acc[mi][ni * 2 + sel], ah[mi],
                                  bh[ni][sel], bh[ni][sel + 2]);
#pragma unroll
            for (int mi = 0; mi < 4; mi++)
#pragma unroll
                for (int ni = 0; ni < 4; ni++)
#pragma unroll
                    for (int sel = 0; sel < 2; sel++)
                        mma16816h(acc[mi][ni * 2 + sel], al[mi],
                                  bh[ni][sel], bh[ni][sel + 2]);
        }
        __syncthreads();
    }

    const int g = lane >> 2, t = lane & 3;
#pragma unroll
    for (int mi = 0; mi < 4; mi++) {
#pragma unroll
        for (int nj = 0; nj < 8; nj++) {
            const float* a = acc[mi][nj];
            int row = bm + wm + mi * 16 + g;
            int col = bn + wn + nj * 8 + t * 2;
            *(float2*)&C[(size_t)row * N + col] = make_float2(a[0], a[1]);
            *(float2*)&C[(size_t)(row + 8) * N + col] = make_float2(a[2], a[3]);
        }
    }
}

// ---------------------------------------------------------------------------
// Pre-pass 1: RoPE + scale, fp16 Q -> [B][NQ][S][D]
// ---------------------------------------------------------------------------
__global__ void rope_q_f16(const float* __restrict__ qkv,
                           const float* __restrict__ cosb,
                           const float* __restrict__ sinb,
                           __half* __restrict__ qf)
{
    int idx = blockIdx.x * blockDim.x + threadIdx.x;
    const int total = BB * SS * NQ * 64;
    if (idx >= total) return;
    int d = idx & 63;
    int rest = idx >> 6;
    int h = rest % NQ;
    int s = (rest / NQ) % SS;
    int b = rest / (NQ * SS);
    const float* base = &qkv[((size_t)(b * SS + s)) * QKVN + h * DD];
    float x1 = base[d], x2 = base[d + 64];
    float c0 = cosb[s * DD + d],      s0 = sinb[s * DD + d];
    float c1 = cosb[s * DD + d + 64], s1 = sinb[s * DD + d + 64];
    size_t o = (((size_t)(b * NQ + h)) * SS + s) * DD + d;
    qf[o]      = __float2half((x1 * c0 - x2 * s0) * SCALE);
    qf[o + 64] = __float2half((x2 * c1 + x1 * s1) * SCALE);
}

// ---------------------------------------------------------------------------
// Pre-pass 2: unified fp16 KV [B][NKV][T][D]; RoPE on new K rows.
// ---------------------------------------------------------------------------
__global__ void build_kv_f16(const float* __restrict__ qkv,
                             const float* __restrict__ kcache,
                             const float* __restrict__ vcache,
                             const float* __restrict__ cosb,
                             const float* __restrict__ sinb,
                             __half* __restrict__ kf, __half* __restrict__ vf)
{
    int idx = blockIdx.x * blockDim.x + threadIdx.x;
    const int total = BB * NKV * TT * 64;
    if (idx >= total) return;
    int d = idx & 63;
    int rest = idx >> 6;
    int t = rest % TT;
    int kh = (rest / TT) % NKV;
    int b = rest / (TT * NKV);

    float k1, k2, v1, v2;
    if (t < PP) {
        size_t src = (((size_t)(b * PP + t)) * NKV + kh) * DD;
        k1 = kcache[src + d]; k2 = kcache[src + d + 64];
        v1 = vcache[src + d]; v2 = vcache[src + d + 64];
    } else {
        int s = t - PP;
        const float* base = &qkv[((size_t)(b * SS + s)) * QKVN];
        float x1 = base[(NQ + kh) * DD + d], x2 = base[(NQ + kh) * DD + d + 64];
        float c0 = cosb[s * DD + d],      s0 = sinb[s * DD + d];
        float c1 = cosb[s * DD + d + 64], s1 = sinb[s * DD + d + 64];
        k1 = x1 * c0 - x2 * s0;
        k2 = x2 * c1 + x1 * s1;
        v1 = base[(NQ + NKV + kh) * DD + d];
        v2 = base[(NQ + NKV + kh) * DD + d + 64];
    }
    size_t o = (((size_t)(b * NKV + kh)) * TT + t) * DD + d;
    kf[o]      = __float2half(k1);
    kf[o + 64] = __float2half(k2);
    vf[o]      = __float2half(v1);
    vf[o + 64] = __float2half(v2);
}

// ---------------------------------------------------------------------------
// Flash attention on tensor cores, fp16 single-pass QK and PV.
// Epilogue emits fp16 hi/lo for the fp16x2 output GEMM.
// ---------------------------------------------------------------------------
#define FA_SMEM (2 * 64 * 256)   // 32768: K tile + V tile (fp16)

__global__ __launch_bounds__(128) void flash_mma(
    const __half* __restrict__ qf_g,
    const __half* __restrict__ kf_g,
    const __half* __restrict__ vf_g,
    __half* __restrict__ attnh, __half* __restrict__ attnl)
{
    extern __shared__ char sm[];
    const uint32_t smb = smem_u32(sm);
    const uint32_t KO = 0, VO = 16384;
    const int tid = threadIdx.x, lane = tid & 31, w = tid >> 5;
    const int qi = blockIdx.x, h = blockIdx.y, b = blockIdx.z;
    const int sq0 = qi * 64;
    const int khd = h >> 2;
    const int g = lane >> 2, t4 = lane & 3;
    const int r0 = w * 16 + g, r1 = r0 + 8;

    uint32_t qf[8][4];
    {
        const __half* qb = qf_g + (((size_t)(b * NQ + h)) * SS + sq0) * DD;
#pragma unroll
        for (int ks = 0; ks < 8; ks++) {
            int c0 = ks * 16 + 2 * t4;
            qf[ks][0] = *(const uint32_t*)(qb + r0 * DD + c0);
            qf[ks][1] = *(const uint32_t*)(qb + r1 * DD + c0);
            qf[ks][2] = *(const uint32_t*)(qb + r0 * DD + c0 + 8);
            qf[ks][3] = *(const uint32_t*)(qb + r1 * DD + c0 + 8);
        }
    }

    float oacc[16][4];
#pragma unroll
    for (int i = 0; i < 16; i++)
#pragma unroll
        for (int j = 0; j < 4; j++) oacc[i][j] = 0.f;
    float m0 = -1e30f, m1 = -1e30f, l0 = 0.f, l1 = 0.f;

    const size_t kvb = ((size_t)(b * NKV + khd)) * TT * DD;
    const int nt = qi + 1 + PP / 64;

    for (int kt = 0; kt < nt; kt++) {
        __syncthreads();
        {
            const __half* srcK = kf_g + kvb + (size_t)kt * 64 * DD;
            const __half* srcV = vf_g + kvb + (size_t)kt * 64 * DD;
#pragma unroll
            for (int i = 0; i < 8; i++) {
                int id = tid + i * 128;
                int r = id >> 4, ch = id & 15;
                uint32_t sw = r * 256 + ((ch ^ (r & 7)) << 4);
                cp16(smb + KO + sw, srcK + r * DD + ch * 8);
                cp16(smb + VO + sw, srcV + r * DD + ch * 8);
            }
            asm volatile("cp.async.commit_group;");
            asm volatile("cp.async.wait_group 0;");
            __syncthreads();
        }

        float sacc[8][4];
#pragma unroll
        for (int j = 0; j < 8; j++)
#pragma unroll
            for (int e = 0; e < 4; e++) sacc[j][e] = 0.f;
#pragma unroll
        for (int ks = 0; ks < 8; ks++) {
            const int c0 = ks * 2 + (lane >> 4);
            uint32_t kb[4][4];
#pragma unroll
            for (int kg = 0; kg < 4; kg++) {
                int r = kg * 16 + (lane & 15);
                ldsm4(kb[kg], smb + KO + r * 256 + ((c0 ^ (r & 7)) << 4));
            }
#pragma unroll
            for (int kg = 0; kg < 4; kg++)
#pragma unroll
                for (int sel = 0; sel < 2; sel++)
                    mma16816h(sacc[kg * 2 + sel], qf[ks],
                              kb[kg][sel], kb[kg][sel + 2]);
        }

        if (kt == nt - 1) {
#pragma unroll
            for (int j = 0; j < 8; j++) {
                int cb = j * 8 + 2 * t4;
                if (cb     > r0) sacc[j][0] = -1e30f;
                if (cb + 1 > r0) sacc[j][1] = -1e30f;
                if (cb     > r1) sacc[j][2] = -1e30f;
                if (cb + 1 > r1) sacc[j][3] = -1e30f;
            }
        }

        float mx0 = m0, mx1 = m1;
#pragma unroll
        for (int j = 0; j < 8; j++) {
            mx0 = fmaxf(mx0, fmaxf(sacc[j][0], sacc[j][1]));
            mx1 = fmaxf(mx1, fmaxf(sacc[j][2], sacc[j][3]));
        }
        mx0 = fmaxf(mx0, __shfl_xor_sync(0xffffffff, mx0, 1));
        mx0 = fmaxf(mx0, __shfl_xor_sync(0xffffffff, mx0, 2));
        mx1 = fmaxf(mx1, __shfl_xor_sync(0xffffffff, mx1, 1));
        mx1 = fmaxf(mx1, __shfl_xor_sync(0xffffffff, mx1, 2));
        float rs0 = __expf(m0 - mx0), rs1 = __expf(m1 - mx1);
        m0 = mx0; m1 = mx1;
        l0 *= rs0; l1 *= rs1;

        uint32_t pf[4][4];
#pragma unroll
        for (int j = 0; j < 8; j++) {
            float p0 = __expf(sacc[j][0] - m0);
            float p1 = __expf(sacc[j][1] - m0);
            float p2 = __expf(sacc[j][2] - m1);
            float p3 = __expf(sacc[j][3] - m1);
            l0 += p0 + p1; l1 += p2 + p3;
            int kk = j >> 1, u = (j & 1) * 2;
            __half2 hA = __float22half2_rn(make_float2(p0, p1));
            __half2 hB = __float22half2_rn(make_float2(p2, p3));
            pf[kk][u]     = *(uint32_t*)&hA;
            pf[kk][u + 1] = *(uint32_t*)&hB;
        }

#pragma unroll
        for (int i = 0; i < 16; i++) {
            oacc[i][0] *= rs0; oacc[i][1] *= rs0;
            oacc[i][2] *= rs1; oacc[i][3] *= rs1;
        }

#pragma unroll
        for (int kk = 0; kk < 4; kk++) {
#pragma unroll
            for (int dp = 0; dp < 4; dp++) {
                const int dg0 = dp * 2, dg1 = dp * 2 + 1;
                int r = kk * 16 + (lane & 15);
                int cA = dg0 * 2 + (lane >> 4);
                int cB = dg1 * 2 + (lane >> 4);
                uint32_t v0[4], v1[4];
                ldsm4t(v0, smb + VO + r * 256 + ((cA ^ (r & 7)) << 4));
                ldsm4t(v1, smb + VO + r * 256 + ((cB ^ (r & 7)) << 4));
                mma16816h(oacc[dg0 * 2],     pf[kk], v0[0], v0[1]);
                mma16816h(oacc[dg0 * 2 + 1], pf[kk], v0[2], v0[3]);
                mma16816h(oacc[dg1 * 2],     pf[kk], v1[0], v1[1]);
                mma16816h(oacc[dg1 * 2 + 1], pf[kk], v1[2], v1[3]);
            }
        }
    }

    l0 += __shfl_xor_sync(0xffffffff, l0, 1);
    l0 += __shfl_xor_sync(0xffffffff, l0, 2);
    l1 += __shfl_xor_sync(0xffffffff, l1, 1);
    l1 += __shfl_xor_sync(0xffffffff, l1, 2);
    float inv0 = 1.f / l0, inv1 = 1.f / l1;

    size_t rowA = ((size_t)(b * SS + sq0 + r0)) * (NQ * DD) + h * DD;
    size_t rowB = ((size_t)(b * SS + sq0 + r1)) * (NQ * DD) + h * DD;
#pragma unroll
    for (int dt = 0; dt < 16; dt++) {
        int c = dt * 8 + 2 * t4;
        float v0 = oacc[dt][0] * inv0, v1 = oacc[dt][1] * inv0;
        float v2 = oacc[dt][2] * inv1, v3 = oacc[dt][3] * inv1;
        __half2 hA = __float22half2_rn(make_float2(v0, v1));
        float2 fA = __half22float2(hA);
        __half2 lA = __float22half2_rn(make_float2(v0 - fA.x, v1 - fA.y));
        __half2 hB = __float22half2_rn(make_float2(v2, v3));
        float2 fB = __half22float2(hB);
        __half2 lB = __float22half2_rn(make_float2(v2 - fB.x, v3 - fB.y));
        *(__half2*)&attnh[rowA + c] = hA;
        *(__half2*)&attnl[rowA + c] = lA;
        *(__half2*)&attnh[rowB + c] = hB;
        *(__half2*)&attnl[rowB + c] = lB;
    }
}

// ---------------------------------------------------------------------------
extern "C" void kernel_launch(void* const* d_in, const int* in_sizes, int n_in,
                              void* d_out, int out_size)
{
    const float* hidden = (const float*)d_in[0];
    const float* w_qkv  = (const float*)d_in[1];
    const float* w_o    = (const float*)d_in[2];
    const float* cosb   = (const float*)d_in[3];
    const float* sinb   = (const float*)d_in[4];
    const float* kc     = (const float*)d_in[5];
    const float* vc     = (const float*)d_in[6];
    float* out = (float*)d_out;

    float *qkv;
    __half *hidf, *wq, *wo, *ath, *atl, *qf, *kf, *vf;
    cudaGetSymbolAddress((void**)&qkv, g_qkv);
    cudaGetSymbolAddress((void**)&hidf, g_hid);
    cudaGetSymbolAddress((void**)&wq, g_wqkv);
    cudaGetSymbolAddress((void**)&wo, g_wo);
    cudaGetSymbolAddress((void**)&ath, g_attn_h);
    cudaGetSymbolAddress((void**)&atl, g_attn_l);
    cudaGetSymbolAddress((void**)&qf, g_q_f);
    cudaGetSymbolAddress((void**)&kf, g_k_f);
    cudaGetSymbolAddress((void**)&vf, g_v_f);

    cudaFuncSetAttribute(gemm_f16x1,
                         cudaFuncAttributeMaxDynamicSharedMemorySize, GEMM1_SMEM);
    cudaFuncSetAttribute(gemm_f16x2,
                         cudaFuncAttributeMaxDynamicSharedMemorySize, GEMM_SMEM);
    cudaFuncSetAttribute(flash_mma,
                         cudaFuncAttributeMaxDynamicSharedMemorySize, FA_SMEM);

    const int M = BB * SS;  // 2048

    // 0) activation convert + weight transposes (single fp16)
    {
        int n = M * HH;
        conv_f16<<<(n + 255) / 256, 256>>>(hidden, hidf, n);
        trans_f16<<<dim3(QKVN / 32, HH / 32), dim3(32, 8)>>>(w_qkv, wq, HH, QKVN);
        trans_f16<<<dim3(HH / 32, HH / 32), dim3(32, 8)>>>(w_o, wo, HH, HH);
    }
    // 1) QKV projection (fp16 single-pass)
    gemm_f16x1<<<dim3(QKVN / 256, M / 128), 256, GEMM1_SMEM>>>(
        hidf, wq, qkv, M, QKVN, HH);
    // 2) pre-passes (fp16 q/k/v)
    {
        int nq = BB * SS * NQ * 64;
        rope_q_f16<<<(nq + 255) / 256, 256>>>(qkv, cosb, sinb, qf);
        int nkv = BB * NKV * TT * 64;
        build_kv_f16<<<(nkv + 255) / 256, 256>>>(qkv, kc, vc, cosb, sinb, kf, vf);
    }
    // 3) Flash attention (fp16 single pass)
    flash_mma<<<dim3(SS / 64, NQ, BB), 128, FA_SMEM>>>(qf, kf, vf, ath, atl);
    // 4) Output projection (fp16x2, 2-pass)
    gemm_f16x2<<<dim3(HH / 256, M / 128), 256, GEMM_SMEM>>>(
        ath, atl, wo, out, M, HH, HH);
}

// round 11
// speedup vs baseline: 2.1579x; 1.0083x over previous
#include <cuda_runtime.h>
#include <cuda_bf16.h>
#include <cuda_fp16.h>
#include <math.h>
#include <stdint.h>

// Problem constants
#define BB   2
#define SS   1024
#define PP   1024
#define TT   (PP + SS)
#define HH   4096
#define NQ   32
#define NKV  8
#define DD   128
#define QKVN ((NQ + 2 * NKV) * DD)   // 6144
#define SCALE 0.08838834764831845f   // 1/sqrt(128)

// ---------------------------------------------------------------------------
// Scratch (device globals: no allocation allowed)
// ---------------------------------------------------------------------------
__device__ float g_qkv[BB * SS * QKVN];
__device__ __half g_hid[BB * SS * HH];               // activations fp16 (GEMM1)
__device__ __half g_wqkv[(size_t)QKVN * HH];         // weights fp16, transposed [N,K]
__device__ __half g_wo[(size_t)HH * HH];             // weights fp16, transposed [N,K]
__device__ __half g_attn_h[BB * SS * NQ * DD];       // attn out hi
__device__ __half g_attn_l[BB * SS * NQ * DD];       // attn out lo
// fp16 Q [B][NQ][S][D], unified fp16 KV [B][NKV][T][D]
__device__ __half g_q_f[(size_t)BB * NQ * SS * DD];
__device__ __half g_k_f[(size_t)BB * NKV * TT * DD];
__device__ __half g_v_f[(size_t)BB * NKV * TT * DD];

// ---------------------------------------------------------------------------
// Low-level helpers (plain sm_80+ ISA)
// ---------------------------------------------------------------------------
__device__ __forceinline__ uint32_t smem_u32(const void* p) {
    uint32_t a;
    asm("{ .reg .u64 t; cvta.to.shared.u64 t, %1; cvt.u32.u64 %0, t; }"
        : "=r"(a) : "l"(p));
    return a;
}
__device__ __forceinline__ void cp16(uint32_t dst, const void* src) {
    asm volatile("cp.async.cg.shared.global [%0], [%1], 16;"
                 :: "r"(dst), "l"(src));
}
__device__ __forceinline__ void ldsm4(uint32_t* r, uint32_t a) {
    asm volatile("ldmatrix.sync.aligned.m8n8.x4.shared.b16 {%0,%1,%2,%3}, [%4];"
                 : "=r"(r[0]), "=r"(r[1]), "=r"(r[2]), "=r"(r[3]) : "r"(a));
}
__device__ __forceinline__ void ldsm4t(uint32_t* r, uint32_t a) {
    asm volatile("ldmatrix.sync.aligned.m8n8.x4.trans.shared.b16 {%0,%1,%2,%3}, [%4];"
                 : "=r"(r[0]), "=r"(r[1]), "=r"(r[2]), "=r"(r[3]) : "r"(a));
}
// fp16 mma
__device__ __forceinline__ void mma16816h(float* c, const uint32_t* a,
                                          const uint32_t b0, const uint32_t b1) {
    asm volatile(
        "mma.sync.aligned.m16n8k16.row.col.f32.f16.f16.f32 "
        "{%0,%1,%2,%3}, {%4,%5,%6,%7}, {%8,%9}, {%0,%1,%2,%3};"
        : "+f"(c[0]), "+f"(c[1]), "+f"(c[2]), "+f"(c[3])
        : "r"(a[0]), "r"(a[1]), "r"(a[2]), "r"(a[3]), "r"(b0), "r"(b1));
}

// ---------------------------------------------------------------------------
// fp32 -> fp16 convert (same layout) — GEMM1 activations
// ---------------------------------------------------------------------------
__global__ void conv_f16(const float* __restrict__ x,
                         __half* __restrict__ xo, int n)
{
    int i = blockIdx.x * blockDim.x + threadIdx.x;
    if (i >= n) return;
    xo[i] = __float2half(x[i]);
}

// fp32 [R,C] -> single fp16 transposed [C,R] — weights
__global__ void trans_f16(const float* __restrict__ x,
                          __half* __restrict__ xo, int R, int C)
{
    __shared__ float t[32][33];
    int r0 = blockIdx.y * 32, c0 = blockIdx.x * 32;
    int tx = threadIdx.x, ty = threadIdx.y;
#pragma unroll
    for (int j = 0; j < 4; j++)
        t[ty + 8 * j][tx] = x[(size_t)(r0 + ty + 8 * j) * C + c0 + tx];
    __syncthreads();
#pragma unroll
    for (int j = 0; j < 4; j++)
        xo[(size_t)(c0 + ty + 8 * j) * R + r0 + tx] = __float2half(t[tx][ty + 8 * j]);
}

// ---------------------------------------------------------------------------
// fp16 single-pass GEMM (QKV projection): 128x256x64 tile, 8 warps,
// 3-stage cp.async pipeline.
// ---------------------------------------------------------------------------
#define X1_A_OFF 0
#define X1_B_OFF 16384
#define X1_STAGE 49152
#define GEMM1_SMEM (3 * X1_STAGE)   // 147456

#define LOAD_STAGE1(c, s) do {                                             \
    int _k0 = (c) * 64;                                                    \
    uint32_t _stb = smb + (s) * X1_STAGE;                                  \
    _Pragma("unroll")                                                      \
    for (int _i = 0; _i < 4; _i++) {                                       \
        int _id = tid + _i * 256;                                          \
        int _row = _id >> 3, _ch = _id & 7;                                \
        uint32_t _sw = (_row << 7) + ((_ch ^ (_row & 7)) << 4);            \
        cp16(_stb + X1_A_OFF + _sw, srcA + (size_t)_row * K + _k0 + _ch * 8); \
    }                                                                      \
    _Pragma("unroll")                                                      \
    for (int _i = 0; _i < 8; _i++) {                                       \
        int _id = tid + _i * 256;                                          \
        int _row = _id >> 3, _ch = _id & 7;                                \
        uint32_t _sw = (_row << 7) + ((_ch ^ (_row & 7)) << 4);            \
        cp16(_stb + X1_B_OFF + _sw, srcB + (size_t)_row * K + _k0 + _ch * 8); \
    }                                                                      \
    asm volatile("cp.async.commit_group;");                                \
} while (0)

__global__ __launch_bounds__(256, 1) void gemm_f16x1(
    const __half* __restrict__ A, const __half* __restrict__ B,
    float* __restrict__ C, int M, int N, int K)
{
    extern __shared__ char sm[];
    const uint32_t smb = smem_u32(sm);
    const int tid = threadIdx.x;
    const int wid = tid >> 5, lane = tid & 31;
    const int bm = blockIdx.y * 128, bn = blockIdx.x * 256;
    const int wm = (wid & 1) * 64, wn = (wid >> 1) * 64;

    const __half* srcA = A + (size_t)bm * K;
    const __half* srcB = B + (size_t)bn * K;

    float acc[4][8][4];
#pragma unroll
    for (int i = 0; i < 4; i++)
#pragma unroll
        for (int j = 0; j < 8; j++)
#pragma unroll
            for (int e = 0; e < 4; e++) acc[i][j][e] = 0.f;

    const int NC = K / 64;
    LOAD_STAGE1(0, 0);
    LOAD_STAGE1(1, 1);

    int sc = 0;      // compute stage
    int sl = 2;      // load stage
    for (int c = 0; c < NC; c++) {
        __syncthreads();   // all warps done with buffer sl (computed at c-1)
        if (c + 2 < NC) {
            LOAD_STAGE1(c + 2, sl);
            asm volatile("cp.async.wait_group 2;");
        } else if (c + 1 < NC) {
            asm volatile("cp.async.wait_group 1;");
        } else {
            asm volatile("cp.async.wait_group 0;");
        }
        __syncthreads();

        const uint32_t base = smb + sc * X1_STAGE;
#pragma unroll
        for (int ks = 0; ks < 4; ks++) {
            const int c0 = ks * 2 + (lane >> 4);
            uint32_t ah[4][4], bh[4][4];
#pragma unroll
            for (int mi = 0; mi < 4; mi++) {
                int row = wm + mi * 16 + (lane & 15);
                uint32_t off = (row << 7) + ((c0 ^ (row & 7)) << 4);
                ldsm4(ah[mi], base + X1_A_OFF + off);
            }
#pragma unroll
            for (int ni = 0; ni < 4; ni++) {
                int row = wn + ni * 16 + (lane & 15);
                uint32_t off = (row << 7) + ((c0 ^ (row & 7)) << 4);
                ldsm4(bh[ni], base + X1_B_OFF + off);
            }
#pragma unroll
            for (int mi = 0; mi < 4; mi++)
#pragma unroll
                for (int ni = 0; ni < 4; ni++)
#pragma unroll
                    for (int sel = 0; sel < 2; sel++)
                        mma16816h(acc[mi][ni * 2 + sel], ah[mi],
                                  bh[ni][sel], bh[ni][sel + 2]);
        }
        sc = (sc == 2) ? 0 : sc + 1;
        sl = (sl == 2) ? 0 : sl + 1;
    }

    const int g = lane >> 2, t = lane & 3;
#pragma unroll
    for (int mi = 0; mi < 4; mi++) {
#pragma unroll
        for (int nj = 0; nj < 8; nj++) {
            const float* a = acc[mi][nj];
            int row = bm + wm + mi * 16 + g;
            int col = bn + wn + nj * 8 + t * 2;
            *(float2*)&C[(size_t)row * N + col] = make_float2(a[0], a[1]);
            *(float2*)&C[(size_t)(row + 8) * N + col] = make_float2(a[2], a[3]);
        }
    }
}

// ---------------------------------------------------------------------------
// fp16x2 GEMM (output projection): (Ah+Al) @ B^T, 3-stage pipeline.
// ---------------------------------------------------------------------------
#define AH_OFF 0
#define AL_OFF 16384
#define BH_OFF 32768
#define STAGE_B  65536
#define GEMM_SMEM (3 * STAGE_B)   // 196608

#define LOAD_STAGE(c, s) do {                                              \
    int _k0 = (c) * 64;                                                    \
    uint32_t _stb = smb + (s) * STAGE_B;                                   \
    _Pragma("unroll")                                                      \
    for (int _i = 0; _i < 4; _i++) {                                       \
        int _id = tid + _i * 256;                                          \
        int _row = _id >> 3, _ch = _id & 7;                                \
        uint32_t _sw = (_row << 7) + ((_ch ^ (_row & 7)) << 4);            \
        const size_t _go = (size_t)_row * K + _k0 + _ch * 8;               \
        cp16(_stb + AH_OFF + _sw, srcAh + _go);                            \
        cp16(_stb + AL_OFF + _sw, srcAl + _go);                            \
    }                                                                      \
    _Pragma("unroll")                                                      \
    for (int _i = 0; _i < 8; _i++) {                                       \
        int _id = tid + _i * 256;                                          \
        int _row = _id >> 3, _ch = _id & 7;                                \
        uint32_t _sw = (_row << 7) + ((_ch ^ (_row & 7)) << 4);            \
        cp16(_stb + BH_OFF + _sw, srcB + (size_t)_row * K + _k0 + _ch * 8); \
    }                                                                      \
    asm volatile("cp.async.commit_group;");                                \
} while (0)

__global__ __launch_bounds__(256, 1) void gemm_f16x2(
    const __half* __restrict__ Ah, const __half* __restrict__ Al,
    const __half* __restrict__ B,
    float* __restrict__ C, int M, int N, int K)
{
    extern __shared__ char sm[];
    const uint32_t smb = smem_u32(sm);
    const int tid = threadIdx.x;
    const int wid = tid >> 5, lane = tid & 31;
    const int bm = blockIdx.y * 128, bn = blockIdx.x * 256;
    const int wm = (wid & 1) * 64, wn = (wid >> 1) * 64;

    const __half* srcAh = Ah + (size_t)bm * K;
    const __half* srcAl = Al + (size_t)bm * K;
    const __half* srcB  = B  + (size_t)bn * K;

    float acc[4][8][4];
#pragma unroll
    for (int i = 0; i < 4; i++)
#pragma unroll
        for (int j = 0; j < 8; j++)
#pragma unroll
            for (int e = 0; e < 4; e++) acc[i][j][e] = 0.f;

    const int NC = K / 64;
    LOAD_STAGE(0, 0);
    LOAD_STAGE(1, 1);

    int sc = 0, sl = 2;
    for (int c = 0; c < NC; c++) {
        __syncthreads();
        if (c + 2 < NC) {
            LOAD_STAGE(c + 2, sl);
            asm volatile("cp.async.wait_group 2;");
        } else if (c + 1 < NC) {
            asm volatile("cp.async.wait_group 1;");
        } else {
            asm volatile("cp.async.wait_group 0;");
        }
        __syncthreads();

        const uint32_t base = smb + sc * STAGE_B;
#pragma unroll
        for (int ks = 0; ks < 4; ks++) {
            const int c0 = ks * 2 + (lane >> 4);
            uint32_t ah[4][4], al[4][4], bh[4][4];
#pragma unroll
            for (int mi = 0; mi < 4; mi++) {
                int row = wm + mi * 16 + (lane & 15);
                uint32_t off = (row << 7) + ((c0 ^ (row & 7)) << 4);
                ldsm4(ah[mi], base + AH_OFF + off);
                ldsm4(al[mi], base + AL_OFF + off);
            }
#pragma unroll
            for (int ni = 0; ni < 4; ni++) {
                int row = wn + ni * 16 + (lane & 15);
                uint32_t off = (row << 7) + ((c0 ^ (row & 7)) << 4);
                ldsm4(bh[ni], base + BH_OFF + off);
            }
#pragma unroll
            for (int mi = 0; mi < 4; mi++)
#pragma unroll
                for (int ni = 0; ni < 4; ni++)
#pragma unroll
                    for (int sel = 0; sel < 2; sel++)
                        mma16816h(acc[mi][ni * 2 + sel], ah[mi],
                                  bh[ni][sel], bh[ni][sel + 2]);
#pragma unroll
            for (int mi = 0; mi < 4; mi++)
#pragma unroll
                for (int ni = 0; ni < 4; ni++)
#pragma unroll
                    for (int sel = 0; sel < 2; sel++)
                        mma16816h(acc[mi][ni * 2 + sel], al[mi],
                                  bh[ni][sel], bh[ni][sel + 2]);
        }
        sc = (sc == 2) ? 0 : sc + 1;
        sl = (sl == 2) ? 0 : sl + 1;
    }

    const int g = lane >> 2, t = lane & 3;
#pragma unroll
    for (int mi = 0; mi < 4; mi++) {
#pragma unroll
        for (int nj = 0; nj < 8; nj++) {
            const float* a = acc[mi][nj];
            int row = bm + wm + mi * 16 + g;
            int col = bn + wn + nj * 8 + t * 2;
            *(float2*)&C[(size_t)row * N + col] = make_float2(a[0], a[1]);
            *(float2*)&C[(size_t)(row + 8) * N + col] = make_float2(a[2], a[3]);
        }
    }
}

// ---------------------------------------------------------------------------
// Fused pre-pass: RoPE+scale Q -> fp16 [B][NQ][S][D]  AND
// unified fp16 KV [B][NKV][T][D] (RoPE on new K) in one launch.
// Identical arithmetic to the round-10 pair of kernels.
// ---------------------------------------------------------------------------
#define NQTOT (BB * SS * NQ * 64)
#define KVTOT (BB * NKV * TT * 64)

__global__ void prep_qkv_f16(const float* __restrict__ qkv,
                             const float* __restrict__ kcache,
                             const float* __restrict__ vcache,
                             const float* __restrict__ cosb,
                             const float* __restrict__ sinb,
                             __half* __restrict__ qf,
                             __half* __restrict__ kf, __half* __restrict__ vf)
{
    int idx = blockIdx.x * blockDim.x + threadIdx.x;
    if (idx < NQTOT) {
        int d = idx & 63;
        int rest = idx >> 6;
        int h = rest % NQ;
        int s = (rest / NQ) % SS;
        int b = rest / (NQ * SS);
        const float* base = &qkv[((size_t)(b * SS + s)) * QKVN + h * DD];
        float x1 = base[d], x2 = base[d + 64];
        float c0 = cosb[s * DD + d],      s0 = sinb[s * DD + d];
        float c1 = cosb[s * DD + d + 64], s1 = sinb[s * DD + d + 64];
        size_t o = (((size_t)(b * NQ + h)) * SS + s) * DD + d;
        qf[o]      = __float2half((x1 * c0 - x2 * s0) * SCALE);
        qf[o + 64] = __float2half((x2 * c1 + x1 * s1) * SCALE);
        return;
    }
    idx -= NQTOT;
    if (idx >= KVTOT) return;
    int d = idx & 63;
    int rest = idx >> 6;
    int t = rest % TT;
    int kh = (rest / TT) % NKV;
    int b = rest / (TT * NKV);

    float k1, k2, v1, v2;
    if (t < PP) {
        size_t src = (((size_t)(b * PP + t)) * NKV + kh) * DD;
        k1 = kcache[src + d]; k2 = kcache[src + d + 64];
        v1 = vcache[src + d]; v2 = vcache[src + d + 64];
    } else {
        int s = t - PP;
        const float* base = &qkv[((size_t)(b * SS + s)) * QKVN];
        float x1 = base[(NQ + kh) * DD + d], x2 = base[(NQ + kh) * DD + d + 64];
        float c0 = cosb[s * DD + d],      s0 = sinb[s * DD + d];
        float c1 = cosb[s * DD + d + 64], s1 = sinb[s * DD + d + 64];
        k1 = x1 * c0 - x2 * s0;
        k2 = x2 * c1 + x1 * s1;
        v1 = base[(NQ + NKV + kh) * DD + d];
        v2 = base[(NQ + NKV + kh) * DD + d + 64];
    }
    size_t o = (((size_t)(b * NKV + kh)) * TT + t) * DD + d;
    kf[o]      = __float2half(k1);
    kf[o + 64] = __float2half(k2);
    vf[o]      = __float2half(v1);
    vf[o + 64] = __float2half(v2);
}

// ---------------------------------------------------------------------------
// Flash attention on tensor cores, fp16 single-pass QK and PV (unchanged).
// ---------------------------------------------------------------------------
#define FA_SMEM (2 * 64 * 256)   // 32768: K tile + V tile (fp16)

__global__ __launch_bounds__(128) void flash_mma(
    const __half* __restrict__ qf_g,
    const __half* __restrict__ kf_g,
    const __half* __restrict__ vf_g,
    __half* __restrict__ attnh, __half* __restrict__ attnl)
{
    extern __shared__ char sm[];
    const uint32_t smb = smem_u32(sm);
    const uint32_t KO = 0, VO = 16384;
    const int tid = threadIdx.x, lane = tid & 31, w = tid >> 5;
    const int qi = blockIdx.x, h = blockIdx.y, b = blockIdx.z;
    const int sq0 = qi * 64;
    const int khd = h >> 2;
    const int g = lane >> 2, t4 = lane & 3;
    const int r0 = w * 16 + g, r1 = r0 + 8;

    uint32_t qf[8][4];
    {
        const __half* qb = qf_g + (((size_t)(b * NQ + h)) * SS + sq0) * DD;
#pragma unroll
        for (int ks = 0; ks < 8; ks++) {
            int c0 = ks * 16 + 2 * t4;
            qf[ks][0] = *(const uint32_t*)(qb + r0 * DD + c0);
            qf[ks][1] = *(const uint32_t*)(qb + r1 * DD + c0);
            qf[ks][2] = *(const uint32_t*)(qb + r0 * DD + c0 + 8);
            qf[ks][3] = *(const uint32_t*)(qb + r1 * DD + c0 + 8);
        }
    }

    float oacc[16][4];
#pragma unroll
    for (int i = 0; i < 16; i++)
#pragma unroll
        for (int j = 0; j < 4; j++) oacc[i][j] = 0.f;
    float m0 = -1e30f, m1 = -1e30f, l0 = 0.f, l1 = 0.f;

    const size_t kvb = ((size_t)(b * NKV + khd)) * TT * DD;
    const int nt = qi + 1 + PP / 64;

    for (int kt = 0; kt < nt; kt++) {
        __syncthreads();
        {
            const __half* srcK = kf_g + kvb + (size_t)kt * 64 * DD;
            const __half* srcV = vf_g + kvb + (size_t)kt * 64 * DD;
#pragma unroll
            for (int i = 0; i < 8; i++) {
                int id = tid + i * 128;
                int r = id >> 4, ch = id & 15;
                uint32_t sw = r * 256 + ((ch ^ (r & 7)) << 4);
                cp16(smb + KO + sw, srcK + r * DD + ch * 8);
                cp16(smb + VO + sw, srcV + r * DD + ch * 8);
            }
            asm volatile("cp.async.commit_group;");
            asm volatile("cp.async.wait_group 0;");
            __syncthreads();
        }

        float sacc[8][4];
#pragma unroll
        for (int j = 0; j < 8; j++)
#pragma unroll
            for (int e = 0; e < 4; e++) sacc[j][e] = 0.f;
#pragma unroll
        for (int ks = 0; ks < 8; ks++) {
            const int c0 = ks * 2 + (lane >> 4);
            uint32_t kb[4][4];
#pragma unroll
            for (int kg = 0; kg < 4; kg++) {
                int r = kg * 16 + (lane & 15);
                ldsm4(kb[kg], smb + KO + r * 256 + ((c0 ^ (r & 7)) << 4));
            }
#pragma unroll
            for (int kg = 0; kg < 4; kg++)
#pragma unroll
                for (int sel = 0; sel < 2; sel++)
                    mma16816h(sacc[kg * 2 + sel], qf[ks],
                              kb[kg][sel], kb[kg][sel + 2]);
        }

        if (kt == nt - 1) {
#pragma unroll
            for (int j = 0; j < 8; j++) {
                int cb = j * 8 + 2 * t4;
                if (cb     > r0) sacc[j][0] = -1e30f;
                if (cb + 1 > r0) sacc[j][1] = -1e30f;
                if (cb     > r1) sacc[j][2] = -1e30f;
                if (cb + 1 > r1) sacc[j][3] = -1e30f;
            }
        }

        float mx0 = m0, mx1 = m1;
#pragma unroll
        for (int j = 0; j < 8; j++) {
            mx0 = fmaxf(mx0, fmaxf(sacc[j][0], sacc[j][1]));
            mx1 = fmaxf(mx1, fmaxf(sacc[j][2], sacc[j][3]));
        }
        mx0 = fmaxf(mx0, __shfl_xor_sync(0xffffffff, mx0, 1));
        mx0 = fmaxf(mx0, __shfl_xor_sync(0xffffffff, mx0, 2));
        mx1 = fmaxf(mx1, __shfl_xor_sync(0xffffffff, mx1, 1));
        mx1 = fmaxf(mx1, __shfl_xor_sync(0xffffffff, mx1, 2));
        float rs0 = __expf(m0 - mx0), rs1 = __expf(m1 - mx1);
        m0 = mx0; m1 = mx1;
        l0 *= rs0; l1 *= rs1;

        uint32_t pf[4][4];
#pragma unroll
        for (int j = 0; j < 8; j++) {
            float p0 = __expf(sacc[j][0] - m0);
            float p1 = __expf(sacc[j][1] - m0);
            float p2 = __expf(sacc[j][2] - m1);
            float p3 = __expf(sacc[j][3] - m1);
            l0 += p0 + p1; l1 += p2 + p3;
            int kk = j >> 1, u = (j & 1) * 2;
            __half2 hA = __float22half2_rn(make_float2(p0, p1));
            __half2 hB = __float22half2_rn(make_float2(p2, p3));
            pf[kk][u]     = *(uint32_t*)&hA;
            pf[kk][u + 1] = *(uint32_t*)&hB;
        }

#pragma unroll
        for (int i = 0; i < 16; i++) {
            oacc[i][0] *= rs0; oacc[i][1] *= rs0;
            oacc[i][2] *= rs1; oacc[i][3] *= rs1;
        }

#pragma unroll
        for (int kk = 0; kk < 4; kk++) {
#pragma unroll
            for (int dp = 0; dp < 4; dp++) {
                const int dg0 = dp * 2, dg1 = dp * 2 + 1;
                int r = kk * 16 + (lane & 15);
                int cA = dg0 * 2 + (lane >> 4);
                int cB = dg1 * 2 + (lane >> 4);
                uint32_t v0[4], v1[4];
                ldsm4t(v0, smb + VO + r * 256 + ((cA ^ (r & 7)) << 4));
                ldsm4t(v1, smb + VO + r * 256 + ((cB ^ (r & 7)) << 4));
                mma16816h(oacc[dg0 * 2],     pf[kk], v0[0], v0[1]);
                mma16816h(oacc[dg0 * 2 + 1], pf[kk], v0[2], v0[3]);
                mma16816h(oacc[dg1 * 2],     pf[kk], v1[0], v1[1]);
                mma16816h(oacc[dg1 * 2 + 1], pf[kk], v1[2], v1[3]);
            }
        }
    }

    l0 += __shfl_xor_sync(0xffffffff, l0, 1);
    l0 += __shfl_xor_sync(0xffffffff, l0, 2);
    l1 += __shfl_xor_sync(0xffffffff, l1, 1);
    l1 += __shfl_xor_sync(0xffffffff, l1, 2);
    float inv0 = 1.f / l0, inv1 = 1.f / l1;

    size_t rowA = ((size_t)(b * SS + sq0 + r0)) * (NQ * DD) + h * DD;
    size_t rowB = ((size_t)(b * SS + sq0 + r1)) * (NQ * DD) + h * DD;
#pragma unroll
    for (int dt = 0; dt < 16; dt++) {
        int c = dt * 8 + 2 * t4;
        float v0 = oacc[dt][0] * inv0, v1 = oacc[dt][1] * inv0;
        float v2 = oacc[dt][2] * inv1, v3 = oacc[dt][3] * inv1;
        __half2 hA = __float22half2_rn(make_float2(v0, v1));
        float2 fA = __half22float2(hA);
        __half2 lA = __float22half2_rn(make_float2(v0 - fA.x, v1 - fA.y));
        __half2 hB = __float22half2_rn(make_float2(v2, v3));
        float2 fB = __half22float2(hB);
        __half2 lB = __float22half2_rn(make_float2(v2 - fB.x, v3 - fB.y));
        *(__half2*)&attnh[rowA + c] = hA;
        *(__half2*)&attnl[rowA + c] = lA;
        *(__half2*)&attnh[rowB + c] = hB;
        *(__half2*)&attnl[rowB + c] = lB;
    }
}

// ---------------------------------------------------------------------------
extern "C" void kernel_launch(void* const* d_in, const int* in_sizes, int n_in,
                              void* d_out, int out_size)
{
    const float* hidden = (const float*)d_in[0];
    const float* w_qkv  = (const float*)d_in[1];
    const float* w_o    = (const float*)d_in[2];
    const float* cosb   = (const float*)d_in[3];
    const float* sinb   = (const float*)d_in[4];
    const float* kc     = (const float*)d_in[5];
    const float* vc     = (const float*)d_in[6];
    float* out = (float*)d_out;

    float *qkv;
    __half *hidf, *wq, *wo, *ath, *atl, *qf, *kf, *vf;
    cudaGetSymbolAddress((void**)&qkv, g_qkv);
    cudaGetSymbolAddress((void**)&hidf, g_hid);
    cudaGetSymbolAddress((void**)&wq, g_wqkv);
    cudaGetSymbolAddress((void**)&wo, g_wo);
    cudaGetSymbolAddress((void**)&ath, g_attn_h);
    cudaGetSymbolAddress((void**)&atl, g_attn_l);
    cudaGetSymbolAddress((void**)&qf, g_q_f);
    cudaGetSymbolAddress((void**)&kf, g_k_f);
    cudaGetSymbolAddress((void**)&vf, g_v_f);

    cudaFuncSetAttribute(gemm_f16x1,
                         cudaFuncAttributeMaxDynamicSharedMemorySize, GEMM1_SMEM);
    cudaFuncSetAttribute(gemm_f16x2,
                         cudaFuncAttributeMaxDynamicSharedMemorySize, GEMM_SMEM);
    cudaFuncSetAttribute(flash_mma,
                         cudaFuncAttributeMaxDynamicSharedMemorySize, FA_SMEM);

    const int M = BB * SS;  // 2048

    // 0) activation convert + weight transposes (single fp16)
    {
        int n = M * HH;
        conv_f16<<<(n + 255) / 256, 256>>>(hidden, hidf, n);
        trans_f16<<<dim3(QKVN / 32, HH / 32), dim3(32, 8)>>>(w_qkv, wq, HH, QKVN);
        trans_f16<<<dim3(HH / 32, HH / 32), dim3(32, 8)>>>(w_o, wo, HH, HH);
    }
    // 1) QKV projection (fp16 single-pass, 3-stage pipeline)
    gemm_f16x1<<<dim3(QKVN / 256, M / 128), 256, GEMM1_SMEM>>>(
        hidf, wq, qkv, M, QKVN, HH);
    // 2) fused pre-pass (fp16 q/k/v)
    {
        int total = NQTOT + KVTOT;
        prep_qkv_f16<<<(total + 255) / 256, 256>>>(qkv, kc, vc, cosb, sinb,
                                                   qf, kf, vf);
    }
    // 3) Flash attention (fp16 single pass)
    flash_mma<<<dim3(SS / 64, NQ, BB), 128, FA_SMEM>>>(qf, kf, vf, ath, atl);
    // 4) Output projection (fp16x2, 3-stage pipeline)
    gemm_f16x2<<<dim3(HH / 256, M / 128), 256, GEMM_SMEM>>>(
        ath, atl, wo, out, M, HH, HH);
}

// round 12
// speedup vs baseline: 2.1642x; 1.0029x over previous
#include <cuda_runtime.h>
#include <cuda_bf16.h>
#include <cuda_fp16.h>
#include <math.h>
#include <stdint.h>

// Problem constants
#define BB   2
#define SS   1024
#define PP   1024
#define TT   (PP + SS)
#define HH   4096
#define NQ   32
#define NKV  8
#define DD   128
#define QKVN ((NQ + 2 * NKV) * DD)   // 6144
#define SCALE 0.08838834764831845f   // 1/sqrt(128)

// ---------------------------------------------------------------------------
// Scratch (device globals: no allocation allowed)
// ---------------------------------------------------------------------------
__device__ float g_qkv[BB * SS * QKVN];
__device__ __half g_hid[BB * SS * HH];
__device__ __half g_wqkv[(size_t)QKVN * HH];         // transposed [N,K]
__device__ __half g_wo[(size_t)HH * HH];             // transposed [N,K]
__device__ __half g_attn_h[BB * SS * NQ * DD];
__device__ __half g_attn_l[BB * SS * NQ * DD];
__device__ __half g_q_f[(size_t)BB * NQ * SS * DD];
__device__ __half g_k_f[(size_t)BB * NKV * TT * DD];
__device__ __half g_v_f[(size_t)BB * NKV * TT * DD];

// ---------------------------------------------------------------------------
// Low-level helpers (plain sm_80+ ISA)
// ---------------------------------------------------------------------------
__device__ __forceinline__ uint32_t smem_u32(const void* p) {
    uint32_t a;
    asm("{ .reg .u64 t; cvta.to.shared.u64 t, %1; cvt.u32.u64 %0, t; }"
        : "=r"(a) : "l"(p));
    return a;
}
__device__ __forceinline__ void cp16(uint32_t dst, const void* src) {
    asm volatile("cp.async.cg.shared.global [%0], [%1], 16;"
                 :: "r"(dst), "l"(src));
}
__device__ __forceinline__ void ldsm4(uint32_t* r, uint32_t a) {
    asm volatile("ldmatrix.sync.aligned.m8n8.x4.shared.b16 {%0,%1,%2,%3}, [%4];"
                 : "=r"(r[0]), "=r"(r[1]), "=r"(r[2]), "=r"(r[3]) : "r"(a));
}
__device__ __forceinline__ void ldsm4t(uint32_t* r, uint32_t a) {
    asm volatile("ldmatrix.sync.aligned.m8n8.x4.trans.shared.b16 {%0,%1,%2,%3}, [%4];"
                 : "=r"(r[0]), "=r"(r[1]), "=r"(r[2]), "=r"(r[3]) : "r"(a));
}
__device__ __forceinline__ void mma16816h(float* c, const uint32_t* a,
                                          const uint32_t b0, const uint32_t b1) {
    asm volatile(
        "mma.sync.aligned.m16n8k16.row.col.f32.f16.f16.f32 "
        "{%0,%1,%2,%3}, {%4,%5,%6,%7}, {%8,%9}, {%0,%1,%2,%3};"
        : "+f"(c[0]), "+f"(c[1]), "+f"(c[2]), "+f"(c[3])
        : "r"(a[0]), "r"(a[1]), "r"(a[2]), "r"(a[3]), "r"(b0), "r"(b1));
}

// ---------------------------------------------------------------------------
// fp32 -> fp16 convert (GEMM1 activations)
// ---------------------------------------------------------------------------
__global__ void conv_f16(const float* __restrict__ x,
                         __half* __restrict__ xo, int n)
{
    int i = blockIdx.x * blockDim.x + threadIdx.x;
    if (i >= n) return;
    xo[i] = __float2half(x[i]);
}

// fp32 [R,C] -> fp16 transposed [C,R] (weights)
__global__ void trans_f16(const float* __restrict__ x,
                          __half* __restrict__ xo, int R, int C)
{
    __shared__ float t[32][33];
    int r0 = blockIdx.y * 32, c0 = blockIdx.x * 32;
    int tx = threadIdx.x, ty = threadIdx.y;
#pragma unroll
    for (int j = 0; j < 4; j++)
        t[ty + 8 * j][tx] = x[(size_t)(r0 + ty + 8 * j) * C + c0 + tx];
    __syncthreads();
#pragma unroll
    for (int j = 0; j < 4; j++)
        xo[(size_t)(c0 + ty + 8 * j) * R + r0 + tx] = __float2half(t[tx][ty + 8 * j]);
}

// ---------------------------------------------------------------------------
// fp16 single-pass GEMM (QKV): 128x256x64, 8 warps, 3-stage pipeline,
// register-double-buffered fragments (ldsm for ks+1 before MMAs of ks).
// ---------------------------------------------------------------------------
#define X1_A_OFF 0
#define X1_B_OFF 16384
#define X1_STAGE 49152
#define GEMM1_SMEM (3 * X1_STAGE)

#define LOAD_STAGE1(c, s) do {                                             \
    int _k0 = (c) * 64;                                                    \
    uint32_t _stb = smb + (s) * X1_STAGE;                                  \
    _Pragma("unroll")                                                      \
    for (int _i = 0; _i < 4; _i++) {                                       \
        int _id = tid + _i * 256;                                          \
        int _row = _id >> 3, _ch = _id & 7;                                \
        uint32_t _sw = (_row << 7) + ((_ch ^ (_row & 7)) << 4);            \
        cp16(_stb + X1_A_OFF + _sw, srcA + (size_t)_row * K + _k0 + _ch * 8); \
    }                                                                      \
    _Pragma("unroll")                                                      \
    for (int _i = 0; _i < 8; _i++) {                                       \
        int _id = tid + _i * 256;                                          \
        int _row = _id >> 3, _ch = _id & 7;                                \
        uint32_t _sw = (_row << 7) + ((_ch ^ (_row & 7)) << 4);            \
        cp16(_stb + X1_B_OFF + _sw, srcB + (size_t)_row * K + _k0 + _ch * 8); \
    }                                                                      \
    asm volatile("cp.async.commit_group;");                                \
} while (0)

__global__ __launch_bounds__(256, 1) void gemm_f16x1(
    const __half* __restrict__ A, const __half* __restrict__ B,
    float* __restrict__ C, int M, int N, int K)
{
    extern __shared__ char sm[];
    const uint32_t smb = smem_u32(sm);
    const int tid = threadIdx.x;
    const int wid = tid >> 5, lane = tid & 31;
    const int bm = blockIdx.y * 128, bn = blockIdx.x * 256;
    const int wm = (wid & 1) * 64, wn = (wid >> 1) * 64;

    const __half* srcA = A + (size_t)bm * K;
    const __half* srcB = B + (size_t)bn * K;

    // per-warp invariant row offsets for ldmatrix
    uint32_t arb[4], brb[4];
#pragma unroll
    for (int mi = 0; mi < 4; mi++) {
        int row = wm + mi * 16 + (lane & 15);
        arb[mi] = (uint32_t)(row << 7) + X1_A_OFF;
    }
#pragma unroll
    for (int ni = 0; ni < 4; ni++) {
        int row = wn + ni * 16 + (lane & 15);
        brb[ni] = (uint32_t)(row << 7) + X1_B_OFF;
    }
    const int rswA[4] = { (wm + 0 * 16 + (lane & 15)) & 7,
                          (wm + 1 * 16 + (lane & 15)) & 7,
                          (wm + 2 * 16 + (lane & 15)) & 7,
                          (wm + 3 * 16 + (lane & 15)) & 7 };
    const int rswB[4] = { (wn + 0 * 16 + (lane & 15)) & 7,
                          (wn + 1 * 16 + (lane & 15)) & 7,
                          (wn + 2 * 16 + (lane & 15)) & 7,
                          (wn + 3 * 16 + (lane & 15)) & 7 };

    float acc[4][8][4];
#pragma unroll
    for (int i = 0; i < 4; i++)
#pragma unroll
        for (int j = 0; j < 8; j++)
#pragma unroll
            for (int e = 0; e < 4; e++) acc[i][j][e] = 0.f;

    const int NC = K / 64;
    LOAD_STAGE1(0, 0);
    LOAD_STAGE1(1, 1);

    uint32_t ah[2][4][4], bh[2][4][4];
    int sc = 0, sl = 2;
    for (int c = 0; c < NC; c++) {
        __syncthreads();
        if (c + 2 < NC) {
            LOAD_STAGE1(c + 2, sl);
            asm volatile("cp.async.wait_group 2;");
        } else if (c + 1 < NC) {
            asm volatile("cp.async.wait_group 1;");
        } else {
            asm volatile("cp.async.wait_group 0;");
        }
        __syncthreads();

        const uint32_t base = smb + sc * X1_STAGE;
        // prefetch ks=0 fragments
        {
            const int c0 = (lane >> 4);
#pragma unroll
            for (int mi = 0; mi < 4; mi++)
                ldsm4(ah[0][mi], base + arb[mi] + ((c0 ^ rswA[mi]) << 4));
#pragma unroll
            for (int ni = 0; ni < 4; ni++)
                ldsm4(bh[0][ni], base + brb[ni] + ((c0 ^ rswB[ni]) << 4));
        }
#pragma unroll
        for (int ks = 0; ks < 4; ks++) {
            const int cur = ks & 1, nxt = cur ^ 1;
            if (ks < 3) {
                const int c0 = (ks + 1) * 2 + (lane >> 4);
#pragma unroll
                for (int mi = 0; mi < 4; mi++)
                    ldsm4(ah[nxt][mi], base + arb[mi] + ((c0 ^ rswA[mi]) << 4));
#pragma unroll
                for (int ni = 0; ni < 4; ni++)
                    ldsm4(bh[nxt][ni], base + brb[ni] + ((c0 ^ rswB[ni]) << 4));
            }
#pragma unroll
            for (int mi = 0; mi < 4; mi++)
#pragma unroll
                for (int ni = 0; ni < 4; ni++)
#pragma unroll
                    for (int sel = 0; sel < 2; sel++)
                        mma16816h(acc[mi][ni * 2 + sel], ah[cur][mi],
                                  bh[cur][ni][sel], bh[cur][ni][sel + 2]);
        }
        sc = (sc == 2) ? 0 : sc + 1;
        sl = (sl == 2) ? 0 : sl + 1;
    }

    const int g = lane >> 2, t = lane & 3;
#pragma unroll
    for (int mi = 0; mi < 4; mi++) {
#pragma unroll
        for (int nj = 0; nj < 8; nj++) {
            const float* a = acc[mi][nj];
            int row = bm + wm + mi * 16 + g;
            int col = bn + wn + nj * 8 + t * 2;
            *(float2*)&C[(size_t)row * N + col] = make_float2(a[0], a[1]);
            *(float2*)&C[(size_t)(row + 8) * N + col] = make_float2(a[2], a[3]);
        }
    }
}

// ---------------------------------------------------------------------------
// fp16x2 GEMM (output projection): prefetch Ah/Bh for ks+1; Al for current
// ks is issued at step start and consumed after the 32-MMA hh pass.
// ---------------------------------------------------------------------------
#define AH_OFF 0
#define AL_OFF 16384
#define BH_OFF 32768
#define STAGE_B  65536
#define GEMM_SMEM (3 * STAGE_B)

#define LOAD_STAGE(c, s) do {                                              \
    int _k0 = (c) * 64;                                                    \
    uint32_t _stb = smb + (s) * STAGE_B;                                   \
    _Pragma("unroll")                                                      \
    for (int _i = 0; _i < 4; _i++) {                                       \
        int _id = tid + _i * 256;                                          \
        int _row = _id >> 3, _ch = _id & 7;                                \
        uint32_t _sw = (_row << 7) + ((_ch ^ (_row & 7)) << 4);            \
        const size_t _go = (size_t)_row * K + _k0 + _ch * 8;               \
        cp16(_stb + AH_OFF + _sw, srcAh + _go);                            \
        cp16(_stb + AL_OFF + _sw, srcAl + _go);                            \
    }                                                                      \
    _Pragma("unroll")                                                      \
    for (int _i = 0; _i < 8; _i++) {                                       \
        int _id = tid + _i * 256;                                          \
        int _row = _id >> 3, _ch = _id & 7;                                \
        uint32_t _sw = (_row << 7) + ((_ch ^ (_row & 7)) << 4);            \
        cp16(_stb + BH_OFF + _sw, srcB + (size_t)_row * K + _k0 + _ch * 8); \
    }                                                                      \
    asm volatile("cp.async.commit_group;");                                \
} while (0)

__global__ __launch_bounds__(256, 1) void gemm_f16x2(
    const __half* __restrict__ Ah, const __half* __restrict__ Al,
    const __half* __restrict__ B,
    float* __restrict__ C, int M, int N, int K)
{
    extern __shared__ char sm[];
    const uint32_t smb = smem_u32(sm);
    const int tid = threadIdx.x;
    const int wid = tid >> 5, lane = tid & 31;
    const int bm = blockIdx.y * 128, bn = blockIdx.x * 256;
    const int wm = (wid & 1) * 64, wn = (wid >> 1) * 64;

    const __half* srcAh = Ah + (size_t)bm * K;
    const __half* srcAl = Al + (size_t)bm * K;
    const __half* srcB  = B  + (size_t)bn * K;

    uint32_t arb[4], brb[4];
#pragma unroll
    for (int mi = 0; mi < 4; mi++)
        arb[mi] = (uint32_t)((wm + mi * 16 + (lane & 15)) << 7);
#pragma unroll
    for (int ni = 0; ni < 4; ni++)
        brb[ni] = (uint32_t)((wn + ni * 16 + (lane & 15)) << 7);
    const int rswA[4] = { (wm + 0 * 16 + (lane & 15)) & 7,
                          (wm + 1 * 16 + (lane & 15)) & 7,
                          (wm + 2 * 16 + (lane & 15)) & 7,
                          (wm + 3 * 16 + (lane & 15)) & 7 };
    const int rswB[4] = { (wn + 0 * 16 + (lane & 15)) & 7,
                          (wn + 1 * 16 + (lane & 15)) & 7,
                          (wn + 2 * 16 + (lane & 15)) & 7,
                          (wn + 3 * 16 + (lane & 15)) & 7 };

    float acc[4][8][4];
#pragma unroll
    for (int i = 0; i < 4; i++)
#pragma unroll
        for (int j = 0; j < 8; j++)
#pragma unroll
            for (int e = 0; e < 4; e++) acc[i][j][e] = 0.f;

    const int NC = K / 64;
    LOAD_STAGE(0, 0);
    LOAD_STAGE(1, 1);

    uint32_t ah[2][4][4], bh[2][4][4], al[4][4];
    int sc = 0, sl = 2;
    for (int c = 0; c < NC; c++) {
        __syncthreads();
        if (c + 2 < NC) {
            LOAD_STAGE(c + 2, sl);
            asm volatile("cp.async.wait_group 2;");
        } else if (c + 1 < NC) {
            asm volatile("cp.async.wait_group 1;");
        } else {
            asm volatile("cp.async.wait_group 0;");
        }
        __syncthreads();

        const uint32_t base = smb + sc * STAGE_B;
        {
            const int c0 = (lane >> 4);
#pragma unroll
            for (int mi = 0; mi < 4; mi++)
                ldsm4(ah[0][mi], base + AH_OFF + arb[mi] + ((c0 ^ rswA[mi]) << 4));
#pragma unroll
            for (int ni = 0; ni < 4; ni++)
                ldsm4(bh[0][ni], base + BH_OFF + brb[ni] + ((c0 ^ rswB[ni]) << 4));
        }
#pragma unroll
        for (int ks = 0; ks < 4; ks++) {
            const int cur = ks & 1, nxt = cur ^ 1;
            const int c0c = ks * 2 + (lane >> 4);
            // Al for current ks (consumed after the 32-MMA hh pass)
#pragma unroll
            for (int mi = 0; mi < 4; mi++)
                ldsm4(al[mi], base + AL_OFF + arb[mi] + ((c0c ^ rswA[mi]) << 4));
            if (ks < 3) {
                const int c0n = (ks + 1) * 2 + (lane >> 4);
#pragma unroll
                for (int mi = 0; mi < 4; mi++)
                    ldsm4(ah[nxt][mi], base + AH_OFF + arb[mi] + ((c0n ^ rswA[mi]) << 4));
#pragma unroll
                for (int ni = 0; ni < 4; ni++)
                    ldsm4(bh[nxt][ni], base + BH_OFF + brb[ni] + ((c0n ^ rswB[ni]) << 4));
            }
            // pass hh
#pragma unroll
            for (int mi = 0; mi < 4; mi++)
#pragma unroll
                for (int ni = 0; ni < 4; ni++)
#pragma unroll
                    for (int sel = 0; sel < 2; sel++)
                        mma16816h(acc[mi][ni * 2 + sel], ah[cur][mi],
                                  bh[cur][ni][sel], bh[cur][ni][sel + 2]);
            // pass lh
#pragma unroll
            for (int mi = 0; mi < 4; mi++)
#pragma unroll
                for (int ni = 0; ni < 4; ni++)
#pragma unroll
                    for (int sel = 0; sel < 2; sel++)
                        mma16816h(acc[mi][ni * 2 + sel], al[mi],
                                  bh[cur][ni][sel], bh[cur][ni][sel + 2]);
        }
        sc = (sc == 2) ? 0 : sc + 1;
        sl = (sl == 2) ? 0 : sl + 1;
    }

    const int g = lane >> 2, t = lane & 3;
#pragma unroll
    for (int mi = 0; mi < 4; mi++) {
#pragma unroll
        for (int nj = 0; nj < 8; nj++) {
            const float* a = acc[mi][nj];
            int row = bm + wm + mi * 16 + g;
            int col = bn + wn + nj * 8 + t * 2;
            *(float2*)&C[(size_t)row * N + col] = make_float2(a[0], a[1]);
            *(float2*)&C[(size_t)(row + 8) * N + col] = make_float2(a[2], a[3]);
        }
    }
}

// ---------------------------------------------------------------------------
// Fused pre-pass (unchanged round-11 arithmetic)
// ---------------------------------------------------------------------------
#define NQTOT (BB * SS * NQ * 64)
#define KVTOT (BB * NKV * TT * 64)

__global__ void prep_qkv_f16(const float* __restrict__ qkv,
                             const float* __restrict__ kcache,
                             const float* __restrict__ vcache,
                             const float* __restrict__ cosb,
                             const float* __restrict__ sinb,
                             __half* __restrict__ qf,
                             __half* __restrict__ kf, __half* __restrict__ vf)
{
    int idx = blockIdx.x * blockDim.x + threadIdx.x;
    if (idx < NQTOT) {
        int d = idx & 63;
        int rest = idx >> 6;
        int h = rest % NQ;
        int s = (rest / NQ) % SS;
        int b = rest / (NQ * SS);
        const float* base = &qkv[((size_t)(b * SS + s)) * QKVN + h * DD];
        float x1 = base[d], x2 = base[d + 64];
        float c0 = cosb[s * DD + d],      s0 = sinb[s * DD + d];
        float c1 = cosb[s * DD + d + 64], s1 = sinb[s * DD + d + 64];
        size_t o = (((size_t)(b * NQ + h)) * SS + s) * DD + d;
        qf[o]      = __float2half((x1 * c0 - x2 * s0) * SCALE);
        qf[o + 64] = __float2half((x2 * c1 + x1 * s1) * SCALE);
        return;
    }
    idx -= NQTOT;
    if (idx >= KVTOT) return;
    int d = idx & 63;
    int rest = idx >> 6;
    int t = rest % TT;
    int kh = (rest / TT) % NKV;
    int b = rest / (TT * NKV);

    float k1, k2, v1, v2;
    if (t < PP) {
        size_t src = (((size_t)(b * PP + t)) * NKV + kh) * DD;
        k1 = kcache[src + d]; k2 = kcache[src + d + 64];
        v1 = vcache[src + d]; v2 = vcache[src + d + 64];
    } else {
        int s = t - PP;
        const float* base = &qkv[((size_t)(b * SS + s)) * QKVN];
        float x1 = base[(NQ + kh) * DD + d], x2 = base[(NQ + kh) * DD + d + 64];
        float c0 = cosb[s * DD + d],      s0 = sinb[s * DD + d];
        float c1 = cosb[s * DD + d + 64], s1 = sinb[s * DD + d + 64];
        k1 = x1 * c0 - x2 * s0;
        k2 = x2 * c1 + x1 * s1;
        v1 = base[(NQ + NKV + kh) * DD + d];
        v2 = base[(NQ + NKV + kh) * DD + d + 64];
    }
    size_t o = (((size_t)(b * NKV + kh)) * TT + t) * DD + d;
    kf[o]      = __float2half(k1);
    kf[o + 64] = __float2half(k2);
    vf[o]      = __float2half(v1);
    vf[o + 64] = __float2half(v2);
}

// ---------------------------------------------------------------------------
// Flash attention, fp16, with register double-buffered K and V fragments.
// ---------------------------------------------------------------------------
#define FA_SMEM (2 * 64 * 256)

__global__ __launch_bounds__(128) void flash_mma(
    const __half* __restrict__ qf_g,
    const __half* __restrict__ kf_g,
    const __half* __restrict__ vf_g,
    __half* __restrict__ attnh, __half* __restrict__ attnl)
{
    extern __shared__ char sm[];
    const uint32_t smb = smem_u32(sm);
    const uint32_t KO = 0, VO = 16384;
    const int tid = threadIdx.x, lane = tid & 31, w = tid >> 5;
    const int qi = blockIdx.x, h = blockIdx.y, b = blockIdx.z;
    const int sq0 = qi * 64;
    const int khd = h >> 2;
    const int g = lane >> 2, t4 = lane & 3;
    const int r0 = w * 16 + g, r1 = r0 + 8;

    uint32_t qf[8][4];
    {
        const __half* qb = qf_g + (((size_t)(b * NQ + h)) * SS + sq0) * DD;
#pragma unroll
        for (int ks = 0; ks < 8; ks++) {
            int c0 = ks * 16 + 2 * t4;
            qf[ks][0] = *(const uint32_t*)(qb + r0 * DD + c0);
            qf[ks][1] = *(const uint32_t*)(qb + r1 * DD + c0);
            qf[ks][2] = *(const uint32_t*)(qb + r0 * DD + c0 + 8);
            qf[ks][3] = *(const uint32_t*)(qb + r1 * DD + c0 + 8);
        }
    }

    // per-warp invariant ldsm rows
    uint32_t krb[4];
    int krsw[4];
#pragma unroll
    for (int kg = 0; kg < 4; kg++) {
        int r = kg * 16 + (lane & 15);
        krb[kg] = (uint32_t)(r * 256);
        krsw[kg] = r & 7;
    }

    float oacc[16][4];
#pragma unroll
    for (int i = 0; i < 16; i++)
#pragma unroll
        for (int j = 0; j < 4; j++) oacc[i][j] = 0.f;
    float m0 = -1e30f, m1 = -1e30f, l0 = 0.f, l1 = 0.f;

    const size_t kvb = ((size_t)(b * NKV + khd)) * TT * DD;
    const int nt = qi + 1 + PP / 64;

    for (int kt = 0; kt < nt; kt++) {
        __syncthreads();
        {
            const __half* srcK = kf_g + kvb + (size_t)kt * 64 * DD;
            const __half* srcV = vf_g + kvb + (size_t)kt * 64 * DD;
#pragma unroll
            for (int i = 0; i < 8; i++) {
                int id = tid + i * 128;
                int r = id >> 4, ch = id & 15;
                uint32_t sw = r * 256 + ((ch ^ (r & 7)) << 4);
                cp16(smb + KO + sw, srcK + r * DD + ch * 8);
                cp16(smb + VO + sw, srcV + r * DD + ch * 8);
            }
            asm volatile("cp.async.commit_group;");
            asm volatile("cp.async.wait_group 0;");
            __syncthreads();
        }

        // S = Q K^T with K-fragment double buffering
        float sacc[8][4];
#pragma unroll
        for (int j = 0; j < 8; j++)
#pragma unroll
            for (int e = 0; e < 4; e++) sacc[j][e] = 0.f;

        uint32_t kb[2][4][4];
        {
            const int c0 = (lane >> 4);
#pragma unroll
            for (int kg = 0; kg < 4; kg++)
                ldsm4(kb[0][kg], smb + KO + krb[kg] + ((c0 ^ krsw[kg]) << 4));
        }
#pragma unroll
        for (int ks = 0; ks < 8; ks++) {
            const int cur = ks & 1, nxt = cur ^ 1;
            if (ks < 7) {
                const int c0 = (ks + 1) * 2 + (lane >> 4);
#pragma unroll
                for (int kg = 0; kg < 4; kg++)
                    ldsm4(kb[nxt][kg], smb + KO + krb[kg] + ((c0 ^ krsw[kg]) << 4));
            }
#pragma unroll
            for (int kg = 0; kg < 4; kg++)
#pragma unroll
                for (int sel = 0; sel < 2; sel++)
                    mma16816h(sacc[kg * 2 + sel], qf[ks],
                              kb[cur][kg][sel], kb[cur][kg][sel + 2]);
        }

        if (kt == nt - 1) {
#pragma unroll
            for (int j = 0; j < 8; j++) {
                int cb = j * 8 + 2 * t4;
                if (cb     > r0) sacc[j][0] = -1e30f;
                if (cb + 1 > r0) sacc[j][1] = -1e30f;
                if (cb     > r1) sacc[j][2] = -1e30f;
                if (cb + 1 > r1) sacc[j][3] = -1e30f;
            }
        }

        float mx0 = m0, mx1 = m1;
#pragma unroll
        for (int j = 0; j < 8; j++) {
            mx0 = fmaxf(mx0, fmaxf(sacc[j][0], sacc[j][1]));
            mx1 = fmaxf(mx1, fmaxf(sacc[j][2], sacc[j][3]));
        }
        mx0 = fmaxf(mx0, __shfl_xor_sync(0xffffffff, mx0, 1));
        mx0 = fmaxf(mx0, __shfl_xor_sync(0xffffffff, mx0, 2));
        mx1 = fmaxf(mx1, __shfl_xor_sync(0xffffffff, mx1, 1));
        mx1 = fmaxf(mx1, __shfl_xor_sync(0xffffffff, mx1, 2));
        float rs0 = __expf(m0 - mx0), rs1 = __expf(m1 - mx1);
        m0 = mx0; m1 = mx1;
        l0 *= rs0; l1 *= rs1;

        uint32_t pf[4][4];
#pragma unroll
        for (int j = 0; j < 8; j++) {
            float p0 = __expf(sacc[j][0] - m0);
            float p1 = __expf(sacc[j][1] - m0);
            float p2 = __expf(sacc[j][2] - m1);
            float p3 = __expf(sacc[j][3] - m1);
            l0 += p0 + p1; l1 += p2 + p3;
            int kk = j >> 1, u = (j & 1) * 2;
            __half2 hA = __float22half2_rn(make_float2(p0, p1));
            __half2 hB = __float22half2_rn(make_float2(p2, p3));
            pf[kk][u]     = *(uint32_t*)&hA;
            pf[kk][u + 1] = *(uint32_t*)&hB;
        }

#pragma unroll
        for (int i = 0; i < 16; i++) {
            oacc[i][0] *= rs0; oacc[i][1] *= rs0;
            oacc[i][2] *= rs1; oacc[i][3] *= rs1;
        }

        // O += P V with V-fragment double buffering (flattened 16 iters)
        uint32_t vfr[2][2][4];
        {
            // idx = 0: kk=0, dp=0
            int r = (lane & 15);
            int cA = 0 * 4 + (lane >> 4);
            int cB = 0 * 4 + 2 + (lane >> 4);
            ldsm4t(vfr[0][0], smb + VO + r * 256 + ((cA ^ (r & 7)) << 4));
            ldsm4t(vfr[0][1], smb + VO + r * 256 + ((cB ^ (r & 7)) << 4));
        }
#pragma unroll
        for (int idx = 0; idx < 16; idx++) {
            const int cur = idx & 1, nxt = cur ^ 1;
            const int kk = idx >> 2, dp = idx & 3;
            if (idx < 15) {
                const int kk2 = (idx + 1) >> 2, dp2 = (idx + 1) & 3;
                int r = kk2 * 16 + (lane & 15);
                int cA = dp2 * 4 + (lane >> 4);
                int cB = dp2 * 4 + 2 + (lane >> 4);
                ldsm4t(vfr[nxt][0], smb + VO + r * 256 + ((cA ^ (r & 7)) << 4));
                ldsm4t(vfr[nxt][1], smb + VO + r * 256 + ((cB ^ (r & 7)) << 4));
            }
            const int dg0 = dp * 2, dg1 = dp * 2 + 1;
            mma16816h(oacc[dg0 * 2],     pf[kk], vfr[cur][0][0], vfr[cur][0][1]);
            mma16816h(oacc[dg0 * 2 + 1], pf[kk], vfr[cur][0][2], vfr[cur][0][3]);
            mma16816h(oacc[dg1 * 2],     pf[kk], vfr[cur][1][0], vfr[cur][1][1]);
            mma16816h(oacc[dg1 * 2 + 1], pf[kk], vfr[cur][1][2], vfr[cur][1][3]);
        }
    }

    l0 += __shfl_xor_sync(0xffffffff, l0, 1);
    l0 += __shfl_xor_sync(0xffffffff, l0, 2);
    l1 += __shfl_xor_sync(0xffffffff, l1, 1);
    l1 += __shfl_xor_sync(0xffffffff, l1, 2);
    float inv0 = 1.f / l0, inv1 = 1.f / l1;

    size_t rowA = ((size_t)(b * SS + sq0 + r0)) * (NQ * DD) + h * DD;
    size_t rowB = ((size_t)(b * SS + sq0 + r1)) * (NQ * DD) + h * DD;
#pragma unroll
    for (int dt = 0; dt < 16; dt++) {
        int c = dt * 8 + 2 * t4;
        float v0 = oacc[dt][0] * inv0, v1 = oacc[dt][1] * inv0;
        float v2 = oacc[dt][2] * inv1, v3 = oacc[dt][3] * inv1;
        __half2 hA = __float22half2_rn(make_float2(v0, v1));
        float2 fA = __half22float2(hA);
        __half2 lA = __float22half2_rn(make_float2(v0 - fA.x, v1 - fA.y));
        __half2 hB = __float22half2_rn(make_float2(v2, v3));
        float2 fB = __half22float2(hB);
        __half2 lB = __float22half2_rn(make_float2(v2 - fB.x, v3 - fB.y));
        *(__half2*)&attnh[rowA + c] = hA;
        *(__half2*)&attnl[rowA + c] = lA;
        *(__half2*)&attnh[rowB + c] = hB;
        *(__half2*)&attnl[rowB + c] = lB;
    }
}

// ---------------------------------------------------------------------------
extern "C" void kernel_launch(void* const* d_in, const int* in_sizes, int n_in,
                              void* d_out, int out_size)
{
    const float* hidden = (const float*)d_in[0];
    const float* w_qkv  = (const float*)d_in[1];
    const float* w_o    = (const float*)d_in[2];
    const float* cosb   = (const float*)d_in[3];
    const float* sinb   = (const float*)d_in[4];
    const float* kc     = (const float*)d_in[5];
    const float* vc     = (const float*)d_in[6];
    float* out = (float*)d_out;

    float *qkv;
    __half *hidf, *wq, *wo, *ath, *atl, *qf, *kf, *vf;
    cudaGetSymbolAddress((void**)&qkv, g_qkv);
    cudaGetSymbolAddress((void**)&hidf, g_hid);
    cudaGetSymbolAddress((void**)&wq, g_wqkv);
    cudaGetSymbolAddress((void**)&wo, g_wo);
    cudaGetSymbolAddress((void**)&ath, g_attn_h);
    cudaGetSymbolAddress((void**)&atl, g_attn_l);
    cudaGetSymbolAddress((void**)&qf, g_q_f);
    cudaGetSymbolAddress((void**)&kf, g_k_f);
    cudaGetSymbolAddress((void**)&vf, g_v_f);

    cudaFuncSetAttribute(gemm_f16x1,
                         cudaFuncAttributeMaxDynamicSharedMemorySize, GEMM1_SMEM);
    cudaFuncSetAttribute(gemm_f16x2,
                         cudaFuncAttributeMaxDynamicSharedMemorySize, GEMM_SMEM);
    cudaFuncSetAttribute(flash_mma,
                         cudaFuncAttributeMaxDynamicSharedMemorySize, FA_SMEM);

    const int M = BB * SS;  // 2048

    // 0) activation convert + weight transposes
    {
        int n = M * HH;
        conv_f16<<<(n + 255) / 256, 256>>>(hidden, hidf, n);
        trans_f16<<<dim3(QKVN / 32, HH / 32), dim3(32, 8)>>>(w_qkv, wq, HH, QKVN);
        trans_f16<<<dim3(HH / 32, HH / 32), dim3(32, 8)>>>(w_o, wo, HH, HH);
    }
    // 1) QKV projection (fp16 single-pass)
    gemm_f16x1<<<dim3(QKVN / 256, M / 128), 256, GEMM1_SMEM>>>(
        hidf, wq, qkv, M, QKVN, HH);
    // 2) fused pre-pass
    {
        int total = NQTOT + KVTOT;
        prep_qkv_f16<<<(total + 255) / 256, 256>>>(qkv, kc, vc, cosb, sinb,
                                                   qf, kf, vf);
    }
    // 3) Flash attention
    flash_mma<<<dim3(SS / 64, NQ, BB), 128, FA_SMEM>>>(qf, kf, vf, ath, atl);
    // 4) Output projection (fp16x2)
    gemm_f16x2<<<dim3(HH / 256, M / 128), 256, GEMM_SMEM>>>(
        ath, atl, wo, out, M, HH, HH);
}